// round 1
// baseline (speedup 1.0000x reference)
#include <cuda_runtime.h>
#include <math.h>

#define BB 16
#define NN 1024
#define CC 768
#define HH 12
#define DD 64
#define BANKN 256
#define MKEYS (NN + BANKN)   // 1280

// Scratch (static device globals -- allocation-free per harness rules)
__device__ float g_q[BB*HH*NN*DD];   // [b,h,n,d]
__device__ float g_k[BB*HH*NN*DD];
__device__ float g_v[BB*HH*NN*DD];
__device__ float g_p[BB*NN*CC];      // proj output, pre-LN

// ---------------------------------------------------------------------------
// GEMM (NT): C[r,f] = sum_c A[r,c] * W[f,c] + bias[f]
// MODE 0: A=x, W=qkv_w -> scatter into g_q/g_k/g_v   (Nf = 2304)
// MODE 1: A=attn out,  W=proj_w -> g_p               (Nf = 768)
// 128x128 tile, K-step 16, 256 threads, 8x8 microtile.
// ---------------------------------------------------------------------------
template<int MODE>
__global__ __launch_bounds__(256)
void gemm_nt(const float* __restrict__ A, const float* __restrict__ W,
             const float* __restrict__ bias)
{
    __shared__ float As[16][128];
    __shared__ float Bs[16][128];

    const int tid  = threadIdx.x;
    const int tx   = tid & 15;
    const int ty   = tid >> 4;
    const int row0 = blockIdx.x * 128;
    const int col0 = blockIdx.y * 128;
    const int lr   = tid >> 2;        // 0..63
    const int lc   = (tid & 3) * 4;   // 0,4,8,12

    float acc[8][8];
    #pragma unroll
    for (int i = 0; i < 8; i++)
        #pragma unroll
        for (int j = 0; j < 8; j++) acc[i][j] = 0.0f;

    for (int k0 = 0; k0 < CC; k0 += 16) {
        #pragma unroll
        for (int half = 0; half < 2; half++) {
            int r = lr + half * 64;
            float4 va = *(const float4*)&A[(size_t)(row0 + r) * CC + k0 + lc];
            As[lc + 0][r] = va.x; As[lc + 1][r] = va.y;
            As[lc + 2][r] = va.z; As[lc + 3][r] = va.w;
            float4 vb = *(const float4*)&W[(size_t)(col0 + r) * CC + k0 + lc];
            Bs[lc + 0][r] = vb.x; Bs[lc + 1][r] = vb.y;
            Bs[lc + 2][r] = vb.z; Bs[lc + 3][r] = vb.w;
        }
        __syncthreads();

        #pragma unroll
        for (int kk = 0; kk < 16; kk++) {
            float4 a0 = *(const float4*)&As[kk][ty * 8];
            float4 a1 = *(const float4*)&As[kk][ty * 8 + 4];
            float4 b0 = *(const float4*)&Bs[kk][tx * 8];
            float4 b1 = *(const float4*)&Bs[kk][tx * 8 + 4];
            float a[8] = {a0.x, a0.y, a0.z, a0.w, a1.x, a1.y, a1.z, a1.w};
            float b[8] = {b0.x, b0.y, b0.z, b0.w, b1.x, b1.y, b1.z, b1.w};
            #pragma unroll
            for (int i = 0; i < 8; i++)
                #pragma unroll
                for (int j = 0; j < 8; j++)
                    acc[i][j] = fmaf(a[i], b[j], acc[i][j]);
        }
        __syncthreads();
    }

    // Epilogue
    #pragma unroll
    for (int i = 0; i < 8; i++) {
        int r = row0 + ty * 8 + i;
        int b = r >> 10;
        int n = r & 1023;
        #pragma unroll
        for (int j = 0; j < 8; j++) {
            int f = col0 + tx * 8 + j;
            float v = acc[i][j] + bias[f];
            if (MODE == 0) {
                int which = f / CC;
                int hd = f - which * CC;
                int h = hd >> 6, d = hd & 63;
                float* dst = (which == 0) ? g_q : ((which == 1) ? g_k : g_v);
                dst[(((size_t)b * HH + h) * NN + n) * DD + d] = v;
            } else {
                g_p[(size_t)r * CC + f] = v;
            }
        }
    }
}

// ---------------------------------------------------------------------------
// Attention: per block 64 queries of one (b,h); loop 20 chunks of 64 keys
// (keys 0..1023 = k/v, 1024..1279 = bank). Online softmax, fp32.
// Dynamic smem: Qs[64][65] + Ks[64][65] + Ps[64][64] = 49664 B.
// ---------------------------------------------------------------------------
#define ATTN_SMEM_FLOATS (64*65 + 64*65 + 64*64)

__global__ __launch_bounds__(256)
void attn_kernel(const float* __restrict__ bank_k, const float* __restrict__ bank_v,
                 float* __restrict__ out)
{
    extern __shared__ float sm[];
    float (*Qs)[65] = (float(*)[65])sm;
    float (*Ks)[65] = (float(*)[65])(sm + 64 * 65);
    float (*Ps)[64] = (float(*)[64])(sm + 2 * 64 * 65);

    const int tid = threadIdx.x;
    const int tx  = tid & 15;      // key-col / d-col group (4 each)
    const int ty  = tid >> 4;      // query-row group (4 each)
    const int bh  = blockIdx.y;
    const int b   = bh / HH;
    const int h   = bh - b * HH;
    const int q0  = blockIdx.x * 64;

    const float* qbase = g_q + (size_t)bh * NN * DD + (size_t)q0 * DD;
    const float* kbase = g_k + (size_t)bh * NN * DD;
    const float* vbase = g_v + (size_t)bh * NN * DD;

    // Load Q tile, fold 1/sqrt(64)
    for (int idx = tid; idx < 64 * 16; idx += 256) {
        int r  = idx >> 4;
        int c4 = (idx & 15) * 4;
        float4 v = *(const float4*)(qbase + (size_t)r * DD + c4);
        Qs[r][c4 + 0] = v.x * 0.125f;
        Qs[r][c4 + 1] = v.y * 0.125f;
        Qs[r][c4 + 2] = v.z * 0.125f;
        Qs[r][c4 + 3] = v.w * 0.125f;
    }

    float o[4][4];
    float mprev[4], l[4];
    #pragma unroll
    for (int i = 0; i < 4; i++) {
        mprev[i] = -INFINITY; l[i] = 0.0f;
        #pragma unroll
        for (int j = 0; j < 4; j++) o[i][j] = 0.0f;
    }

    for (int kc = 0; kc < MKEYS / 64; kc++) {
        const int m0 = kc * 64;
        __syncthreads();   // protect Ks(V) reads of previous chunk + Ps
        // Load K chunk
        for (int idx = tid; idx < 64 * 16; idx += 256) {
            int r  = idx >> 4;
            int c4 = (idx & 15) * 4;
            int m  = m0 + r;
            const float* src = (m < NN)
                ? (kbase + (size_t)m * DD + c4)
                : (bank_k + (size_t)(m - NN) * CC + h * DD + c4);
            float4 v = *(const float4*)src;
            Ks[r][c4 + 0] = v.x; Ks[r][c4 + 1] = v.y;
            Ks[r][c4 + 2] = v.z; Ks[r][c4 + 3] = v.w;
        }
        __syncthreads();

        // S = Q K^T  (64x64 tile; thread owns 4x4)
        float s[4][4];
        #pragma unroll
        for (int i = 0; i < 4; i++)
            #pragma unroll
            for (int j = 0; j < 4; j++) s[i][j] = 0.0f;

        #pragma unroll 8
        for (int d = 0; d < 64; d++) {
            float qr[4], kr[4];
            #pragma unroll
            for (int ii = 0; ii < 4; ii++) qr[ii] = Qs[ty * 4 + ii][d];
            #pragma unroll
            for (int jj = 0; jj < 4; jj++) kr[jj] = Ks[tx * 4 + jj][d];
            #pragma unroll
            for (int ii = 0; ii < 4; ii++)
                #pragma unroll
                for (int jj = 0; jj < 4; jj++)
                    s[ii][jj] = fmaf(qr[ii], kr[jj], s[ii][jj]);
        }

        // Online softmax update (row reductions across the 16 tx lanes)
        #pragma unroll
        for (int ii = 0; ii < 4; ii++) {
            float mx = fmaxf(fmaxf(s[ii][0], s[ii][1]), fmaxf(s[ii][2], s[ii][3]));
            #pragma unroll
            for (int off = 8; off >= 1; off >>= 1)
                mx = fmaxf(mx, __shfl_xor_sync(0xffffffffu, mx, off));
            float mnew  = fmaxf(mprev[ii], mx);
            float alpha = __expf(mprev[ii] - mnew);
            float ps = 0.0f;
            #pragma unroll
            for (int jj = 0; jj < 4; jj++) {
                float p = __expf(s[ii][jj] - mnew);
                Ps[ty * 4 + ii][tx * 4 + jj] = p;
                ps += p;
            }
            #pragma unroll
            for (int off = 8; off >= 1; off >>= 1)
                ps += __shfl_xor_sync(0xffffffffu, ps, off);
            l[ii] = l[ii] * alpha + ps;
            mprev[ii] = mnew;
            #pragma unroll
            for (int jj = 0; jj < 4; jj++) o[ii][jj] *= alpha;
        }
        __syncthreads();   // Ps complete; all S-phase Ks reads done

        // Load V chunk into Ks buffer
        for (int idx = tid; idx < 64 * 16; idx += 256) {
            int r  = idx >> 4;
            int c4 = (idx & 15) * 4;
            int m  = m0 + r;
            const float* src = (m < NN)
                ? (vbase + (size_t)m * DD + c4)
                : (bank_v + (size_t)(m - NN) * CC + h * DD + c4);
            float4 v = *(const float4*)src;
            Ks[r][c4 + 0] = v.x; Ks[r][c4 + 1] = v.y;
            Ks[r][c4 + 2] = v.z; Ks[r][c4 + 3] = v.w;
        }
        __syncthreads();

        // O += P @ V
        #pragma unroll 8
        for (int m = 0; m < 64; m++) {
            float pv[4], vv[4];
            #pragma unroll
            for (int ii = 0; ii < 4; ii++) pv[ii] = Ps[ty * 4 + ii][m];
            #pragma unroll
            for (int jj = 0; jj < 4; jj++) vv[jj] = Ks[m][tx * 4 + jj];
            #pragma unroll
            for (int ii = 0; ii < 4; ii++)
                #pragma unroll
                for (int jj = 0; jj < 4; jj++)
                    o[ii][jj] = fmaf(pv[ii], vv[jj], o[ii][jj]);
        }
    }

    // Normalize + write out[(b, n, h*64+d)]
    #pragma unroll
    for (int ii = 0; ii < 4; ii++) {
        int n = q0 + ty * 4 + ii;
        float inv = 1.0f / l[ii];
        #pragma unroll
        for (int jj = 0; jj < 4; jj++) {
            int c = h * DD + tx * 4 + jj;
            out[((size_t)b * NN + n) * CC + c] = o[ii][jj] * inv;
        }
    }
}

// ---------------------------------------------------------------------------
// LayerNorm over rows of g_p -> bank_update
// ---------------------------------------------------------------------------
__global__ __launch_bounds__(256)
void ln_kernel(const float* __restrict__ nw, const float* __restrict__ nb,
               float* __restrict__ outb)
{
    __shared__ float shs[8], shs2[8];
    const int row = blockIdx.x;
    const int tid = threadIdx.x;
    const float* pr = g_p + (size_t)row * CC;

    float v[3];
    float s = 0.0f, s2 = 0.0f;
    #pragma unroll
    for (int i = 0; i < 3; i++) {
        v[i] = pr[tid + i * 256];
        s  += v[i];
        s2 += v[i] * v[i];
    }
    #pragma unroll
    for (int off = 16; off >= 1; off >>= 1) {
        s  += __shfl_xor_sync(0xffffffffu, s,  off);
        s2 += __shfl_xor_sync(0xffffffffu, s2, off);
    }
    if ((tid & 31) == 0) { shs[tid >> 5] = s; shs2[tid >> 5] = s2; }
    __syncthreads();
    float ts = 0.0f, ts2 = 0.0f;
    #pragma unroll
    for (int w = 0; w < 8; w++) { ts += shs[w]; ts2 += shs2[w]; }

    const float mu  = ts * (1.0f / CC);
    const float var = ts2 * (1.0f / CC) - mu * mu;
    const float r   = rsqrtf(var + 1e-5f);

    #pragma unroll
    for (int i = 0; i < 3; i++) {
        int c = tid + i * 256;
        outb[(size_t)row * CC + c] = (v[i] - mu) * r * nw[c] + nb[c];
    }
}

// ---------------------------------------------------------------------------
extern "C" void kernel_launch(void* const* d_in, const int* in_sizes, int n_in,
                              void* d_out, int out_size)
{
    const float* x      = (const float*)d_in[0];
    const float* qkv_w  = (const float*)d_in[1];
    const float* qkv_b  = (const float*)d_in[2];
    const float* proj_w = (const float*)d_in[3];
    const float* proj_b = (const float*)d_in[4];
    const float* norm_w = (const float*)d_in[5];
    const float* norm_b = (const float*)d_in[6];
    const float* bank_k = (const float*)d_in[7];
    const float* bank_v = (const float*)d_in[8];

    float* out      = (float*)d_out;                       // (B,N,C)
    float* bank_upd = out + (size_t)BB * NN * CC;          // (B,N,C)

    const int attn_smem = ATTN_SMEM_FLOATS * sizeof(float); // 49664
    cudaFuncSetAttribute(attn_kernel, cudaFuncAttributeMaxDynamicSharedMemorySize,
                         attn_smem);

    // 1) QKV projection -> g_q/g_k/g_v
    gemm_nt<0><<<dim3(128, 18), 256>>>(x, qkv_w, qkv_b);
    // 2) Attention (incl. memory bank) -> out
    attn_kernel<<<dim3(NN / 64, BB * HH), 256, attn_smem>>>(bank_k, bank_v, out);
    // 3) Projection -> g_p
    gemm_nt<1><<<dim3(128, 6), 256>>>(out, proj_w, proj_b);
    // 4) LayerNorm -> bank_update
    ln_kernel<<<BB * NN, 256>>>(norm_w, norm_b, bank_upd);
}

// round 7
// speedup vs baseline: 1.3374x; 1.3374x over previous
#include <cuda_runtime.h>
#include <cuda_bf16.h>
#include <cstdint>
#include <math.h>

#define BB 16
#define NN 1024
#define CC 768
#define HH 12
#define DD 64
#define BANKN 256
#define MKEYS (NN + BANKN)   // 1280
#define K3 (3*CC)            // 2304 expanded K (3x bf16 split)
#define KC 64                // bf16 K elems per chunk (128 B rows)
#define NCHUNK (K3/KC)       // 36
#define STRIDE 132           // stage row stride (floats, multiple of 4)
#define GSMEM (128*STRIDE*4) // 67584 >= double-buffer 65536

// ---------------- scratch (static device globals, 16B-aligned) ----------------
__device__ __align__(16) float g_q[BB*HH*NN*DD];
__device__ __align__(16) float g_k[BB*HH*NN*DD];
__device__ __align__(16) float g_v[BB*HH*NN*DD];
__device__ __align__(16) float g_p[BB*NN*CC];
__device__ __align__(16) __nv_bfloat16 g_a3[(size_t)BB*NN*K3];   // x expanded
__device__ __align__(16) __nv_bfloat16 g_o3[(size_t)BB*NN*K3];   // attn out expanded
__device__ __align__(16) __nv_bfloat16 g_w3q[(size_t)3*CC*K3];   // qkv_w expanded
__device__ __align__(16) __nv_bfloat16 g_w3p[(size_t)CC*K3];     // proj_w expanded

// ---------------- PTX helpers (sm_80-class only: mma.sync / ldmatrix / cp.async)
__device__ __forceinline__ uint32_t smem_u32(const void* p) {
    uint32_t a;
    asm("{ .reg .u64 t; cvta.to.shared.u64 t, %1; cvt.u32.u64 %0, t; }" : "=r"(a) : "l"(p));
    return a;
}
__device__ __forceinline__ void cp_async16(uint32_t dst, const void* src) {
    asm volatile("cp.async.cg.shared.global [%0], [%1], 16;" :: "r"(dst), "l"(src));
}
__device__ __forceinline__ void cp_commit() {
    asm volatile("cp.async.commit_group;");
}
template<int N>
__device__ __forceinline__ void cp_wait() {
    asm volatile("cp.async.wait_group %0;" :: "n"(N));
}
__device__ __forceinline__ void ldsm4(uint32_t* r, uint32_t addr) {
    asm volatile("ldmatrix.sync.aligned.m8n8.x4.shared.b16 {%0,%1,%2,%3}, [%4];"
                 : "=r"(r[0]), "=r"(r[1]), "=r"(r[2]), "=r"(r[3]) : "r"(addr));
}
__device__ __forceinline__ void mma16816(float* d, const uint32_t* a, const uint32_t* b) {
    asm volatile(
        "mma.sync.aligned.m16n8k16.row.col.f32.bf16.bf16.f32 "
        "{%0,%1,%2,%3}, {%4,%5,%6,%7}, {%8,%9}, {%0,%1,%2,%3};"
        : "+f"(d[0]), "+f"(d[1]), "+f"(d[2]), "+f"(d[3])
        : "r"(a[0]), "r"(a[1]), "r"(a[2]), "r"(a[3]), "r"(b[0]), "r"(b[1]));
}

// ---------------------------------------------------------------------------
// Split-precision expansion:  mode 0 -> [hi, hi, lo]   mode 1 -> [hi, lo, hi]
// ---------------------------------------------------------------------------
__global__ __launch_bounds__(256)
void conv3(const float4* __restrict__ src, int which_dst, int n8, int mode)
{
    int i = blockIdx.x * blockDim.x + threadIdx.x;
    if (i >= n8) return;
    __nv_bfloat16* dst = (which_dst == 0) ? g_a3 : (which_dst == 1) ? g_w3q
                       : (which_dst == 2) ? g_w3p : g_o3;
    float4 a = src[2 * i], b = src[2 * i + 1];
    float f[8] = {a.x, a.y, a.z, a.w, b.x, b.y, b.z, b.w};
    __nv_bfloat16 o[24];
    #pragma unroll
    for (int j = 0; j < 8; j++) {
        __nv_bfloat16 hi = __float2bfloat16(f[j]);
        __nv_bfloat16 lo = __float2bfloat16(f[j] - __bfloat162float(hi));
        if (mode == 0) { o[3*j] = hi; o[3*j+1] = hi; o[3*j+2] = lo; }
        else           { o[3*j] = hi; o[3*j+1] = lo; o[3*j+2] = hi; }
    }
    uint4* dp = (uint4*)dst + (size_t)3 * i;
    const uint4* op = (const uint4*)o;
    dp[0] = op[0]; dp[1] = op[1]; dp[2] = op[2];
}

// ---------------------------------------------------------------------------
// HMMA GEMM:  C[r, f] = sum_k' A3[r, k'] * W3[f, k']   (K' = 2304 bf16)
// MODE 0: A3=g_a3, W3=g_w3q (2304 cols) -> scatter g_q/g_k/g_v
// MODE 1: A3=g_o3, W3=g_w3p (768 cols)  -> g_p
// 128x128 tile, cp.async ping-pong chunks of 64 K-elems, mma.sync m16n8k16.
// 8 warps: warp tile 32(m) x 64(n).
// ---------------------------------------------------------------------------
template<int MODE>
__global__ __launch_bounds__(256)
void gemm3(const float* __restrict__ bias)
{
    extern __shared__ __align__(1024) char sm[];
    const uint32_t smb = smem_u32(sm);
    const int tid = threadIdx.x, wid = tid >> 5, lane = tid & 31;
    const int row0 = blockIdx.x * 128, col0 = blockIdx.y * 128;
    const __nv_bfloat16* __restrict__ A = (MODE == 0) ? g_a3 : g_o3;
    const __nv_bfloat16* __restrict__ W = (MODE == 0) ? g_w3q : g_w3p;

    const int wm = wid >> 1;          // 0..3  -> m offset wm*32
    const int wn = wid & 1;           // 0..1  -> n offset wn*64

    // ldmatrix fragment addressing: base = row*128; per k-step the 16B k-group
    // index is XORed with (row & 7)  (SW128 swizzle -- XOR, never add!)
    uint32_t abase[2]; uint32_t asw[2];
    #pragma unroll
    for (int mt = 0; mt < 2; mt++) {
        int r = wm * 32 + mt * 16 + (lane & 7) + ((lane >> 3) & 1) * 8;
        abase[mt] = (uint32_t)(r * 128);
        asw[mt]   = (uint32_t)(r & 7);
    }
    uint32_t bbase[4]; uint32_t bsw[4];
    #pragma unroll
    for (int p = 0; p < 4; p++) {
        int r = wn * 64 + p * 16 + (lane & 7) + ((lane >> 4) & 1) * 8;
        bbase[p] = (uint32_t)(r * 128);
        bsw[p]   = (uint32_t)(r & 7);
    }
    const uint32_t ka = (lane >> 4) & 1;   // A k-group low bit
    const uint32_t kb = (lane >> 3) & 1;   // B k-group low bit

    // loader: thread copies 4 x 16B for A and for B per chunk
    const int lr = tid >> 1;               // 0..127 row
    const int lu = (tid & 1) * 4;          // 16B-group base 0 or 4
    uint32_t st_off[4];
    #pragma unroll
    for (int it = 0; it < 4; it++) {
        int u = lu + it;
        st_off[it] = (uint32_t)(lr * 128 + (((uint32_t)u ^ (uint32_t)(lr & 7)) << 4));
    }

    float acc[2][8][4];
    #pragma unroll
    for (int mt = 0; mt < 2; mt++)
        #pragma unroll
        for (int nt = 0; nt < 8; nt++)
            #pragma unroll
            for (int c = 0; c < 4; c++) acc[mt][nt][c] = 0.0f;

    // -------- prologue: load chunk 0 into buf 0
    {
        const __nv_bfloat16* Asrc = A + (size_t)row0 * K3;
        const __nv_bfloat16* Wsrc = W + (size_t)col0 * K3;
        #pragma unroll
        for (int it = 0; it < 4; it++) {
            cp_async16(smb + st_off[it],         Asrc + (size_t)lr * K3 + (lu + it) * 8);
            cp_async16(smb + 16384 + st_off[it], Wsrc + (size_t)lr * K3 + (lu + it) * 8);
        }
        cp_commit();
    }

    for (int ch = 0; ch < NCHUNK; ch++) {
        const uint32_t buf = smb + (ch & 1) * 32768;
        if (ch + 1 < NCHUNK) {
            const uint32_t nbuf = smb + ((ch + 1) & 1) * 32768;
            const __nv_bfloat16* Asrc = A + (size_t)row0 * K3 + (ch + 1) * KC;
            const __nv_bfloat16* Wsrc = W + (size_t)col0 * K3 + (ch + 1) * KC;
            #pragma unroll
            for (int it = 0; it < 4; it++) {
                cp_async16(nbuf + st_off[it],         Asrc + (size_t)lr * K3 + (lu + it) * 8);
                cp_async16(nbuf + 16384 + st_off[it], Wsrc + (size_t)lr * K3 + (lu + it) * 8);
            }
            cp_commit();
            cp_wait<1>();
        } else {
            cp_wait<0>();
        }
        __syncthreads();

        #pragma unroll
        for (int ks = 0; ks < 4; ks++) {
            uint32_t af[2][4], bf[4][4];
            const uint32_t ga = ka + 2 * ks;   // A 16B k-group
            const uint32_t gb = kb + 2 * ks;   // B 16B k-group
            #pragma unroll
            for (int mt = 0; mt < 2; mt++)
                ldsm4(af[mt], buf + abase[mt] + ((ga ^ asw[mt]) << 4));
            #pragma unroll
            for (int p = 0; p < 4; p++)
                ldsm4(bf[p], buf + 16384 + bbase[p] + ((gb ^ bsw[p]) << 4));
            #pragma unroll
            for (int mt = 0; mt < 2; mt++)
                #pragma unroll
                for (int p = 0; p < 4; p++) {
                    mma16816(acc[mt][2*p],     af[mt], &bf[p][0]);
                    mma16816(acc[mt][2*p + 1], af[mt], &bf[p][2]);
                }
        }
        __syncthreads();
    }

    // -------- epilogue: regs -> stage smem -> coalesced global
    float* stage = (float*)sm;
    const int g   = lane >> 2;
    const int tp  = (lane & 3) * 2;
    #pragma unroll
    for (int mt = 0; mt < 2; mt++) {
        int rbase = wm * 32 + mt * 16 + g;
        #pragma unroll
        for (int nt = 0; nt < 8; nt++) {
            int cbase = wn * 64 + nt * 8 + tp;
            stage[rbase * STRIDE + cbase]           = acc[mt][nt][0];
            stage[rbase * STRIDE + cbase + 1]       = acc[mt][nt][1];
            stage[(rbase + 8) * STRIDE + cbase]     = acc[mt][nt][2];
            stage[(rbase + 8) * STRIDE + cbase + 1] = acc[mt][nt][3];
        }
    }
    __syncthreads();

    #pragma unroll
    for (int it = 0; it < 16; it++) {
        int idx = tid + it * 256;             // 128 rows x 32 float4
        int r = idx >> 5, q = idx & 31, c = q * 4;
        float4 v = *(float4*)&stage[r * STRIDE + c];
        int f0 = col0 + c;
        v.x += bias[f0]; v.y += bias[f0 + 1]; v.z += bias[f0 + 2]; v.w += bias[f0 + 3];
        int gr = row0 + r;
        if (MODE == 0) {
            int b = gr >> 10, n = gr & 1023;
            int which = f0 / CC;
            int hd = f0 - which * CC;
            int h = hd >> 6, d = hd & 63;
            float* dst = (which == 0) ? g_q : (which == 1) ? g_k : g_v;
            *(float4*)&dst[(((size_t)b * HH + h) * NN + n) * DD + d] = v;
        } else {
            *(float4*)&g_p[(size_t)gr * CC + f0] = v;
        }
    }
}

// ---------------------------------------------------------------------------
// Attention (fp32 SIMT)
// ---------------------------------------------------------------------------
#define ATTN_SMEM_FLOATS (64*65 + 64*65 + 64*64)

__global__ __launch_bounds__(256)
void attn_kernel(const float* __restrict__ bank_k, const float* __restrict__ bank_v,
                 float* __restrict__ out)
{
    extern __shared__ float smf[];
    float (*Qs)[65] = (float(*)[65])smf;
    float (*Ks)[65] = (float(*)[65])(smf + 64 * 65);
    float (*Ps)[64] = (float(*)[64])(smf + 2 * 64 * 65);

    const int tid = threadIdx.x;
    const int tx  = tid & 15;
    const int ty  = tid >> 4;
    const int bh  = blockIdx.y;
    const int b   = bh / HH;
    const int h   = bh - b * HH;
    const int q0  = blockIdx.x * 64;

    const float* qbase = g_q + (size_t)bh * NN * DD + (size_t)q0 * DD;
    const float* kbase = g_k + (size_t)bh * NN * DD;
    const float* vbase = g_v + (size_t)bh * NN * DD;

    for (int idx = tid; idx < 64 * 16; idx += 256) {
        int r  = idx >> 4;
        int c4 = (idx & 15) * 4;
        float4 v = *(const float4*)(qbase + (size_t)r * DD + c4);
        Qs[r][c4 + 0] = v.x * 0.125f;
        Qs[r][c4 + 1] = v.y * 0.125f;
        Qs[r][c4 + 2] = v.z * 0.125f;
        Qs[r][c4 + 3] = v.w * 0.125f;
    }

    float o[4][4];
    float mprev[4], l[4];
    #pragma unroll
    for (int i = 0; i < 4; i++) {
        mprev[i] = -INFINITY; l[i] = 0.0f;
        #pragma unroll
        for (int j = 0; j < 4; j++) o[i][j] = 0.0f;
    }

    for (int kc = 0; kc < MKEYS / 64; kc++) {
        const int m0 = kc * 64;
        __syncthreads();
        for (int idx = tid; idx < 64 * 16; idx += 256) {
            int r  = idx >> 4;
            int c4 = (idx & 15) * 4;
            int m  = m0 + r;
            const float* src = (m < NN)
                ? (kbase + (size_t)m * DD + c4)
                : (bank_k + (size_t)(m - NN) * CC + h * DD + c4);
            float4 v = *(const float4*)src;
            Ks[r][c4 + 0] = v.x; Ks[r][c4 + 1] = v.y;
            Ks[r][c4 + 2] = v.z; Ks[r][c4 + 3] = v.w;
        }
        __syncthreads();

        float s[4][4];
        #pragma unroll
        for (int i = 0; i < 4; i++)
            #pragma unroll
            for (int j = 0; j < 4; j++) s[i][j] = 0.0f;

        #pragma unroll 8
        for (int d = 0; d < 64; d++) {
            float qr[4], kr[4];
            #pragma unroll
            for (int ii = 0; ii < 4; ii++) qr[ii] = Qs[ty * 4 + ii][d];
            #pragma unroll
            for (int jj = 0; jj < 4; jj++) kr[jj] = Ks[tx * 4 + jj][d];
            #pragma unroll
            for (int ii = 0; ii < 4; ii++)
                #pragma unroll
                for (int jj = 0; jj < 4; jj++)
                    s[ii][jj] = fmaf(qr[ii], kr[jj], s[ii][jj]);
        }

        #pragma unroll
        for (int ii = 0; ii < 4; ii++) {
            float mx = fmaxf(fmaxf(s[ii][0], s[ii][1]), fmaxf(s[ii][2], s[ii][3]));
            #pragma unroll
            for (int off = 8; off >= 1; off >>= 1)
                mx = fmaxf(mx, __shfl_xor_sync(0xffffffffu, mx, off));
            float mnew  = fmaxf(mprev[ii], mx);
            float alpha = __expf(mprev[ii] - mnew);
            float ps = 0.0f;
            #pragma unroll
            for (int jj = 0; jj < 4; jj++) {
                float p = __expf(s[ii][jj] - mnew);
                Ps[ty * 4 + ii][tx * 4 + jj] = p;
                ps += p;
            }
            #pragma unroll
            for (int off = 8; off >= 1; off >>= 1)
                ps += __shfl_xor_sync(0xffffffffu, ps, off);
            l[ii] = l[ii] * alpha + ps;
            mprev[ii] = mnew;
            #pragma unroll
            for (int jj = 0; jj < 4; jj++) o[ii][jj] *= alpha;
        }
        __syncthreads();

        for (int idx = tid; idx < 64 * 16; idx += 256) {
            int r  = idx >> 4;
            int c4 = (idx & 15) * 4;
            int m  = m0 + r;
            const float* src = (m < NN)
                ? (vbase + (size_t)m * DD + c4)
                : (bank_v + (size_t)(m - NN) * CC + h * DD + c4);
            float4 v = *(const float4*)src;
            Ks[r][c4 + 0] = v.x; Ks[r][c4 + 1] = v.y;
            Ks[r][c4 + 2] = v.z; Ks[r][c4 + 3] = v.w;
        }
        __syncthreads();

        #pragma unroll 8
        for (int m = 0; m < 64; m++) {
            float pv[4], vv[4];
            #pragma unroll
            for (int ii = 0; ii < 4; ii++) pv[ii] = Ps[ty * 4 + ii][m];
            #pragma unroll
            for (int jj = 0; jj < 4; jj++) vv[jj] = Ks[m][tx * 4 + jj];
            #pragma unroll
            for (int ii = 0; ii < 4; ii++)
                #pragma unroll
                for (int jj = 0; jj < 4; jj++)
                    o[ii][jj] = fmaf(pv[ii], vv[jj], o[ii][jj]);
        }
    }

    #pragma unroll
    for (int ii = 0; ii < 4; ii++) {
        int n = q0 + ty * 4 + ii;
        float inv = 1.0f / l[ii];
        #pragma unroll
        for (int jj = 0; jj < 4; jj++) {
            int c = h * DD + tx * 4 + jj;
            out[((size_t)b * NN + n) * CC + c] = o[ii][jj] * inv;
        }
    }
}

// ---------------------------------------------------------------------------
// LayerNorm over rows of g_p -> bank_update
// ---------------------------------------------------------------------------
__global__ __launch_bounds__(256)
void ln_kernel(const float* __restrict__ nw, const float* __restrict__ nb,
               float* __restrict__ outb)
{
    __shared__ float shs[8], shs2[8];
    const int row = blockIdx.x;
    const int tid = threadIdx.x;
    const float* pr = g_p + (size_t)row * CC;

    float v[3];
    float s = 0.0f, s2 = 0.0f;
    #pragma unroll
    for (int i = 0; i < 3; i++) {
        v[i] = pr[tid + i * 256];
        s  += v[i];
        s2 += v[i] * v[i];
    }
    #pragma unroll
    for (int off = 16; off >= 1; off >>= 1) {
        s  += __shfl_xor_sync(0xffffffffu, s,  off);
        s2 += __shfl_xor_sync(0xffffffffu, s2, off);
    }
    if ((tid & 31) == 0) { shs[tid >> 5] = s; shs2[tid >> 5] = s2; }
    __syncthreads();
    float ts = 0.0f, ts2 = 0.0f;
    #pragma unroll
    for (int w = 0; w < 8; w++) { ts += shs[w]; ts2 += shs2[w]; }

    const float mu  = ts * (1.0f / CC);
    const float var = ts2 * (1.0f / CC) - mu * mu;
    const float r   = rsqrtf(var + 1e-5f);

    #pragma unroll
    for (int i = 0; i < 3; i++) {
        int c = tid + i * 256;
        outb[(size_t)row * CC + c] = (v[i] - mu) * r * nw[c] + nb[c];
    }
}

// ---------------------------------------------------------------------------
extern "C" void kernel_launch(void* const* d_in, const int* in_sizes, int n_in,
                              void* d_out, int out_size)
{
    const float* x      = (const float*)d_in[0];
    const float* qkv_w  = (const float*)d_in[1];
    const float* qkv_b  = (const float*)d_in[2];
    const float* proj_w = (const float*)d_in[3];
    const float* proj_b = (const float*)d_in[4];
    const float* norm_w = (const float*)d_in[5];
    const float* norm_b = (const float*)d_in[6];
    const float* bank_k = (const float*)d_in[7];
    const float* bank_v = (const float*)d_in[8];

    float* out      = (float*)d_out;
    float* bank_upd = out + (size_t)BB * NN * CC;

    const int attn_smem = ATTN_SMEM_FLOATS * sizeof(float);
    cudaFuncSetAttribute(attn_kernel, cudaFuncAttributeMaxDynamicSharedMemorySize, attn_smem);
    cudaFuncSetAttribute(gemm3<0>, cudaFuncAttributeMaxDynamicSharedMemorySize, GSMEM);
    cudaFuncSetAttribute(gemm3<1>, cudaFuncAttributeMaxDynamicSharedMemorySize, GSMEM);

    const int nx8 = BB * NN * CC / 8;       // 1572864
    const int nwq8 = 3 * CC * CC / 8;       // 221184
    const int nwp8 = CC * CC / 8;           // 73728

    // 1) expand x and qkv_w to 3x-bf16
    conv3<<<(nx8 + 255) / 256, 256>>>((const float4*)x, 0, nx8, 0);
    conv3<<<(nwq8 + 255) / 256, 256>>>((const float4*)qkv_w, 1, nwq8, 1);
    // 2) QKV GEMM (HMMA) -> g_q/g_k/g_v
    gemm3<0><<<dim3(128, 18), 256, GSMEM>>>(qkv_b);
    // 3) attention -> out
    attn_kernel<<<dim3(NN / 64, BB * HH), 256, attn_smem>>>(bank_k, bank_v, out);
    // 4) expand attn out and proj_w
    conv3<<<(nx8 + 255) / 256, 256>>>((const float4*)out, 3, nx8, 0);
    conv3<<<(nwp8 + 255) / 256, 256>>>((const float4*)proj_w, 2, nwp8, 1);
    // 5) proj GEMM (HMMA) -> g_p
    gemm3<1><<<dim3(128, 6), 256, GSMEM>>>(proj_b);
    // 6) LayerNorm -> bank_update
    ln_kernel<<<BB * NN, 256>>>(norm_w, norm_b, bank_upd);
}

// round 9
// speedup vs baseline: 2.2343x; 1.6706x over previous
#include <cuda_runtime.h>
#include <cuda_bf16.h>
#include <cstdint>
#include <math.h>

#define BB 16
#define NN 1024
#define CC 768
#define HH 12
#define DD 64
#define BANKN 256
#define MKEYS (NN + BANKN)   // 1280
#define K3 (3*CC)            // 2304 expanded K (3x bf16 split)
#define KC 64
#define NCHUNK (K3/KC)       // 36
#define STRIDE 132
#define GSMEM (128*STRIDE*4)

// attention tiling
#define AQ 128
#define ACH 64
#define ANCH (MKEYS/ACH)     // 20
#define SM_Q 0               // [128][68] f32 (tf32 bits)
#define SM_K 34816           // 2 x [64][68] f32
#define SM_V 69632           // 2 x [64][100] u32 (bf16x2)
#define SM_P 120832          // [128][100] u32 (bf16x2)
#define ASMEM 172032

// ---------------- scratch ----------------
__device__ __align__(16) float g_q[BB*HH*NN*DD];
__device__ __align__(16) float g_k[BB*HH*NN*DD];
__device__ __align__(16) float g_v[BB*HH*NN*DD];
__device__ __align__(16) float g_p[BB*NN*CC];
__device__ __align__(16) __nv_bfloat16 g_a3[(size_t)BB*NN*K3];
__device__ __align__(16) __nv_bfloat16 g_o3[(size_t)BB*NN*K3];
__device__ __align__(16) __nv_bfloat16 g_w3q[(size_t)3*CC*K3];
__device__ __align__(16) __nv_bfloat16 g_w3p[(size_t)CC*K3];
__device__ __align__(16) uint32_t g_qt[(size_t)BB*HH*NN*DD];
__device__ __align__(16) uint32_t g_kt[(size_t)BB*HH*MKEYS*DD];
__device__ __align__(16) __nv_bfloat16 g_v3[(size_t)BB*HH*DD*3*MKEYS];

// ---------------- PTX helpers ----------------
__device__ __forceinline__ uint32_t smem_u32(const void* p) {
    uint32_t a;
    asm("{ .reg .u64 t; cvta.to.shared.u64 t, %1; cvt.u32.u64 %0, t; }" : "=r"(a) : "l"(p));
    return a;
}
__device__ __forceinline__ void cp_async16(uint32_t dst, const void* src) {
    asm volatile("cp.async.cg.shared.global [%0], [%1], 16;" :: "r"(dst), "l"(src));
}
__device__ __forceinline__ void cp_commit() {
    asm volatile("cp.async.commit_group;");
}
template<int N>
__device__ __forceinline__ void cp_wait() {
    asm volatile("cp.async.wait_group %0;" :: "n"(N));
}
__device__ __forceinline__ void ldsm4(uint32_t* r, uint32_t addr) {
    asm volatile("ldmatrix.sync.aligned.m8n8.x4.shared.b16 {%0,%1,%2,%3}, [%4];"
                 : "=r"(r[0]), "=r"(r[1]), "=r"(r[2]), "=r"(r[3]) : "r"(addr));
}
__device__ __forceinline__ void mma16816(float* d, const uint32_t* a, const uint32_t* b) {
    asm volatile(
        "mma.sync.aligned.m16n8k16.row.col.f32.bf16.bf16.f32 "
        "{%0,%1,%2,%3}, {%4,%5,%6,%7}, {%8,%9}, {%0,%1,%2,%3};"
        : "+f"(d[0]), "+f"(d[1]), "+f"(d[2]), "+f"(d[3])
        : "r"(a[0]), "r"(a[1]), "r"(a[2]), "r"(a[3]), "r"(b[0]), "r"(b[1]));
}
__device__ __forceinline__ void mma1688(float* d, const uint32_t* a, const uint32_t* b) {
    asm volatile(
        "mma.sync.aligned.m16n8k8.row.col.f32.tf32.tf32.f32 "
        "{%0,%1,%2,%3}, {%4,%5,%6,%7}, {%8,%9}, {%0,%1,%2,%3};"
        : "+f"(d[0]), "+f"(d[1]), "+f"(d[2]), "+f"(d[3])
        : "r"(a[0]), "r"(a[1]), "r"(a[2]), "r"(a[3]), "r"(b[0]), "r"(b[1]));
}
__device__ __forceinline__ uint32_t tf32c(float f) {
    uint32_t r; asm("cvt.rna.tf32.f32 %0, %1;" : "=r"(r) : "f"(f)); return r;
}
__device__ __forceinline__ uint32_t pk_bf16(__nv_bfloat16 lo, __nv_bfloat16 hi) {
    uint16_t a = *(uint16_t*)&lo, b = *(uint16_t*)&hi;
    return (uint32_t)a | ((uint32_t)b << 16);
}

// ---------------------------------------------------------------------------
__global__ __launch_bounds__(256)
void conv3(const float4* __restrict__ src, int which_dst, int n8, int mode)
{
    int i = blockIdx.x * blockDim.x + threadIdx.x;
    if (i >= n8) return;
    __nv_bfloat16* dst = (which_dst == 0) ? g_a3 : (which_dst == 1) ? g_w3q
                       : (which_dst == 2) ? g_w3p : g_o3;
    float4 a = src[2 * i], b = src[2 * i + 1];
    float f[8] = {a.x, a.y, a.z, a.w, b.x, b.y, b.z, b.w};
    __nv_bfloat16 o[24];
    #pragma unroll
    for (int j = 0; j < 8; j++) {
        __nv_bfloat16 hi = __float2bfloat16(f[j]);
        __nv_bfloat16 lo = __float2bfloat16(f[j] - __bfloat162float(hi));
        if (mode == 0) { o[3*j] = hi; o[3*j+1] = hi; o[3*j+2] = lo; }
        else           { o[3*j] = hi; o[3*j+1] = lo; o[3*j+2] = hi; }
    }
    uint4* dp = (uint4*)dst + (size_t)3 * i;
    const uint4* op = (const uint4*)o;
    dp[0] = op[0]; dp[1] = op[1]; dp[2] = op[2];
}

__global__ __launch_bounds__(256)
void convqt()
{
    size_t i = (size_t)blockIdx.x * 256 + threadIdx.x;
    if (i >= (size_t)BB*HH*NN*DD/4) return;
    float4 v = *((const float4*)g_q + i);
    uint4 o;
    o.x = tf32c(v.x * 0.125f); o.y = tf32c(v.y * 0.125f);
    o.z = tf32c(v.z * 0.125f); o.w = tf32c(v.w * 0.125f);
    *((uint4*)g_qt + i) = o;
}
__global__ __launch_bounds__(256)
void convkt(const float* __restrict__ bank_k)
{
    size_t i = (size_t)blockIdx.x * 256 + threadIdx.x;
    if (i >= (size_t)BB*HH*MKEYS*DD/4) return;
    int c4 = (int)(i & 15);
    int m  = (int)((i >> 4) % MKEYS);
    int bh = (int)((i >> 4) / MKEYS);
    int h  = bh % HH;
    const float* src = (m < NN)
        ? g_k + ((size_t)bh*NN + m)*DD + c4*4
        : bank_k + (size_t)(m - NN)*CC + h*DD + c4*4;
    float4 v = *(const float4*)src;
    uint4 o;
    o.x = tf32c(v.x); o.y = tf32c(v.y); o.z = tf32c(v.z); o.w = tf32c(v.w);
    *((uint4*)g_kt + (((size_t)bh*MKEYS + m)*DD + c4*4) / 4) = o;
}
__global__ __launch_bounds__(256)
void convv3(const float* __restrict__ bank_v)
{
    __shared__ float t[64][65];
    const int tid = threadIdx.x;
    const int m0 = blockIdx.x * 64;
    const int bh = blockIdx.y;
    const int h  = bh % HH;
    #pragma unroll
    for (int i = 0; i < 4; i++) {
        int idx = tid + i * 256;
        int m = idx >> 4, d4 = (idx & 15) * 4;
        int gm = m0 + m;
        const float* src = (gm < NN)
            ? g_v + ((size_t)bh*NN + gm)*DD + d4
            : bank_v + (size_t)(gm - NN)*CC + h*DD + d4;
        float4 v = *(const float4*)src;
        t[m][d4] = v.x; t[m][d4+1] = v.y; t[m][d4+2] = v.z; t[m][d4+3] = v.w;
    }
    __syncthreads();
    const int d = tid >> 2, part = tid & 3;
    __nv_bfloat16 buf[48];
    #pragma unroll
    for (int mm = 0; mm < 16; mm++) {
        float f = t[part*16 + mm][d];
        __nv_bfloat16 hi = __float2bfloat16(f);
        __nv_bfloat16 lo = __float2bfloat16(f - __bfloat162float(hi));
        buf[3*mm] = hi; buf[3*mm+1] = lo; buf[3*mm+2] = hi;
    }
    uint4* dst = (uint4*)(g_v3 + ((size_t)bh*DD + d)*3*MKEYS + 3*(m0 + part*16));
    const uint4* sp = (const uint4*)buf;
    #pragma unroll
    for (int j = 0; j < 6; j++) dst[j] = sp[j];
}

// ---------------------------------------------------------------------------
template<int MODE>
__global__ __launch_bounds__(256)
void gemm3(const float* __restrict__ bias)
{
    extern __shared__ __align__(1024) char sm[];
    const uint32_t smb = smem_u32(sm);
    const int tid = threadIdx.x, wid = tid >> 5, lane = tid & 31;
    const int row0 = blockIdx.x * 128, col0 = blockIdx.y * 128;
    const __nv_bfloat16* __restrict__ A = (MODE == 0) ? g_a3 : g_o3;
    const __nv_bfloat16* __restrict__ W = (MODE == 0) ? g_w3q : g_w3p;

    const int wm = wid >> 1;
    const int wn = wid & 1;

    uint32_t abase[2]; uint32_t asw[2];
    #pragma unroll
    for (int mt = 0; mt < 2; mt++) {
        int r = wm * 32 + mt * 16 + (lane & 7) + ((lane >> 3) & 1) * 8;
        abase[mt] = (uint32_t)(r * 128);
        asw[mt]   = (uint32_t)(r & 7);
    }
    uint32_t bbase[4]; uint32_t bsw[4];
    #pragma unroll
    for (int p = 0; p < 4; p++) {
        int r = wn * 64 + p * 16 + (lane & 7) + ((lane >> 4) & 1) * 8;
        bbase[p] = (uint32_t)(r * 128);
        bsw[p]   = (uint32_t)(r & 7);
    }
    const uint32_t ka = (lane >> 4) & 1;
    const uint32_t kb = (lane >> 3) & 1;

    const int lr = tid >> 1;
    const int lu = (tid & 1) * 4;
    uint32_t st_off[4];
    #pragma unroll
    for (int it = 0; it < 4; it++) {
        int u = lu + it;
        st_off[it] = (uint32_t)(lr * 128 + (((uint32_t)u ^ (uint32_t)(lr & 7)) << 4));
    }

    float acc[2][8][4];
    #pragma unroll
    for (int mt = 0; mt < 2; mt++)
        #pragma unroll
        for (int nt = 0; nt < 8; nt++)
            #pragma unroll
            for (int c = 0; c < 4; c++) acc[mt][nt][c] = 0.0f;

    {
        const __nv_bfloat16* Asrc = A + (size_t)row0 * K3;
        const __nv_bfloat16* Wsrc = W + (size_t)col0 * K3;
        #pragma unroll
        for (int it = 0; it < 4; it++) {
            cp_async16(smb + st_off[it],         Asrc + (size_t)lr * K3 + (lu + it) * 8);
            cp_async16(smb + 16384 + st_off[it], Wsrc + (size_t)lr * K3 + (lu + it) * 8);
        }
        cp_commit();
    }

    for (int ch = 0; ch < NCHUNK; ch++) {
        const uint32_t buf = smb + (ch & 1) * 32768;
        if (ch + 1 < NCHUNK) {
            const uint32_t nbuf = smb + ((ch + 1) & 1) * 32768;
            const __nv_bfloat16* Asrc = A + (size_t)row0 * K3 + (ch + 1) * KC;
            const __nv_bfloat16* Wsrc = W + (size_t)col0 * K3 + (ch + 1) * KC;
            #pragma unroll
            for (int it = 0; it < 4; it++) {
                cp_async16(nbuf + st_off[it],         Asrc + (size_t)lr * K3 + (lu + it) * 8);
                cp_async16(nbuf + 16384 + st_off[it], Wsrc + (size_t)lr * K3 + (lu + it) * 8);
            }
            cp_commit();
            cp_wait<1>();
        } else {
            cp_wait<0>();
        }
        __syncthreads();

        #pragma unroll
        for (int ks = 0; ks < 4; ks++) {
            uint32_t af[2][4], bf[4][4];
            const uint32_t ga = ka + 2 * ks;
            const uint32_t gb = kb + 2 * ks;
            #pragma unroll
            for (int mt = 0; mt < 2; mt++)
                ldsm4(af[mt], buf + abase[mt] + ((ga ^ asw[mt]) << 4));
            #pragma unroll
            for (int p = 0; p < 4; p++)
                ldsm4(bf[p], buf + 16384 + bbase[p] + ((gb ^ bsw[p]) << 4));
            #pragma unroll
            for (int mt = 0; mt < 2; mt++)
                #pragma unroll
                for (int p = 0; p < 4; p++) {
                    mma16816(acc[mt][2*p],     af[mt], &bf[p][0]);
                    mma16816(acc[mt][2*p + 1], af[mt], &bf[p][2]);
                }
        }
        __syncthreads();
    }

    float* stage = (float*)sm;
    const int g   = lane >> 2;
    const int tp  = (lane & 3) * 2;
    #pragma unroll
    for (int mt = 0; mt < 2; mt++) {
        int rbase = wm * 32 + mt * 16 + g;
        #pragma unroll
        for (int nt = 0; nt < 8; nt++) {
            int cbase = wn * 64 + nt * 8 + tp;
            stage[rbase * STRIDE + cbase]           = acc[mt][nt][0];
            stage[rbase * STRIDE + cbase + 1]       = acc[mt][nt][1];
            stage[(rbase + 8) * STRIDE + cbase]     = acc[mt][nt][2];
            stage[(rbase + 8) * STRIDE + cbase + 1] = acc[mt][nt][3];
        }
    }
    __syncthreads();

    #pragma unroll
    for (int it = 0; it < 16; it++) {
        int idx = tid + it * 256;
        int r = idx >> 5, q = idx & 31, c = q * 4;
        float4 v = *(float4*)&stage[r * STRIDE + c];
        int f0 = col0 + c;
        v.x += bias[f0]; v.y += bias[f0 + 1]; v.z += bias[f0 + 2]; v.w += bias[f0 + 3];
        int gr = row0 + r;
        if (MODE == 0) {
            int b = gr >> 10, n = gr & 1023;
            int which = f0 / CC;
            int hd = f0 - which * CC;
            int h = hd >> 6, d = hd & 63;
            float* dst = (which == 0) ? g_q : (which == 1) ? g_k : g_v;
            *(float4*)&dst[(((size_t)b * HH + h) * NN + n) * DD + d] = v;
        } else {
            *(float4*)&g_p[(size_t)gr * CC + f0] = v;
        }
    }
}

// ---------------------------------------------------------------------------
// Tensor-core flash attention: tf32 QK^T + 3x-bf16-split PV
// ---------------------------------------------------------------------------
__global__ __launch_bounds__(256)
void attn2(float* __restrict__ out)
{
    extern __shared__ __align__(16) char sm[];
    const uint32_t smb = smem_u32(sm);
    const int tid = threadIdx.x, w = tid >> 5, lane = tid & 31;
    const int g = lane >> 2, c = lane & 3;
    const int bh = blockIdx.y, q0 = blockIdx.x * AQ;
    const int b = bh / HH, h = bh - b * HH;

    {
        const uint32_t* src = g_qt + ((size_t)bh * NN + q0) * DD;
        #pragma unroll
        for (int i = 0; i < 8; i++) {
            int idx = tid + i * 256;
            int r = idx >> 4, c16 = idx & 15;
            cp_async16(smb + SM_Q + r * 272 + c16 * 16, src + (size_t)r * DD + c16 * 4);
        }
        const uint32_t* ks = g_kt + (size_t)bh * MKEYS * DD;
        #pragma unroll
        for (int i = 0; i < 4; i++) {
            int idx = tid + i * 256;
            int r = idx >> 4, c16 = idx & 15;
            cp_async16(smb + SM_K + r * 272 + c16 * 16, ks + (size_t)r * DD + c16 * 4);
        }
        const __nv_bfloat16* vs = g_v3 + (size_t)bh * DD * 3 * MKEYS;
        #pragma unroll
        for (int i = 0; i < 6; i++) {
            int idx = tid + i * 256;
            int r = idx / 24, j = idx - r * 24;
            cp_async16(smb + SM_V + r * 400 + j * 16, vs + (size_t)r * 3 * MKEYS + j * 8);
        }
        cp_commit();
    }

    float mprev0 = -INFINITY, mprev1 = -INFINITY, l0 = 0.0f, l1 = 0.0f;
    float o[8][4];
    #pragma unroll
    for (int t = 0; t < 8; t++)
        #pragma unroll
        for (int j = 0; j < 4; j++) o[t][j] = 0.0f;

    for (int ch = 0; ch < ANCH; ch++) {
        const int buf = ch & 1;
        if (ch + 1 < ANCH) {
            const int nb = buf ^ 1;
            const uint32_t* ks = g_kt + ((size_t)bh * MKEYS + (ch + 1) * ACH) * DD;
            #pragma unroll
            for (int i = 0; i < 4; i++) {
                int idx = tid + i * 256;
                int r = idx >> 4, c16 = idx & 15;
                cp_async16(smb + SM_K + nb * 17408 + r * 272 + c16 * 16,
                           ks + (size_t)r * DD + c16 * 4);
            }
            const __nv_bfloat16* vs = g_v3 + (size_t)bh * DD * 3 * MKEYS + (ch + 1) * 192;
            #pragma unroll
            for (int i = 0; i < 6; i++) {
                int idx = tid + i * 256;
                int r = idx / 24, j = idx - r * 24;
                cp_async16(smb + SM_V + nb * 25600 + r * 400 + j * 16,
                           vs + (size_t)r * 3 * MKEYS + j * 8);
            }
            cp_commit();
            cp_wait<1>();
        } else {
            cp_wait<0>();
        }
        __syncthreads();

        // ---- S = Q K^T (tf32)
        const uint32_t* Qs = (const uint32_t*)(sm + SM_Q);
        const uint32_t* Ks = (const uint32_t*)(sm + SM_K + buf * 17408);
        float sacc[8][4];
        #pragma unroll
        for (int t = 0; t < 8; t++)
            #pragma unroll
            for (int j = 0; j < 4; j++) sacc[t][j] = 0.0f;

        #pragma unroll
        for (int ks = 0; ks < 8; ks++) {
            uint32_t a[4];
            const uint32_t* qb = Qs + (16 * w + g) * 68 + ks * 8 + c;
            a[0] = qb[0]; a[1] = qb[8 * 68]; a[2] = qb[4]; a[3] = qb[8 * 68 + 4];
            #pragma unroll
            for (int t = 0; t < 8; t++) {
                uint32_t bf[2];
                const uint32_t* kb = Ks + (t * 8 + g) * 68 + ks * 8 + c;
                bf[0] = kb[0]; bf[1] = kb[4];
                mma1688(sacc[t], a, bf);
            }
        }

        // ---- online softmax
        float mx0 = -INFINITY, mx1 = -INFINITY;
        #pragma unroll
        for (int t = 0; t < 8; t++) {
            mx0 = fmaxf(mx0, fmaxf(sacc[t][0], sacc[t][1]));
            mx1 = fmaxf(mx1, fmaxf(sacc[t][2], sacc[t][3]));
        }
        mx0 = fmaxf(mx0, __shfl_xor_sync(0xffffffffu, mx0, 1));
        mx0 = fmaxf(mx0, __shfl_xor_sync(0xffffffffu, mx0, 2));
        mx1 = fmaxf(mx1, __shfl_xor_sync(0xffffffffu, mx1, 1));
        mx1 = fmaxf(mx1, __shfl_xor_sync(0xffffffffu, mx1, 2));
        const float mnew0 = fmaxf(mprev0, mx0);
        const float mnew1 = fmaxf(mprev1, mx1);
        const float alpha0 = __expf(mprev0 - mnew0);
        const float alpha1 = __expf(mprev1 - mnew1);

        uint32_t* P0 = (uint32_t*)(sm + SM_P) + (16 * w + g) * 100;
        uint32_t* P1 = P0 + 8 * 100;
        float ps0 = 0.0f, ps1 = 0.0f;
        #pragma unroll
        for (int t = 0; t < 8; t++) {
            float p00 = __expf(sacc[t][0] - mnew0);
            float p01 = __expf(sacc[t][1] - mnew0);
            float p10 = __expf(sacc[t][2] - mnew1);
            float p11 = __expf(sacc[t][3] - mnew1);
            ps0 += p00 + p01; ps1 += p10 + p11;
            __nv_bfloat16 h00 = __float2bfloat16(p00);
            __nv_bfloat16 l00 = __float2bfloat16(p00 - __bfloat162float(h00));
            __nv_bfloat16 h01 = __float2bfloat16(p01);
            __nv_bfloat16 l01 = __float2bfloat16(p01 - __bfloat162float(h01));
            __nv_bfloat16 h10 = __float2bfloat16(p10);
            __nv_bfloat16 l10 = __float2bfloat16(p10 - __bfloat162float(h10));
            __nv_bfloat16 h11 = __float2bfloat16(p11);
            __nv_bfloat16 l11 = __float2bfloat16(p11 - __bfloat162float(h11));
            int base = 12 * t + 3 * c;
            P0[base]     = pk_bf16(h00, h00);
            P0[base + 1] = pk_bf16(l00, h01);
            P0[base + 2] = pk_bf16(h01, l01);
            P1[base]     = pk_bf16(h10, h10);
            P1[base + 1] = pk_bf16(l10, h11);
            P1[base + 2] = pk_bf16(h11, l11);
        }
        ps0 += __shfl_xor_sync(0xffffffffu, ps0, 1);
        ps0 += __shfl_xor_sync(0xffffffffu, ps0, 2);
        ps1 += __shfl_xor_sync(0xffffffffu, ps1, 1);
        ps1 += __shfl_xor_sync(0xffffffffu, ps1, 2);
        l0 = l0 * alpha0 + ps0; l1 = l1 * alpha1 + ps1;
        mprev0 = mnew0; mprev1 = mnew1;
        #pragma unroll
        for (int t = 0; t < 8; t++) {
            o[t][0] *= alpha0; o[t][1] *= alpha0;
            o[t][2] *= alpha1; o[t][3] *= alpha1;
        }
        __syncwarp();

        // ---- O += P3 V3 (bf16 split)
        const uint32_t* Pw = (const uint32_t*)(sm + SM_P) + 16 * w * 100;
        const uint32_t* Vs = (const uint32_t*)(sm + SM_V + buf * 25600);
        #pragma unroll
        for (int k2 = 0; k2 < 12; k2++) {
            uint32_t a[4];
            const uint32_t* pb = Pw + g * 100 + k2 * 8 + c;
            a[0] = pb[0]; a[1] = pb[8 * 100]; a[2] = pb[4]; a[3] = pb[8 * 100 + 4];
            #pragma unroll
            for (int t = 0; t < 8; t++) {
                uint32_t bf[2];
                const uint32_t* vb = Vs + (t * 8 + g) * 100 + k2 * 8 + c;
                bf[0] = vb[0]; bf[1] = vb[4];
                mma16816(o[t], a, bf);
            }
        }
        __syncthreads();
    }

    const float inv0 = 1.0f / l0, inv1 = 1.0f / l1;
    const int n0 = q0 + 16 * w + g, n1 = n0 + 8;
    #pragma unroll
    for (int t = 0; t < 8; t++) {
        int col = h * DD + 8 * t + 2 * c;
        float2 v0 = make_float2(o[t][0] * inv0, o[t][1] * inv0);
        float2 v1 = make_float2(o[t][2] * inv1, o[t][3] * inv1);
        *(float2*)&out[((size_t)b * NN + n0) * CC + col] = v0;
        *(float2*)&out[((size_t)b * NN + n1) * CC + col] = v1;
    }
}

// ---------------------------------------------------------------------------
__global__ __launch_bounds__(256)
void ln_kernel(const float* __restrict__ nw, const float* __restrict__ nb,
               float* __restrict__ outb)
{
    __shared__ float shs[8], shs2[8];
    const int row = blockIdx.x;
    const int tid = threadIdx.x;
    const float* pr = g_p + (size_t)row * CC;

    float v[3];
    float s = 0.0f, s2 = 0.0f;
    #pragma unroll
    for (int i = 0; i < 3; i++) {
        v[i] = pr[tid + i * 256];
        s  += v[i];
        s2 += v[i] * v[i];
    }
    #pragma unroll
    for (int off = 16; off >= 1; off >>= 1) {
        s  += __shfl_xor_sync(0xffffffffu, s,  off);
        s2 += __shfl_xor_sync(0xffffffffu, s2, off);
    }
    if ((tid & 31) == 0) { shs[tid >> 5] = s; shs2[tid >> 5] = s2; }
    __syncthreads();
    float ts = 0.0f, ts2 = 0.0f;
    #pragma unroll
    for (int w = 0; w < 8; w++) { ts += shs[w]; ts2 += shs2[w]; }

    const float mu  = ts * (1.0f / CC);
    const float var = ts2 * (1.0f / CC) - mu * mu;
    const float r   = rsqrtf(var + 1e-5f);

    #pragma unroll
    for (int i = 0; i < 3; i++) {
        int c = tid + i * 256;
        outb[(size_t)row * CC + c] = (v[i] - mu) * r * nw[c] + nb[c];
    }
}

// ---------------------------------------------------------------------------
extern "C" void kernel_launch(void* const* d_in, const int* in_sizes, int n_in,
                              void* d_out, int out_size)
{
    const float* x      = (const float*)d_in[0];
    const float* qkv_w  = (const float*)d_in[1];
    const float* qkv_b  = (const float*)d_in[2];
    const float* proj_w = (const float*)d_in[3];
    const float* proj_b = (const float*)d_in[4];
    const float* norm_w = (const float*)d_in[5];
    const float* norm_b = (const float*)d_in[6];
    const float* bank_k = (const float*)d_in[7];
    const float* bank_v = (const float*)d_in[8];

    float* out      = (float*)d_out;
    float* bank_upd = out + (size_t)BB * NN * CC;

    cudaFuncSetAttribute(attn2, cudaFuncAttributeMaxDynamicSharedMemorySize, ASMEM);
    cudaFuncSetAttribute(gemm3<0>, cudaFuncAttributeMaxDynamicSharedMemorySize, GSMEM);
    cudaFuncSetAttribute(gemm3<1>, cudaFuncAttributeMaxDynamicSharedMemorySize, GSMEM);

    const int nx8 = BB * NN * CC / 8;
    const int nwq8 = 3 * CC * CC / 8;
    const int nwp8 = CC * CC / 8;

    conv3<<<(nx8 + 255) / 256, 256>>>((const float4*)x, 0, nx8, 0);
    conv3<<<(nwq8 + 255) / 256, 256>>>((const float4*)qkv_w, 1, nwq8, 1);
    gemm3<0><<<dim3(128, 18), 256, GSMEM>>>(qkv_b);
    convqt<<<(BB*HH*NN*DD/4 + 255) / 256, 256>>>();
    convkt<<<(BB*HH*MKEYS*DD/4 + 255) / 256, 256>>>(bank_k);
    convv3<<<dim3(ANCH, BB*HH), 256>>>(bank_v);
    attn2<<<dim3(NN / AQ, BB * HH), 256, ASMEM>>>(out);
    conv3<<<(nx8 + 255) / 256, 256>>>((const float4*)out, 3, nx8, 0);
    conv3<<<(nwp8 + 255) / 256, 256>>>((const float4*)proj_w, 2, nwp8, 1);
    gemm3<1><<<dim3(128, 6), 256, GSMEM>>>(proj_b);
    ln_kernel<<<BB * NN, 256>>>(norm_w, norm_b, bank_upd);
}

// round 10
// speedup vs baseline: 2.6166x; 1.1711x over previous
#include <cuda_runtime.h>
#include <cuda_bf16.h>
#include <cstdint>
#include <math.h>

#define BB 16
#define NN 1024
#define CC 768
#define HH 12
#define DD 64
#define BANKN 256
#define MKEYS (NN + BANKN)   // 1280
#define KC2 32               // fp32 K elems per chunk (128 B rows)
#define NCHUNK2 (CC/KC2)     // 24
#define STRIDE 132
#define GSMEM (128*STRIDE*4)

// attention tiling
#define AQ 128
#define ACH 64
#define ANCH (MKEYS/ACH)     // 20
#define SM_Q 0               // [128][68] f32 (tf32 bits)
#define SM_K 34816           // 2 x [64][68] f32
#define SM_V 69632           // 2 x [64][100] u32 (bf16x2)
#define SM_P 120832          // [128][100] u32 (bf16x2)
#define ASMEM 172032

// ---------------- scratch ----------------
__device__ __align__(16) float    g_v[BB*HH*NN*DD];             // v (fp32, [bh][n][d])
__device__ __align__(16) float    g_p[BB*NN*CC];                // proj out, pre-LN
__device__ __align__(16) uint32_t g_xt[(size_t)BB*NN*CC];       // x  (tf32)
__device__ __align__(16) uint32_t g_ot[(size_t)BB*NN*CC];       // attn out (tf32)
__device__ __align__(16) uint32_t g_wqt[(size_t)3*CC*CC];       // qkv_w (tf32)
__device__ __align__(16) uint32_t g_wpt[(size_t)CC*CC];         // proj_w (tf32)
__device__ __align__(16) uint32_t g_qt[(size_t)BB*HH*NN*DD];    // q (tf32, scaled 1/8)
__device__ __align__(16) uint32_t g_kt[(size_t)BB*HH*MKEYS*DD]; // k + bank (tf32)
__device__ __align__(16) __nv_bfloat16 g_v3[(size_t)BB*HH*DD*3*MKEYS]; // v split [bh][d][3m]

// ---------------- PTX helpers ----------------
__device__ __forceinline__ uint32_t smem_u32(const void* p) {
    uint32_t a;
    asm("{ .reg .u64 t; cvta.to.shared.u64 t, %1; cvt.u32.u64 %0, t; }" : "=r"(a) : "l"(p));
    return a;
}
__device__ __forceinline__ void cp_async16(uint32_t dst, const void* src) {
    asm volatile("cp.async.cg.shared.global [%0], [%1], 16;" :: "r"(dst), "l"(src));
}
__device__ __forceinline__ void cp_commit() {
    asm volatile("cp.async.commit_group;");
}
template<int N>
__device__ __forceinline__ void cp_wait() {
    asm volatile("cp.async.wait_group %0;" :: "n"(N));
}
__device__ __forceinline__ void ldsm4(uint32_t* r, uint32_t addr) {
    asm volatile("ldmatrix.sync.aligned.m8n8.x4.shared.b16 {%0,%1,%2,%3}, [%4];"
                 : "=r"(r[0]), "=r"(r[1]), "=r"(r[2]), "=r"(r[3]) : "r"(addr));
}
__device__ __forceinline__ void mma16816(float* d, const uint32_t* a, const uint32_t* b) {
    asm volatile(
        "mma.sync.aligned.m16n8k16.row.col.f32.bf16.bf16.f32 "
        "{%0,%1,%2,%3}, {%4,%5,%6,%7}, {%8,%9}, {%0,%1,%2,%3};"
        : "+f"(d[0]), "+f"(d[1]), "+f"(d[2]), "+f"(d[3])
        : "r"(a[0]), "r"(a[1]), "r"(a[2]), "r"(a[3]), "r"(b[0]), "r"(b[1]));
}
__device__ __forceinline__ void mma1688(float* d, const uint32_t* a, const uint32_t* b) {
    asm volatile(
        "mma.sync.aligned.m16n8k8.row.col.f32.tf32.tf32.f32 "
        "{%0,%1,%2,%3}, {%4,%5,%6,%7}, {%8,%9}, {%0,%1,%2,%3};"
        : "+f"(d[0]), "+f"(d[1]), "+f"(d[2]), "+f"(d[3])
        : "r"(a[0]), "r"(a[1]), "r"(a[2]), "r"(a[3]), "r"(b[0]), "r"(b[1]));
}
__device__ __forceinline__ uint32_t tf32c(float f) {
    uint32_t r; asm("cvt.rna.tf32.f32 %0, %1;" : "=r"(r) : "f"(f)); return r;
}
__device__ __forceinline__ uint32_t pk_bf16(__nv_bfloat16 lo, __nv_bfloat16 hi) {
    uint16_t a = *(uint16_t*)&lo, b = *(uint16_t*)&hi;
    return (uint32_t)a | ((uint32_t)b << 16);
}

// ---------------------------------------------------------------------------
// tf32 pre-rounding (RNA): 0=x->g_xt  1=qkv_w->g_wqt  2=out->g_ot  3=proj_w->g_wpt
// ---------------------------------------------------------------------------
template<int W>
__global__ __launch_bounds__(256)
void convt(const float4* __restrict__ src, int n4)
{
    int i = blockIdx.x * blockDim.x + threadIdx.x;
    if (i >= n4) return;
    uint4* dst = (W == 0) ? (uint4*)g_xt : (W == 1) ? (uint4*)g_wqt
               : (W == 2) ? (uint4*)g_ot : (uint4*)g_wpt;
    float4 v = src[i];
    uint4 o;
    o.x = tf32c(v.x); o.y = tf32c(v.y); o.z = tf32c(v.z); o.w = tf32c(v.w);
    dst[i] = o;
}

// bank_k rows -> g_kt tail (tf32)
__global__ __launch_bounds__(256)
void convkt_bank(const float* __restrict__ bank_k)
{
    int i = blockIdx.x * blockDim.x + threadIdx.x;     // float4 index
    if (i >= BB*HH*BANKN*DD/4) return;
    int c4 = i & 15;
    int m  = (i >> 4) % BANKN;
    int bh = (i >> 4) / BANKN;
    int h  = bh % HH;
    float4 v = *(const float4*)(bank_k + (size_t)m * CC + h * DD + c4 * 4);
    uint4 o;
    o.x = tf32c(v.x); o.y = tf32c(v.y); o.z = tf32c(v.z); o.w = tf32c(v.w);
    *((uint4*)g_kt + (((size_t)bh * MKEYS + NN + m) * DD + c4 * 4) / 4) = o;
}

// g_v + bank_v -> [bh][d][3m] bf16 split
__global__ __launch_bounds__(256)
void convv3(const float* __restrict__ bank_v)
{
    __shared__ float t[64][65];
    const int tid = threadIdx.x;
    const int m0 = blockIdx.x * 64;
    const int bh = blockIdx.y;
    const int h  = bh % HH;
    #pragma unroll
    for (int i = 0; i < 4; i++) {
        int idx = tid + i * 256;
        int m = idx >> 4, d4 = (idx & 15) * 4;
        int gm = m0 + m;
        const float* src = (gm < NN)
            ? g_v + ((size_t)bh*NN + gm)*DD + d4
            : bank_v + (size_t)(gm - NN)*CC + h*DD + d4;
        float4 v = *(const float4*)src;
        t[m][d4] = v.x; t[m][d4+1] = v.y; t[m][d4+2] = v.z; t[m][d4+3] = v.w;
    }
    __syncthreads();
    const int d = tid >> 2, part = tid & 3;
    __nv_bfloat16 buf[48];
    #pragma unroll
    for (int mm = 0; mm < 16; mm++) {
        float f = t[part*16 + mm][d];
        __nv_bfloat16 hi = __float2bfloat16(f);
        __nv_bfloat16 lo = __float2bfloat16(f - __bfloat162float(hi));
        buf[3*mm] = hi; buf[3*mm+1] = lo; buf[3*mm+2] = hi;
    }
    uint4* dst = (uint4*)(g_v3 + ((size_t)bh*DD + d)*3*MKEYS + 3*(m0 + part*16));
    const uint4* sp = (const uint4*)buf;
    #pragma unroll
    for (int j = 0; j < 6; j++) dst[j] = sp[j];
}

// ---------------------------------------------------------------------------
// tf32 GEMM:  C[r, f] = sum_k A[r, k] * W[f, k]   (K = 768 tf32, fp32 accum)
// MODE 0: A=g_xt, W=g_wqt (2304 cols) -> q(tf32*0.125)->g_qt, k(tf32)->g_kt, v->g_v
// MODE 1: A=g_ot, W=g_wpt (768 cols)  -> g_p
// 128x128 tile, cp.async ping-pong chunks of 32 K-floats (128B rows, same
// byte geometry as the bf16 version), mma m16n8k8.tf32. 8 warps, 32x64 each.
// ---------------------------------------------------------------------------
template<int MODE>
__global__ __launch_bounds__(256)
void gemm_t(const float* __restrict__ bias)
{
    extern __shared__ __align__(1024) char sm[];
    const uint32_t smb = smem_u32(sm);
    const int tid = threadIdx.x, wid = tid >> 5, lane = tid & 31;
    const int row0 = blockIdx.x * 128, col0 = blockIdx.y * 128;
    const uint32_t* __restrict__ A = (MODE == 0) ? g_xt : g_ot;
    const uint32_t* __restrict__ W = (MODE == 0) ? g_wqt : g_wpt;

    const int wm = wid >> 1;
    const int wn = wid & 1;

    uint32_t abase[2]; uint32_t asw[2];
    #pragma unroll
    for (int mt = 0; mt < 2; mt++) {
        int r = wm * 32 + mt * 16 + (lane & 7) + ((lane >> 3) & 1) * 8;
        abase[mt] = (uint32_t)(r * 128);
        asw[mt]   = (uint32_t)(r & 7);
    }
    uint32_t bbase[4]; uint32_t bsw[4];
    #pragma unroll
    for (int p = 0; p < 4; p++) {
        int r = wn * 64 + p * 16 + (lane & 7) + ((lane >> 4) & 1) * 8;
        bbase[p] = (uint32_t)(r * 128);
        bsw[p]   = (uint32_t)(r & 7);
    }
    const uint32_t ka = (lane >> 4) & 1;
    const uint32_t kb = (lane >> 3) & 1;

    const int lr = tid >> 1;
    const int lu = (tid & 1) * 4;
    uint32_t st_off[4];
    #pragma unroll
    for (int it = 0; it < 4; it++) {
        int u = lu + it;
        st_off[it] = (uint32_t)(lr * 128 + (((uint32_t)u ^ (uint32_t)(lr & 7)) << 4));
    }

    float acc[2][8][4];
    #pragma unroll
    for (int mt = 0; mt < 2; mt++)
        #pragma unroll
        for (int nt = 0; nt < 8; nt++)
            #pragma unroll
            for (int c = 0; c < 4; c++) acc[mt][nt][c] = 0.0f;

    {
        const uint32_t* Asrc = A + (size_t)row0 * CC;
        const uint32_t* Wsrc = W + (size_t)col0 * CC;
        #pragma unroll
        for (int it = 0; it < 4; it++) {
            cp_async16(smb + st_off[it],         Asrc + (size_t)lr * CC + (lu + it) * 4);
            cp_async16(smb + 16384 + st_off[it], Wsrc + (size_t)lr * CC + (lu + it) * 4);
        }
        cp_commit();
    }

    for (int ch = 0; ch < NCHUNK2; ch++) {
        const uint32_t buf = smb + (ch & 1) * 32768;
        if (ch + 1 < NCHUNK2) {
            const uint32_t nbuf = smb + ((ch + 1) & 1) * 32768;
            const uint32_t* Asrc = A + (size_t)row0 * CC + (ch + 1) * KC2;
            const uint32_t* Wsrc = W + (size_t)col0 * CC + (ch + 1) * KC2;
            #pragma unroll
            for (int it = 0; it < 4; it++) {
                cp_async16(nbuf + st_off[it],         Asrc + (size_t)lr * CC + (lu + it) * 4);
                cp_async16(nbuf + 16384 + st_off[it], Wsrc + (size_t)lr * CC + (lu + it) * 4);
            }
            cp_commit();
            cp_wait<1>();
        } else {
            cp_wait<0>();
        }
        __syncthreads();

        // 4 k-steps of k8 per 32-float chunk; same 16B-group XOR addressing.
        #pragma unroll
        for (int ks = 0; ks < 4; ks++) {
            uint32_t af[2][4], bf[4][4];
            const uint32_t ga = ka + 2 * ks;
            const uint32_t gb = kb + 2 * ks;
            #pragma unroll
            for (int mt = 0; mt < 2; mt++)
                ldsm4(af[mt], buf + abase[mt] + ((ga ^ asw[mt]) << 4));
            #pragma unroll
            for (int p = 0; p < 4; p++)
                ldsm4(bf[p], buf + 16384 + bbase[p] + ((gb ^ bsw[p]) << 4));
            #pragma unroll
            for (int mt = 0; mt < 2; mt++)
                #pragma unroll
                for (int p = 0; p < 4; p++) {
                    mma1688(acc[mt][2*p],     af[mt], &bf[p][0]);
                    mma1688(acc[mt][2*p + 1], af[mt], &bf[p][2]);
                }
        }
        __syncthreads();
    }

    // -------- epilogue: regs -> stage smem -> coalesced conversion + scatter
    float* stage = (float*)sm;
    const int g   = lane >> 2;
    const int tp  = (lane & 3) * 2;
    #pragma unroll
    for (int mt = 0; mt < 2; mt++) {
        int rbase = wm * 32 + mt * 16 + g;
        #pragma unroll
        for (int nt = 0; nt < 8; nt++) {
            int cbase = wn * 64 + nt * 8 + tp;
            stage[rbase * STRIDE + cbase]           = acc[mt][nt][0];
            stage[rbase * STRIDE + cbase + 1]       = acc[mt][nt][1];
            stage[(rbase + 8) * STRIDE + cbase]     = acc[mt][nt][2];
            stage[(rbase + 8) * STRIDE + cbase + 1] = acc[mt][nt][3];
        }
    }
    __syncthreads();

    #pragma unroll
    for (int it = 0; it < 16; it++) {
        int idx = tid + it * 256;
        int r = idx >> 5, q = idx & 31, c = q * 4;
        float4 v = *(float4*)&stage[r * STRIDE + c];
        int f0 = col0 + c;
        v.x += bias[f0]; v.y += bias[f0 + 1]; v.z += bias[f0 + 2]; v.w += bias[f0 + 3];
        int gr = row0 + r;
        if (MODE == 0) {
            int b = gr >> 10, n = gr & 1023;
            int which = f0 / CC;
            int hd = f0 - which * CC;
            int h = hd >> 6, d = hd & 63;
            int bh = b * HH + h;
            if (which == 0) {
                uint4 o;
                o.x = tf32c(v.x * 0.125f); o.y = tf32c(v.y * 0.125f);
                o.z = tf32c(v.z * 0.125f); o.w = tf32c(v.w * 0.125f);
                *(uint4*)&g_qt[((size_t)bh * NN + n) * DD + d] = o;
            } else if (which == 1) {
                uint4 o;
                o.x = tf32c(v.x); o.y = tf32c(v.y); o.z = tf32c(v.z); o.w = tf32c(v.w);
                *(uint4*)&g_kt[((size_t)bh * MKEYS + n) * DD + d] = o;
            } else {
                *(float4*)&g_v[((size_t)bh * NN + n) * DD + d] = v;
            }
        } else {
            *(float4*)&g_p[(size_t)gr * CC + f0] = v;
        }
    }
}

// ---------------------------------------------------------------------------
// Tensor-core flash attention: tf32 QK^T + 3x-bf16-split PV (unchanged)
// ---------------------------------------------------------------------------
__global__ __launch_bounds__(256)
void attn2(float* __restrict__ out)
{
    extern __shared__ __align__(16) char sm[];
    const uint32_t smb = smem_u32(sm);
    const int tid = threadIdx.x, w = tid >> 5, lane = tid & 31;
    const int g = lane >> 2, c = lane & 3;
    const int bh = blockIdx.y, q0 = blockIdx.x * AQ;
    const int b = bh / HH, h = bh - b * HH;

    {
        const uint32_t* src = g_qt + ((size_t)bh * NN + q0) * DD;
        #pragma unroll
        for (int i = 0; i < 8; i++) {
            int idx = tid + i * 256;
            int r = idx >> 4, c16 = idx & 15;
            cp_async16(smb + SM_Q + r * 272 + c16 * 16, src + (size_t)r * DD + c16 * 4);
        }
        const uint32_t* ks = g_kt + (size_t)bh * MKEYS * DD;
        #pragma unroll
        for (int i = 0; i < 4; i++) {
            int idx = tid + i * 256;
            int r = idx >> 4, c16 = idx & 15;
            cp_async16(smb + SM_K + r * 272 + c16 * 16, ks + (size_t)r * DD + c16 * 4);
        }
        const __nv_bfloat16* vs = g_v3 + (size_t)bh * DD * 3 * MKEYS;
        #pragma unroll
        for (int i = 0; i < 6; i++) {
            int idx = tid + i * 256;
            int r = idx / 24, j = idx - r * 24;
            cp_async16(smb + SM_V + r * 400 + j * 16, vs + (size_t)r * 3 * MKEYS + j * 8);
        }
        cp_commit();
    }

    float mprev0 = -INFINITY, mprev1 = -INFINITY, l0 = 0.0f, l1 = 0.0f;
    float o[8][4];
    #pragma unroll
    for (int t = 0; t < 8; t++)
        #pragma unroll
        for (int j = 0; j < 4; j++) o[t][j] = 0.0f;

    for (int ch = 0; ch < ANCH; ch++) {
        const int buf = ch & 1;
        if (ch + 1 < ANCH) {
            const int nb = buf ^ 1;
            const uint32_t* ks = g_kt + ((size_t)bh * MKEYS + (ch + 1) * ACH) * DD;
            #pragma unroll
            for (int i = 0; i < 4; i++) {
                int idx = tid + i * 256;
                int r = idx >> 4, c16 = idx & 15;
                cp_async16(smb + SM_K + nb * 17408 + r * 272 + c16 * 16,
                           ks + (size_t)r * DD + c16 * 4);
            }
            const __nv_bfloat16* vs = g_v3 + (size_t)bh * DD * 3 * MKEYS + (ch + 1) * 192;
            #pragma unroll
            for (int i = 0; i < 6; i++) {
                int idx = tid + i * 256;
                int r = idx / 24, j = idx - r * 24;
                cp_async16(smb + SM_V + nb * 25600 + r * 400 + j * 16,
                           vs + (size_t)r * 3 * MKEYS + j * 8);
            }
            cp_commit();
            cp_wait<1>();
        } else {
            cp_wait<0>();
        }
        __syncthreads();

        const uint32_t* Qs = (const uint32_t*)(sm + SM_Q);
        const uint32_t* Ks = (const uint32_t*)(sm + SM_K + buf * 17408);
        float sacc[8][4];
        #pragma unroll
        for (int t = 0; t < 8; t++)
            #pragma unroll
            for (int j = 0; j < 4; j++) sacc[t][j] = 0.0f;

        #pragma unroll
        for (int ks = 0; ks < 8; ks++) {
            uint32_t a[4];
            const uint32_t* qb = Qs + (16 * w + g) * 68 + ks * 8 + c;
            a[0] = qb[0]; a[1] = qb[8 * 68]; a[2] = qb[4]; a[3] = qb[8 * 68 + 4];
            #pragma unroll
            for (int t = 0; t < 8; t++) {
                uint32_t bf[2];
                const uint32_t* kb = Ks + (t * 8 + g) * 68 + ks * 8 + c;
                bf[0] = kb[0]; bf[1] = kb[4];
                mma1688(sacc[t], a, bf);
            }
        }

        float mx0 = -INFINITY, mx1 = -INFINITY;
        #pragma unroll
        for (int t = 0; t < 8; t++) {
            mx0 = fmaxf(mx0, fmaxf(sacc[t][0], sacc[t][1]));
            mx1 = fmaxf(mx1, fmaxf(sacc[t][2], sacc[t][3]));
        }
        mx0 = fmaxf(mx0, __shfl_xor_sync(0xffffffffu, mx0, 1));
        mx0 = fmaxf(mx0, __shfl_xor_sync(0xffffffffu, mx0, 2));
        mx1 = fmaxf(mx1, __shfl_xor_sync(0xffffffffu, mx1, 1));
        mx1 = fmaxf(mx1, __shfl_xor_sync(0xffffffffu, mx1, 2));
        const float mnew0 = fmaxf(mprev0, mx0);
        const float mnew1 = fmaxf(mprev1, mx1);
        const float alpha0 = __expf(mprev0 - mnew0);
        const float alpha1 = __expf(mprev1 - mnew1);

        uint32_t* P0 = (uint32_t*)(sm + SM_P) + (16 * w + g) * 100;
        uint32_t* P1 = P0 + 8 * 100;
        float ps0 = 0.0f, ps1 = 0.0f;
        #pragma unroll
        for (int t = 0; t < 8; t++) {
            float p00 = __expf(sacc[t][0] - mnew0);
            float p01 = __expf(sacc[t][1] - mnew0);
            float p10 = __expf(sacc[t][2] - mnew1);
            float p11 = __expf(sacc[t][3] - mnew1);
            ps0 += p00 + p01; ps1 += p10 + p11;
            __nv_bfloat16 h00 = __float2bfloat16(p00);
            __nv_bfloat16 l00 = __float2bfloat16(p00 - __bfloat162float(h00));
            __nv_bfloat16 h01 = __float2bfloat16(p01);
            __nv_bfloat16 l01 = __float2bfloat16(p01 - __bfloat162float(h01));
            __nv_bfloat16 h10 = __float2bfloat16(p10);
            __nv_bfloat16 l10 = __float2bfloat16(p10 - __bfloat162float(h10));
            __nv_bfloat16 h11 = __float2bfloat16(p11);
            __nv_bfloat16 l11 = __float2bfloat16(p11 - __bfloat162float(h11));
            int base = 12 * t + 3 * c;
            P0[base]     = pk_bf16(h00, h00);
            P0[base + 1] = pk_bf16(l00, h01);
            P0[base + 2] = pk_bf16(h01, l01);
            P1[base]     = pk_bf16(h10, h10);
            P1[base + 1] = pk_bf16(l10, h11);
            P1[base + 2] = pk_bf16(h11, l11);
        }
        ps0 += __shfl_xor_sync(0xffffffffu, ps0, 1);
        ps0 += __shfl_xor_sync(0xffffffffu, ps0, 2);
        ps1 += __shfl_xor_sync(0xffffffffu, ps1, 1);
        ps1 += __shfl_xor_sync(0xffffffffu, ps1, 2);
        l0 = l0 * alpha0 + ps0; l1 = l1 * alpha1 + ps1;
        mprev0 = mnew0; mprev1 = mnew1;
        #pragma unroll
        for (int t = 0; t < 8; t++) {
            o[t][0] *= alpha0; o[t][1] *= alpha0;
            o[t][2] *= alpha1; o[t][3] *= alpha1;
        }
        __syncwarp();

        const uint32_t* Pw = (const uint32_t*)(sm + SM_P) + 16 * w * 100;
        const uint32_t* Vs = (const uint32_t*)(sm + SM_V + buf * 25600);
        #pragma unroll
        for (int k2 = 0; k2 < 12; k2++) {
            uint32_t a[4];
            const uint32_t* pb = Pw + g * 100 + k2 * 8 + c;
            a[0] = pb[0]; a[1] = pb[8 * 100]; a[2] = pb[4]; a[3] = pb[8 * 100 + 4];
            #pragma unroll
            for (int t = 0; t < 8; t++) {
                uint32_t bf[2];
                const uint32_t* vb = Vs + (t * 8 + g) * 100 + k2 * 8 + c;
                bf[0] = vb[0]; bf[1] = vb[4];
                mma16816(o[t], a, bf);
            }
        }
        __syncthreads();
    }

    const float inv0 = 1.0f / l0, inv1 = 1.0f / l1;
    const int n0 = q0 + 16 * w + g, n1 = n0 + 8;
    #pragma unroll
    for (int t = 0; t < 8; t++) {
        int col = h * DD + 8 * t + 2 * c;
        float2 v0 = make_float2(o[t][0] * inv0, o[t][1] * inv0);
        float2 v1 = make_float2(o[t][2] * inv1, o[t][3] * inv1);
        *(float2*)&out[((size_t)b * NN + n0) * CC + col] = v0;
        *(float2*)&out[((size_t)b * NN + n1) * CC + col] = v1;
    }
}

// ---------------------------------------------------------------------------
__global__ __launch_bounds__(256)
void ln_kernel(const float* __restrict__ nw, const float* __restrict__ nb,
               float* __restrict__ outb)
{
    __shared__ float shs[8], shs2[8];
    const int row = blockIdx.x;
    const int tid = threadIdx.x;
    const float* pr = g_p + (size_t)row * CC;

    float v[3];
    float s = 0.0f, s2 = 0.0f;
    #pragma unroll
    for (int i = 0; i < 3; i++) {
        v[i] = pr[tid + i * 256];
        s  += v[i];
        s2 += v[i] * v[i];
    }
    #pragma unroll
    for (int off = 16; off >= 1; off >>= 1) {
        s  += __shfl_xor_sync(0xffffffffu, s,  off);
        s2 += __shfl_xor_sync(0xffffffffu, s2, off);
    }
    if ((tid & 31) == 0) { shs[tid >> 5] = s; shs2[tid >> 5] = s2; }
    __syncthreads();
    float ts = 0.0f, ts2 = 0.0f;
    #pragma unroll
    for (int w = 0; w < 8; w++) { ts += shs[w]; ts2 += shs2[w]; }

    const float mu  = ts * (1.0f / CC);
    const float var = ts2 * (1.0f / CC) - mu * mu;
    const float r   = rsqrtf(var + 1e-5f);

    #pragma unroll
    for (int i = 0; i < 3; i++) {
        int c = tid + i * 256;
        outb[(size_t)row * CC + c] = (v[i] - mu) * r * nw[c] + nb[c];
    }
}

// ---------------------------------------------------------------------------
extern "C" void kernel_launch(void* const* d_in, const int* in_sizes, int n_in,
                              void* d_out, int out_size)
{
    const float* x      = (const float*)d_in[0];
    const float* qkv_w  = (const float*)d_in[1];
    const float* qkv_b  = (const float*)d_in[2];
    const float* proj_w = (const float*)d_in[3];
    const float* proj_b = (const float*)d_in[4];
    const float* norm_w = (const float*)d_in[5];
    const float* norm_b = (const float*)d_in[6];
    const float* bank_k = (const float*)d_in[7];
    const float* bank_v = (const float*)d_in[8];

    float* out      = (float*)d_out;
    float* bank_upd = out + (size_t)BB * NN * CC;

    cudaFuncSetAttribute(attn2, cudaFuncAttributeMaxDynamicSharedMemorySize, ASMEM);
    cudaFuncSetAttribute(gemm_t<0>, cudaFuncAttributeMaxDynamicSharedMemorySize, GSMEM);
    cudaFuncSetAttribute(gemm_t<1>, cudaFuncAttributeMaxDynamicSharedMemorySize, GSMEM);

    const int nx4  = BB * NN * CC / 4;       // 3145728
    const int nwq4 = 3 * CC * CC / 4;        // 442368
    const int nwp4 = CC * CC / 4;            // 147456
    const int nbk4 = BB * HH * BANKN * DD / 4;

    // 1) tf32 pre-round x, qkv_w
    convt<0><<<(nx4 + 255) / 256, 256>>>((const float4*)x, nx4);
    convt<1><<<(nwq4 + 255) / 256, 256>>>((const float4*)qkv_w, nwq4);
    // 2) QKV GEMM (tf32) -> g_qt (scaled tf32), g_kt (tf32), g_v (fp32)
    gemm_t<0><<<dim3(128, 18), 256, GSMEM>>>(qkv_b);
    // 3) bank tails + V split
    convkt_bank<<<(nbk4 + 255) / 256, 256>>>(bank_k);
    convv3<<<dim3(ANCH, BB*HH), 256>>>(bank_v);
    // 4) flash attention -> out
    attn2<<<dim3(NN / AQ, BB * HH), 256, ASMEM>>>(out);
    // 5) tf32 pre-round out, proj_w; proj GEMM -> g_p
    convt<2><<<(nx4 + 255) / 256, 256>>>((const float4*)out, nx4);
    convt<3><<<(nwp4 + 255) / 256, 256>>>((const float4*)proj_w, nwp4);
    gemm_t<1><<<dim3(128, 6), 256, GSMEM>>>(proj_b);
    // 6) LayerNorm -> bank_update
    ln_kernel<<<BB * NN, 256>>>(norm_w, norm_b, bank_upd);
}

// round 12
// speedup vs baseline: 2.7985x; 1.0695x over previous
#include <cuda_runtime.h>
#include <cuda_bf16.h>
#include <cstdint>
#include <math.h>

#define BB 16
#define NN 1024
#define CC 768
#define HH 12
#define DD 64
#define BANKN 256
#define MKEYS (NN + BANKN)   // 1280
#define KC2 32               // fp32 K elems per chunk (128 B rows)
#define NCHUNK2 (CC/KC2)     // 24
#define STRIDE 132
#define GSMEM 98304          // 3 x 32768 pipeline stages (>= 67584 stage buf)

#define LOG2E 1.44269504088896f

// attention tiling
#define AQ 128
#define ACH 64
#define ANCH (MKEYS/ACH)     // 20
#define SM_Q 0               // [128][68] f32 (tf32 bits)
#define SM_K 34816           // 2 x [64][68] f32
#define SM_V 69632           // 2 x [64][100] u32 (bf16x2)
#define SM_P 120832          // [128][100] u32 (bf16x2)
#define ASMEM 172032

// ---------------- scratch ----------------
__device__ __align__(16) float    g_v[BB*HH*NN*DD];             // v (fp32, [bh][n][d])
__device__ __align__(16) float    g_p[BB*NN*CC];                // proj out, pre-LN
__device__ __align__(16) uint32_t g_xt[(size_t)BB*NN*CC];       // x  (tf32)
__device__ __align__(16) uint32_t g_ot[(size_t)BB*NN*CC];       // attn out (tf32)
__device__ __align__(16) uint32_t g_wqt[(size_t)3*CC*CC];       // qkv_w (tf32)
__device__ __align__(16) uint32_t g_wpt[(size_t)CC*CC];         // proj_w (tf32)
__device__ __align__(16) uint32_t g_qt[(size_t)BB*HH*NN*DD];    // q (tf32, scaled log2e/8)
__device__ __align__(16) uint32_t g_kt[(size_t)BB*HH*MKEYS*DD]; // k + bank (tf32)
__device__ __align__(16) __nv_bfloat16 g_v3[(size_t)BB*HH*DD*3*MKEYS]; // v split [bh][d][3m]

// ---------------- PTX helpers ----------------
__device__ __forceinline__ uint32_t smem_u32(const void* p) {
    uint32_t a;
    asm("{ .reg .u64 t; cvta.to.shared.u64 t, %1; cvt.u32.u64 %0, t; }" : "=r"(a) : "l"(p));
    return a;
}
__device__ __forceinline__ void cp_async16(uint32_t dst, const void* src) {
    asm volatile("cp.async.cg.shared.global [%0], [%1], 16;" :: "r"(dst), "l"(src));
}
__device__ __forceinline__ void cp_commit() {
    asm volatile("cp.async.commit_group;");
}
template<int N>
__device__ __forceinline__ void cp_wait() {
    asm volatile("cp.async.wait_group %0;" :: "n"(N));
}
__device__ __forceinline__ void ldsm4(uint32_t* r, uint32_t addr) {
    asm volatile("ldmatrix.sync.aligned.m8n8.x4.shared.b16 {%0,%1,%2,%3}, [%4];"
                 : "=r"(r[0]), "=r"(r[1]), "=r"(r[2]), "=r"(r[3]) : "r"(addr));
}
__device__ __forceinline__ void mma16816(float* d, const uint32_t* a, const uint32_t* b) {
    asm volatile(
        "mma.sync.aligned.m16n8k16.row.col.f32.bf16.bf16.f32 "
        "{%0,%1,%2,%3}, {%4,%5,%6,%7}, {%8,%9}, {%0,%1,%2,%3};"
        : "+f"(d[0]), "+f"(d[1]), "+f"(d[2]), "+f"(d[3])
        : "r"(a[0]), "r"(a[1]), "r"(a[2]), "r"(a[3]), "r"(b[0]), "r"(b[1]));
}
__device__ __forceinline__ void mma1688(float* d, const uint32_t* a, const uint32_t* b) {
    asm volatile(
        "mma.sync.aligned.m16n8k8.row.col.f32.tf32.tf32.f32 "
        "{%0,%1,%2,%3}, {%4,%5,%6,%7}, {%8,%9}, {%0,%1,%2,%3};"
        : "+f"(d[0]), "+f"(d[1]), "+f"(d[2]), "+f"(d[3])
        : "r"(a[0]), "r"(a[1]), "r"(a[2]), "r"(a[3]), "r"(b[0]), "r"(b[1]));
}
__device__ __forceinline__ uint32_t tf32c(float f) {
    uint32_t r; asm("cvt.rna.tf32.f32 %0, %1;" : "=r"(r) : "f"(f)); return r;
}
__device__ __forceinline__ float ex2(float x) {
    float r; asm("ex2.approx.ftz.f32 %0, %1;" : "=f"(r) : "f"(x)); return r;
}
__device__ __forceinline__ uint32_t pk_bf16(__nv_bfloat16 lo, __nv_bfloat16 hi) {
    uint16_t a = *(uint16_t*)&lo, b = *(uint16_t*)&hi;
    return (uint32_t)a | ((uint32_t)b << 16);
}

// ---------------------------------------------------------------------------
// tf32 pre-rounding (RNA): 0=x->g_xt  1=qkv_w->g_wqt  3=proj_w->g_wpt
// ---------------------------------------------------------------------------
template<int W>
__global__ __launch_bounds__(256)
void convt(const float4* __restrict__ src, int n4)
{
    int i = blockIdx.x * blockDim.x + threadIdx.x;
    if (i >= n4) return;
    uint4* dst = (W == 0) ? (uint4*)g_xt : (W == 1) ? (uint4*)g_wqt : (uint4*)g_wpt;
    float4 v = src[i];
    uint4 o;
    o.x = tf32c(v.x); o.y = tf32c(v.y); o.z = tf32c(v.z); o.w = tf32c(v.w);
    dst[i] = o;
}

// bank_k rows -> g_kt tail (tf32)
__global__ __launch_bounds__(256)
void convkt_bank(const float* __restrict__ bank_k)
{
    int i = blockIdx.x * blockDim.x + threadIdx.x;     // float4 index
    if (i >= BB*HH*BANKN*DD/4) return;
    int c4 = i & 15;
    int m  = (i >> 4) % BANKN;
    int bh = (i >> 4) / BANKN;
    int h  = bh % HH;
    float4 v = *(const float4*)(bank_k + (size_t)m * CC + h * DD + c4 * 4);
    uint4 o;
    o.x = tf32c(v.x); o.y = tf32c(v.y); o.z = tf32c(v.z); o.w = tf32c(v.w);
    *((uint4*)g_kt + (((size_t)bh * MKEYS + NN + m) * DD + c4 * 4) / 4) = o;
}

// g_v + bank_v -> [bh][d][3m] bf16 split
__global__ __launch_bounds__(256)
void convv3(const float* __restrict__ bank_v)
{
    __shared__ float t[64][65];
    const int tid = threadIdx.x;
    const int m0 = blockIdx.x * 64;
    const int bh = blockIdx.y;
    const int h  = bh % HH;
    #pragma unroll
    for (int i = 0; i < 4; i++) {
        int idx = tid + i * 256;
        int m = idx >> 4, d4 = (idx & 15) * 4;
        int gm = m0 + m;
        const float* src = (gm < NN)
            ? g_v + ((size_t)bh*NN + gm)*DD + d4
            : bank_v + (size_t)(gm - NN)*CC + h*DD + d4;
        float4 v = *(const float4*)src;
        t[m][d4] = v.x; t[m][d4+1] = v.y; t[m][d4+2] = v.z; t[m][d4+3] = v.w;
    }
    __syncthreads();
    const int d = tid >> 2, part = tid & 3;
    __nv_bfloat16 buf[48];
    #pragma unroll
    for (int mm = 0; mm < 16; mm++) {
        float f = t[part*16 + mm][d];
        __nv_bfloat16 hi = __float2bfloat16(f);
        __nv_bfloat16 lo = __float2bfloat16(f - __bfloat162float(hi));
        buf[3*mm] = hi; buf[3*mm+1] = lo; buf[3*mm+2] = hi;
    }
    uint4* dst = (uint4*)(g_v3 + ((size_t)bh*DD + d)*3*MKEYS + 3*(m0 + part*16));
    const uint4* sp = (const uint4*)buf;
    #pragma unroll
    for (int j = 0; j < 6; j++) dst[j] = sp[j];
}

// ---------------------------------------------------------------------------
// tf32 GEMM, 3-stage cp.async pipeline. 128x128 tile, mma m16n8k8.tf32.
// MODE 0 -> q (tf32 * 0.125*log2e) -> g_qt, k (tf32) -> g_kt, v -> g_v
// MODE 1 -> g_p
// ---------------------------------------------------------------------------
template<int MODE>
__global__ __launch_bounds__(256)
void gemm_t(const float* __restrict__ bias)
{
    extern __shared__ __align__(1024) char sm[];
    const uint32_t smb = smem_u32(sm);
    const int tid = threadIdx.x, wid = tid >> 5, lane = tid & 31;
    const int row0 = blockIdx.x * 128, col0 = blockIdx.y * 128;
    const uint32_t* __restrict__ A = (MODE == 0) ? g_xt : g_ot;
    const uint32_t* __restrict__ W = (MODE == 0) ? g_wqt : g_wpt;

    const int wm = wid >> 1;
    const int wn = wid & 1;

    uint32_t abase[2]; uint32_t asw[2];
    #pragma unroll
    for (int mt = 0; mt < 2; mt++) {
        int r = wm * 32 + mt * 16 + (lane & 7) + ((lane >> 3) & 1) * 8;
        abase[mt] = (uint32_t)(r * 128);
        asw[mt]   = (uint32_t)(r & 7);
    }
    uint32_t bbase[4]; uint32_t bsw[4];
    #pragma unroll
    for (int p = 0; p < 4; p++) {
        int r = wn * 64 + p * 16 + (lane & 7) + ((lane >> 4) & 1) * 8;
        bbase[p] = (uint32_t)(r * 128);
        bsw[p]   = (uint32_t)(r & 7);
    }
    const uint32_t ka = (lane >> 4) & 1;
    const uint32_t kb = (lane >> 3) & 1;

    const int lr = tid >> 1;
    const int lu = (tid & 1) * 4;
    uint32_t st_off[4];
    #pragma unroll
    for (int it = 0; it < 4; it++) {
        int u = lu + it;
        st_off[it] = (uint32_t)(lr * 128 + (((uint32_t)u ^ (uint32_t)(lr & 7)) << 4));
    }

    float acc[2][8][4];
    #pragma unroll
    for (int mt = 0; mt < 2; mt++)
        #pragma unroll
        for (int nt = 0; nt < 8; nt++)
            #pragma unroll
            for (int c = 0; c < 4; c++) acc[mt][nt][c] = 0.0f;

    // -------- prologue: load chunks 0, 1
    #pragma unroll
    for (int pre = 0; pre < 2; pre++) {
        const uint32_t pbuf = smb + pre * 32768;
        const uint32_t* Asrc = A + (size_t)row0 * CC + pre * KC2;
        const uint32_t* Wsrc = W + (size_t)col0 * CC + pre * KC2;
        #pragma unroll
        for (int it = 0; it < 4; it++) {
            cp_async16(pbuf + st_off[it],         Asrc + (size_t)lr * CC + (lu + it) * 4);
            cp_async16(pbuf + 16384 + st_off[it], Wsrc + (size_t)lr * CC + (lu + it) * 4);
        }
        cp_commit();
    }

    int bufsel = 0;
    for (int ch = 0; ch < NCHUNK2; ch++) {
        const uint32_t buf = smb + bufsel * 32768;
        if (ch + 2 < NCHUNK2) {
            int nb = bufsel + 2; if (nb >= 3) nb -= 3;
            const uint32_t nbuf = smb + nb * 32768;
            const uint32_t* Asrc = A + (size_t)row0 * CC + (ch + 2) * KC2;
            const uint32_t* Wsrc = W + (size_t)col0 * CC + (ch + 2) * KC2;
            #pragma unroll
            for (int it = 0; it < 4; it++) {
                cp_async16(nbuf + st_off[it],         Asrc + (size_t)lr * CC + (lu + it) * 4);
                cp_async16(nbuf + 16384 + st_off[it], Wsrc + (size_t)lr * CC + (lu + it) * 4);
            }
            cp_commit();
            cp_wait<2>();
        } else if (ch + 1 < NCHUNK2) {
            cp_wait<1>();
        } else {
            cp_wait<0>();
        }
        __syncthreads();

        #pragma unroll
        for (int ks = 0; ks < 4; ks++) {
            uint32_t af[2][4], bf[4][4];
            const uint32_t ga = ka + 2 * ks;
            const uint32_t gb = kb + 2 * ks;
            #pragma unroll
            for (int mt = 0; mt < 2; mt++)
                ldsm4(af[mt], buf + abase[mt] + ((ga ^ asw[mt]) << 4));
            #pragma unroll
            for (int p = 0; p < 4; p++)
                ldsm4(bf[p], buf + 16384 + bbase[p] + ((gb ^ bsw[p]) << 4));
            #pragma unroll
            for (int mt = 0; mt < 2; mt++)
                #pragma unroll
                for (int p = 0; p < 4; p++) {
                    mma1688(acc[mt][2*p],     af[mt], &bf[p][0]);
                    mma1688(acc[mt][2*p + 1], af[mt], &bf[p][2]);
                }
        }
        __syncthreads();
        if (++bufsel == 3) bufsel = 0;
    }

    // -------- epilogue
    float* stage = (float*)sm;
    const int g   = lane >> 2;
    const int tp  = (lane & 3) * 2;
    #pragma unroll
    for (int mt = 0; mt < 2; mt++) {
        int rbase = wm * 32 + mt * 16 + g;
        #pragma unroll
        for (int nt = 0; nt < 8; nt++) {
            int cbase = wn * 64 + nt * 8 + tp;
            stage[rbase * STRIDE + cbase]           = acc[mt][nt][0];
            stage[rbase * STRIDE + cbase + 1]       = acc[mt][nt][1];
            stage[(rbase + 8) * STRIDE + cbase]     = acc[mt][nt][2];
            stage[(rbase + 8) * STRIDE + cbase + 1] = acc[mt][nt][3];
        }
    }
    __syncthreads();

    #pragma unroll
    for (int it = 0; it < 16; it++) {
        int idx = tid + it * 256;
        int r = idx >> 5, q = idx & 31, c = q * 4;
        float4 v = *(float4*)&stage[r * STRIDE + c];
        int f0 = col0 + c;
        v.x += bias[f0]; v.y += bias[f0 + 1]; v.z += bias[f0 + 2]; v.w += bias[f0 + 3];
        int gr = row0 + r;
        if (MODE == 0) {
            int b = gr >> 10, n = gr & 1023;
            int which = f0 / CC;
            int hd = f0 - which * CC;
            int h = hd >> 6, d = hd & 63;
            int bh = b * HH + h;
            if (which == 0) {
                const float qs = 0.125f * LOG2E;    // fold log2e for exp2 softmax
                uint4 o;
                o.x = tf32c(v.x * qs); o.y = tf32c(v.y * qs);
                o.z = tf32c(v.z * qs); o.w = tf32c(v.w * qs);
                *(uint4*)&g_qt[((size_t)bh * NN + n) * DD + d] = o;
            } else if (which == 1) {
                uint4 o;
                o.x = tf32c(v.x); o.y = tf32c(v.y); o.z = tf32c(v.z); o.w = tf32c(v.w);
                *(uint4*)&g_kt[((size_t)bh * MKEYS + n) * DD + d] = o;
            } else {
                *(float4*)&g_v[((size_t)bh * NN + n) * DD + d] = v;
            }
        } else {
            *(float4*)&g_p[(size_t)gr * CC + f0] = v;
        }
    }
}

// ---------------------------------------------------------------------------
// Tensor-core flash attention: tf32 QK^T (exp2 domain) + 3x-bf16-split PV.
// V fragments loaded via ldmatrix.x4. Epilogue also emits tf32 copy (g_ot).
// ---------------------------------------------------------------------------
__global__ __launch_bounds__(256)
void attn2(float* __restrict__ out)
{
    extern __shared__ __align__(16) char sm[];
    const uint32_t smb = smem_u32(sm);
    const int tid = threadIdx.x, w = tid >> 5, lane = tid & 31;
    const int g = lane >> 2, c = lane & 3;
    const int bh = blockIdx.y, q0 = blockIdx.x * AQ;
    const int b = bh / HH, h = bh - b * HH;

    // ldmatrix V fragment base addresses (pitch 400B, conflict-free)
    uint32_t vab[4];
    #pragma unroll
    for (int p = 0; p < 4; p++) {
        int vr = p * 16 + (lane & 7) + ((lane >> 4) & 1) * 8;
        vab[p] = smb + SM_V + (uint32_t)vr * 400 + ((lane >> 3) & 1) * 16;
    }

    {
        const uint32_t* src = g_qt + ((size_t)bh * NN + q0) * DD;
        #pragma unroll
        for (int i = 0; i < 8; i++) {
            int idx = tid + i * 256;
            int r = idx >> 4, c16 = idx & 15;
            cp_async16(smb + SM_Q + r * 272 + c16 * 16, src + (size_t)r * DD + c16 * 4);
        }
        const uint32_t* ks = g_kt + (size_t)bh * MKEYS * DD;
        #pragma unroll
        for (int i = 0; i < 4; i++) {
            int idx = tid + i * 256;
            int r = idx >> 4, c16 = idx & 15;
            cp_async16(smb + SM_K + r * 272 + c16 * 16, ks + (size_t)r * DD + c16 * 4);
        }
        const __nv_bfloat16* vs = g_v3 + (size_t)bh * DD * 3 * MKEYS;
        #pragma unroll
        for (int i = 0; i < 6; i++) {
            int idx = tid + i * 256;
            int r = idx / 24, j = idx - r * 24;
            cp_async16(smb + SM_V + r * 400 + j * 16, vs + (size_t)r * 3 * MKEYS + j * 8);
        }
        cp_commit();
    }

    float mprev0 = -INFINITY, mprev1 = -INFINITY, l0 = 0.0f, l1 = 0.0f;
    float o[8][4];
    #pragma unroll
    for (int t = 0; t < 8; t++)
        #pragma unroll
        for (int j = 0; j < 4; j++) o[t][j] = 0.0f;

    for (int ch = 0; ch < ANCH; ch++) {
        const int buf = ch & 1;
        if (ch + 1 < ANCH) {
            const int nb = buf ^ 1;
            const uint32_t* ks = g_kt + ((size_t)bh * MKEYS + (ch + 1) * ACH) * DD;
            #pragma unroll
            for (int i = 0; i < 4; i++) {
                int idx = tid + i * 256;
                int r = idx >> 4, c16 = idx & 15;
                cp_async16(smb + SM_K + nb * 17408 + r * 272 + c16 * 16,
                           ks + (size_t)r * DD + c16 * 4);
            }
            const __nv_bfloat16* vs = g_v3 + (size_t)bh * DD * 3 * MKEYS + (ch + 1) * 192;
            #pragma unroll
            for (int i = 0; i < 6; i++) {
                int idx = tid + i * 256;
                int r = idx / 24, j = idx - r * 24;
                cp_async16(smb + SM_V + nb * 25600 + r * 400 + j * 16,
                           vs + (size_t)r * 3 * MKEYS + j * 8);
            }
            cp_commit();
            cp_wait<1>();
        } else {
            cp_wait<0>();
        }
        __syncthreads();

        // ---- S = Q K^T (tf32, log2 domain)
        const uint32_t* Qs = (const uint32_t*)(sm + SM_Q);
        const uint32_t* Ks = (const uint32_t*)(sm + SM_K + buf * 17408);
        float sacc[8][4];
        #pragma unroll
        for (int t = 0; t < 8; t++)
            #pragma unroll
            for (int j = 0; j < 4; j++) sacc[t][j] = 0.0f;

        #pragma unroll
        for (int ks = 0; ks < 8; ks++) {
            uint32_t a[4];
            const uint32_t* qb = Qs + (16 * w + g) * 68 + ks * 8 + c;
            a[0] = qb[0]; a[1] = qb[8 * 68]; a[2] = qb[4]; a[3] = qb[8 * 68 + 4];
            #pragma unroll
            for (int t = 0; t < 8; t++) {
                uint32_t bf[2];
                const uint32_t* kb2 = Ks + (t * 8 + g) * 68 + ks * 8 + c;
                bf[0] = kb2[0]; bf[1] = kb2[4];
                mma1688(sacc[t], a, bf);
            }
        }

        // ---- online softmax (exp2)
        float mx0 = -INFINITY, mx1 = -INFINITY;
        #pragma unroll
        for (int t = 0; t < 8; t++) {
            mx0 = fmaxf(mx0, fmaxf(sacc[t][0], sacc[t][1]));
            mx1 = fmaxf(mx1, fmaxf(sacc[t][2], sacc[t][3]));
        }
        mx0 = fmaxf(mx0, __shfl_xor_sync(0xffffffffu, mx0, 1));
        mx0 = fmaxf(mx0, __shfl_xor_sync(0xffffffffu, mx0, 2));
        mx1 = fmaxf(mx1, __shfl_xor_sync(0xffffffffu, mx1, 1));
        mx1 = fmaxf(mx1, __shfl_xor_sync(0xffffffffu, mx1, 2));
        const float mnew0 = fmaxf(mprev0, mx0);
        const float mnew1 = fmaxf(mprev1, mx1);
        const float alpha0 = ex2(mprev0 - mnew0);
        const float alpha1 = ex2(mprev1 - mnew1);

        uint32_t* P0 = (uint32_t*)(sm + SM_P) + (16 * w + g) * 100;
        uint32_t* P1 = P0 + 8 * 100;
        float ps0 = 0.0f, ps1 = 0.0f;
        #pragma unroll
        for (int t = 0; t < 8; t++) {
            float p00 = ex2(sacc[t][0] - mnew0);
            float p01 = ex2(sacc[t][1] - mnew0);
            float p10 = ex2(sacc[t][2] - mnew1);
            float p11 = ex2(sacc[t][3] - mnew1);
            ps0 += p00 + p01; ps1 += p10 + p11;
            __nv_bfloat16 h00 = __float2bfloat16(p00);
            __nv_bfloat16 l00 = __float2bfloat16(p00 - __bfloat162float(h00));
            __nv_bfloat16 h01 = __float2bfloat16(p01);
            __nv_bfloat16 l01 = __float2bfloat16(p01 - __bfloat162float(h01));
            __nv_bfloat16 h10 = __float2bfloat16(p10);
            __nv_bfloat16 l10 = __float2bfloat16(p10 - __bfloat162float(h10));
            __nv_bfloat16 h11 = __float2bfloat16(p11);
            __nv_bfloat16 l11 = __float2bfloat16(p11 - __bfloat162float(h11));
            int base = 12 * t + 3 * c;
            P0[base]     = pk_bf16(h00, h00);
            P0[base + 1] = pk_bf16(l00, h01);
            P0[base + 2] = pk_bf16(h01, l01);
            P1[base]     = pk_bf16(h10, h10);
            P1[base + 1] = pk_bf16(l10, h11);
            P1[base + 2] = pk_bf16(h11, l11);
        }
        ps0 += __shfl_xor_sync(0xffffffffu, ps0, 1);
        ps0 += __shfl_xor_sync(0xffffffffu, ps0, 2);
        ps1 += __shfl_xor_sync(0xffffffffu, ps1, 1);
        ps1 += __shfl_xor_sync(0xffffffffu, ps1, 2);
        l0 = l0 * alpha0 + ps0; l1 = l1 * alpha1 + ps1;
        mprev0 = mnew0; mprev1 = mnew1;
        #pragma unroll
        for (int t = 0; t < 8; t++) {
            o[t][0] *= alpha0; o[t][1] *= alpha0;
            o[t][2] *= alpha1; o[t][3] *= alpha1;
        }
        __syncwarp();

        // ---- O += P3 V3 (bf16 split) -- V fragments via ldmatrix.x4
        const uint32_t* Pw = (const uint32_t*)(sm + SM_P) + 16 * w * 100;
        const uint32_t vbuf_off = buf * 25600;
        #pragma unroll
        for (int k2 = 0; k2 < 12; k2++) {
            uint32_t a[4];
            const uint32_t* pb = Pw + g * 100 + k2 * 8 + c;
            a[0] = pb[0]; a[1] = pb[8 * 100]; a[2] = pb[4]; a[3] = pb[8 * 100 + 4];
            uint32_t bf[4][4];
            #pragma unroll
            for (int p = 0; p < 4; p++)
                ldsm4(bf[p], vab[p] + vbuf_off + k2 * 32);
            #pragma unroll
            for (int p = 0; p < 4; p++) {
                mma16816(o[2*p],     a, &bf[p][0]);
                mma16816(o[2*p + 1], a, &bf[p][2]);
            }
        }
        __syncthreads();
    }

    // ---- normalize + write out (fp32) and g_ot (tf32)
    const float inv0 = 1.0f / l0, inv1 = 1.0f / l1;
    const int n0 = q0 + 16 * w + g, n1 = n0 + 8;
    #pragma unroll
    for (int t = 0; t < 8; t++) {
        int col = h * DD + 8 * t + 2 * c;
        float v00 = o[t][0] * inv0, v01 = o[t][1] * inv0;
        float v10 = o[t][2] * inv1, v11 = o[t][3] * inv1;
        *(float2*)&out[((size_t)b * NN + n0) * CC + col] = make_float2(v00, v01);
        *(float2*)&out[((size_t)b * NN + n1) * CC + col] = make_float2(v10, v11);
        uint2 t0; t0.x = tf32c(v00); t0.y = tf32c(v01);
        uint2 t1; t1.x = tf32c(v10); t1.y = tf32c(v11);
        *(uint2*)&g_ot[((size_t)b * NN + n0) * CC + col] = t0;
        *(uint2*)&g_ot[((size_t)b * NN + n1) * CC + col] = t1;
    }
}

// ---------------------------------------------------------------------------
__global__ __launch_bounds__(256)
void ln_kernel(const float* __restrict__ nw, const float* __restrict__ nb,
               float* __restrict__ outb)
{
    __shared__ float shs[8], shs2[8];
    const int row = blockIdx.x;
    const int tid = threadIdx.x;
    const float* pr = g_p + (size_t)row * CC;

    float v[3];
    float s = 0.0f, s2 = 0.0f;
    #pragma unroll
    for (int i = 0; i < 3; i++) {
        v[i] = pr[tid + i * 256];
        s  += v[i];
        s2 += v[i] * v[i];
    }
    #pragma unroll
    for (int off = 16; off >= 1; off >>= 1) {
        s  += __shfl_xor_sync(0xffffffffu, s,  off);
        s2 += __shfl_xor_sync(0xffffffffu, s2, off);
    }
    if ((tid & 31) == 0) { shs[tid >> 5] = s; shs2[tid >> 5] = s2; }
    __syncthreads();
    float ts = 0.0f, ts2 = 0.0f;
    #pragma unroll
    for (int w = 0; w < 8; w++) { ts += shs[w]; ts2 += shs2[w]; }

    const float mu  = ts * (1.0f / CC);
    const float var = ts2 * (1.0f / CC) - mu * mu;
    const float r   = rsqrtf(var + 1e-5f);

    #pragma unroll
    for (int i = 0; i < 3; i++) {
        int c = tid + i * 256;
        outb[(size_t)row * CC + c] = (v[i] - mu) * r * nw[c] + nb[c];
    }
}

// ---------------------------------------------------------------------------
extern "C" void kernel_launch(void* const* d_in, const int* in_sizes, int n_in,
                              void* d_out, int out_size)
{
    const float* x      = (const float*)d_in[0];
    const float* qkv_w  = (const float*)d_in[1];
    const float* qkv_b  = (const float*)d_in[2];
    const float* proj_w = (const float*)d_in[3];
    const float* proj_b = (const float*)d_in[4];
    const float* norm_w = (const float*)d_in[5];
    const float* norm_b = (const float*)d_in[6];
    const float* bank_k = (const float*)d_in[7];
    const float* bank_v = (const float*)d_in[8];

    float* out      = (float*)d_out;
    float* bank_upd = out + (size_t)BB * NN * CC;

    cudaFuncSetAttribute(attn2, cudaFuncAttributeMaxDynamicSharedMemorySize, ASMEM);
    cudaFuncSetAttribute(gemm_t<0>, cudaFuncAttributeMaxDynamicSharedMemorySize, GSMEM);
    cudaFuncSetAttribute(gemm_t<1>, cudaFuncAttributeMaxDynamicSharedMemorySize, GSMEM);

    const int nx4  = BB * NN * CC / 4;
    const int nwq4 = 3 * CC * CC / 4;
    const int nwp4 = CC * CC / 4;
    const int nbk4 = BB * HH * BANKN * DD / 4;

    // 1) tf32 pre-round x, qkv_w
    convt<0><<<(nx4 + 255) / 256, 256>>>((const float4*)x, nx4);
    convt<1><<<(nwq4 + 255) / 256, 256>>>((const float4*)qkv_w, nwq4);
    // 2) QKV GEMM (tf32)
    gemm_t<0><<<dim3(128, 18), 256, GSMEM>>>(qkv_b);
    // 3) bank tails + V split
    convkt_bank<<<(nbk4 + 255) / 256, 256>>>(bank_k);
    convv3<<<dim3(ANCH, BB*HH), 256>>>(bank_v);
    // 4) flash attention -> out (fp32) + g_ot (tf32)
    attn2<<<dim3(NN / AQ, BB * HH), 256, ASMEM>>>(out);
    // 5) proj weights tf32; proj GEMM -> g_p
    convt<3><<<(nwp4 + 255) / 256, 256>>>((const float4*)proj_w, nwp4);
    gemm_t<1><<<dim3(128, 6), 256, GSMEM>>>(proj_b);
    // 6) LayerNorm -> bank_update
    ln_kernel<<<BB * NN, 256>>>(norm_w, norm_b, bank_upd);
}

// round 13
// speedup vs baseline: 3.0484x; 1.0893x over previous
#include <cuda_runtime.h>
#include <cuda_bf16.h>
#include <cstdint>
#include <math.h>

#define BB 16
#define NN 1024
#define CC 768
#define HH 12
#define DD 64
#define BANKN 256
#define MKEYS (NN + BANKN)   // 1280
#define KC2 32               // fp32 K elems per chunk (128 B rows)
#define NCHUNK2 (CC/KC2)     // 24
#define STRIDE 132
#define GSMEM 98304          // 3 x 32768 pipeline stages (>= 67584 stage buf)

#define LOG2E 1.44269504088896f

// attention tiling
#define AQ 128
#define ACH 64
#define ANCH (MKEYS/ACH)     // 20
#define SM_Q 0               // [128][68] f32 (tf32 bits)
#define SM_K 34816           // 2 x [64][68] f32
#define SM_V 69632           // 2 x [64][100] u32 (bf16x2)
#define SM_P 120832          // [128][100] u32 (bf16x2)
#define ASMEM 172032

// ---------------- scratch ----------------
__device__ __align__(16) float    g_v[BB*HH*NN*DD];             // v (fp32, [bh][n][d])
__device__ __align__(16) float    g_p[BB*NN*CC];                // proj out, pre-LN
__device__ __align__(16) uint32_t g_xt[(size_t)BB*NN*CC];       // x  (tf32)
__device__ __align__(16) uint32_t g_ot[(size_t)BB*NN*CC];       // attn out (tf32)
__device__ __align__(16) uint32_t g_wqt[(size_t)3*CC*CC];       // qkv_w (tf32)
__device__ __align__(16) uint32_t g_wpt[(size_t)CC*CC];         // proj_w (tf32)
__device__ __align__(16) uint32_t g_qt[(size_t)BB*HH*NN*DD];    // q (tf32, scaled log2e/8)
__device__ __align__(16) uint32_t g_kt[(size_t)BB*HH*MKEYS*DD]; // k + bank (tf32)
__device__ __align__(16) __nv_bfloat16 g_v3[(size_t)BB*HH*DD*3*MKEYS]; // v split [bh][d][3m]

// ---------------- PTX helpers ----------------
__device__ __forceinline__ uint32_t smem_u32(const void* p) {
    uint32_t a;
    asm("{ .reg .u64 t; cvta.to.shared.u64 t, %1; cvt.u32.u64 %0, t; }" : "=r"(a) : "l"(p));
    return a;
}
__device__ __forceinline__ void cp_async16(uint32_t dst, const void* src) {
    asm volatile("cp.async.cg.shared.global [%0], [%1], 16;" :: "r"(dst), "l"(src));
}
__device__ __forceinline__ void cp_commit() {
    asm volatile("cp.async.commit_group;");
}
template<int N>
__device__ __forceinline__ void cp_wait() {
    asm volatile("cp.async.wait_group %0;" :: "n"(N));
}
__device__ __forceinline__ void ldsm4(uint32_t* r, uint32_t addr) {
    asm volatile("ldmatrix.sync.aligned.m8n8.x4.shared.b16 {%0,%1,%2,%3}, [%4];"
                 : "=r"(r[0]), "=r"(r[1]), "=r"(r[2]), "=r"(r[3]) : "r"(addr));
}
__device__ __forceinline__ void mma16816(float* d, const uint32_t* a, const uint32_t* b) {
    asm volatile(
        "mma.sync.aligned.m16n8k16.row.col.f32.bf16.bf16.f32 "
        "{%0,%1,%2,%3}, {%4,%5,%6,%7}, {%8,%9}, {%0,%1,%2,%3};"
        : "+f"(d[0]), "+f"(d[1]), "+f"(d[2]), "+f"(d[3])
        : "r"(a[0]), "r"(a[1]), "r"(a[2]), "r"(a[3]), "r"(b[0]), "r"(b[1]));
}
__device__ __forceinline__ void mma1688(float* d, const uint32_t* a, const uint32_t* b) {
    asm volatile(
        "mma.sync.aligned.m16n8k8.row.col.f32.tf32.tf32.f32 "
        "{%0,%1,%2,%3}, {%4,%5,%6,%7}, {%8,%9}, {%0,%1,%2,%3};"
        : "+f"(d[0]), "+f"(d[1]), "+f"(d[2]), "+f"(d[3])
        : "r"(a[0]), "r"(a[1]), "r"(a[2]), "r"(a[3]), "r"(b[0]), "r"(b[1]));
}
__device__ __forceinline__ uint32_t tf32c(float f) {
    uint32_t r; asm("cvt.rna.tf32.f32 %0, %1;" : "=r"(r) : "f"(f)); return r;
}
__device__ __forceinline__ float ex2(float x) {
    float r; asm("ex2.approx.ftz.f32 %0, %1;" : "=f"(r) : "f"(x)); return r;
}

// ---------------------------------------------------------------------------
// tf32 pre-rounding (RNA): 0=x->g_xt  1=qkv_w->g_wqt  3=proj_w->g_wpt
// ---------------------------------------------------------------------------
template<int W>
__global__ __launch_bounds__(256)
void convt(const float4* __restrict__ src, int n4)
{
    int i = blockIdx.x * blockDim.x + threadIdx.x;
    if (i >= n4) return;
    uint4* dst = (W == 0) ? (uint4*)g_xt : (W == 1) ? (uint4*)g_wqt : (uint4*)g_wpt;
    float4 v = src[i];
    uint4 o;
    o.x = tf32c(v.x); o.y = tf32c(v.y); o.z = tf32c(v.z); o.w = tf32c(v.w);
    dst[i] = o;
}

// bank_k rows -> g_kt tail (tf32)
__global__ __launch_bounds__(256)
void convkt_bank(const float* __restrict__ bank_k)
{
    int i = blockIdx.x * blockDim.x + threadIdx.x;     // float4 index
    if (i >= BB*HH*BANKN*DD/4) return;
    int c4 = i & 15;
    int m  = (i >> 4) % BANKN;
    int bh = (i >> 4) / BANKN;
    int h  = bh % HH;
    float4 v = *(const float4*)(bank_k + (size_t)m * CC + h * DD + c4 * 4);
    uint4 o;
    o.x = tf32c(v.x); o.y = tf32c(v.y); o.z = tf32c(v.z); o.w = tf32c(v.w);
    *((uint4*)g_kt + (((size_t)bh * MKEYS + NN + m) * DD + c4 * 4) / 4) = o;
}

// g_v + bank_v -> [bh][d][3m] bf16 split
__global__ __launch_bounds__(256)
void convv3(const float* __restrict__ bank_v)
{
    __shared__ float t[64][65];
    const int tid = threadIdx.x;
    const int m0 = blockIdx.x * 64;
    const int bh = blockIdx.y;
    const int h  = bh % HH;
    #pragma unroll
    for (int i = 0; i < 4; i++) {
        int idx = tid + i * 256;
        int m = idx >> 4, d4 = (idx & 15) * 4;
        int gm = m0 + m;
        const float* src = (gm < NN)
            ? g_v + ((size_t)bh*NN + gm)*DD + d4
            : bank_v + (size_t)(gm - NN)*CC + h*DD + d4;
        float4 v = *(const float4*)src;
        t[m][d4] = v.x; t[m][d4+1] = v.y; t[m][d4+2] = v.z; t[m][d4+3] = v.w;
    }
    __syncthreads();
    const int d = tid >> 2, part = tid & 3;
    __nv_bfloat16 buf[48];
    #pragma unroll
    for (int mm = 0; mm < 16; mm++) {
        float f = t[part*16 + mm][d];
        __nv_bfloat16 hi = __float2bfloat16(f);
        __nv_bfloat16 lo = __float2bfloat16(f - __bfloat162float(hi));
        buf[3*mm] = hi; buf[3*mm+1] = lo; buf[3*mm+2] = hi;
    }
    uint4* dst = (uint4*)(g_v3 + ((size_t)bh*DD + d)*3*MKEYS + 3*(m0 + part*16));
    const uint4* sp = (const uint4*)buf;
    #pragma unroll
    for (int j = 0; j < 6; j++) dst[j] = sp[j];
}

// ---------------------------------------------------------------------------
// tf32 GEMM, 3-stage cp.async pipeline. 128x128 tile, mma m16n8k8.tf32.
// MODE 0 -> q (tf32 * 0.125*log2e) -> g_qt, k (tf32) -> g_kt, v -> g_v
// MODE 1 -> g_p
// ---------------------------------------------------------------------------
template<int MODE>
__global__ __launch_bounds__(256)
void gemm_t(const float* __restrict__ bias)
{
    extern __shared__ __align__(1024) char sm[];
    const uint32_t smb = smem_u32(sm);
    const int tid = threadIdx.x, wid = tid >> 5, lane = tid & 31;
    const int row0 = blockIdx.x * 128, col0 = blockIdx.y * 128;
    const uint32_t* __restrict__ A = (MODE == 0) ? g_xt : g_ot;
    const uint32_t* __restrict__ W = (MODE == 0) ? g_wqt : g_wpt;

    const int wm = wid >> 1;
    const int wn = wid & 1;

    uint32_t abase[2]; uint32_t asw[2];
    #pragma unroll
    for (int mt = 0; mt < 2; mt++) {
        int r = wm * 32 + mt * 16 + (lane & 7) + ((lane >> 3) & 1) * 8;
        abase[mt] = (uint32_t)(r * 128);
        asw[mt]   = (uint32_t)(r & 7);
    }
    uint32_t bbase[4]; uint32_t bsw[4];
    #pragma unroll
    for (int p = 0; p < 4; p++) {
        int r = wn * 64 + p * 16 + (lane & 7) + ((lane >> 4) & 1) * 8;
        bbase[p] = (uint32_t)(r * 128);
        bsw[p]   = (uint32_t)(r & 7);
    }
    const uint32_t ka = (lane >> 4) & 1;
    const uint32_t kb = (lane >> 3) & 1;

    const int lr = tid >> 1;
    const int lu = (tid & 1) * 4;
    uint32_t st_off[4];
    #pragma unroll
    for (int it = 0; it < 4; it++) {
        int u = lu + it;
        st_off[it] = (uint32_t)(lr * 128 + (((uint32_t)u ^ (uint32_t)(lr & 7)) << 4));
    }

    float acc[2][8][4];
    #pragma unroll
    for (int mt = 0; mt < 2; mt++)
        #pragma unroll
        for (int nt = 0; nt < 8; nt++)
            #pragma unroll
            for (int c = 0; c < 4; c++) acc[mt][nt][c] = 0.0f;

    // -------- prologue: load chunks 0, 1
    #pragma unroll
    for (int pre = 0; pre < 2; pre++) {
        const uint32_t pbuf = smb + pre * 32768;
        const uint32_t* Asrc = A + (size_t)row0 * CC + pre * KC2;
        const uint32_t* Wsrc = W + (size_t)col0 * CC + pre * KC2;
        #pragma unroll
        for (int it = 0; it < 4; it++) {
            cp_async16(pbuf + st_off[it],         Asrc + (size_t)lr * CC + (lu + it) * 4);
            cp_async16(pbuf + 16384 + st_off[it], Wsrc + (size_t)lr * CC + (lu + it) * 4);
        }
        cp_commit();
    }

    int bufsel = 0;
    for (int ch = 0; ch < NCHUNK2; ch++) {
        const uint32_t buf = smb + bufsel * 32768;
        if (ch + 2 < NCHUNK2) {
            int nb = bufsel + 2; if (nb >= 3) nb -= 3;
            const uint32_t nbuf = smb + nb * 32768;
            const uint32_t* Asrc = A + (size_t)row0 * CC + (ch + 2) * KC2;
            const uint32_t* Wsrc = W + (size_t)col0 * CC + (ch + 2) * KC2;
            #pragma unroll
            for (int it = 0; it < 4; it++) {
                cp_async16(nbuf + st_off[it],         Asrc + (size_t)lr * CC + (lu + it) * 4);
                cp_async16(nbuf + 16384 + st_off[it], Wsrc + (size_t)lr * CC + (lu + it) * 4);
            }
            cp_commit();
            cp_wait<2>();
        } else if (ch + 1 < NCHUNK2) {
            cp_wait<1>();
        } else {
            cp_wait<0>();
        }
        __syncthreads();

        #pragma unroll
        for (int ks = 0; ks < 4; ks++) {
            uint32_t af[2][4], bf[4][4];
            const uint32_t ga = ka + 2 * ks;
            const uint32_t gb = kb + 2 * ks;
            #pragma unroll
            for (int mt = 0; mt < 2; mt++)
                ldsm4(af[mt], buf + abase[mt] + ((ga ^ asw[mt]) << 4));
            #pragma unroll
            for (int p = 0; p < 4; p++)
                ldsm4(bf[p], buf + 16384 + bbase[p] + ((gb ^ bsw[p]) << 4));
            #pragma unroll
            for (int mt = 0; mt < 2; mt++)
                #pragma unroll
                for (int p = 0; p < 4; p++) {
                    mma1688(acc[mt][2*p],     af[mt], &bf[p][0]);
                    mma1688(acc[mt][2*p + 1], af[mt], &bf[p][2]);
                }
        }
        __syncthreads();
        if (++bufsel == 3) bufsel = 0;
    }

    // -------- epilogue
    float* stage = (float*)sm;
    const int g   = lane >> 2;
    const int tp  = (lane & 3) * 2;
    #pragma unroll
    for (int mt = 0; mt < 2; mt++) {
        int rbase = wm * 32 + mt * 16 + g;
        #pragma unroll
        for (int nt = 0; nt < 8; nt++) {
            int cbase = wn * 64 + nt * 8 + tp;
            stage[rbase * STRIDE + cbase]           = acc[mt][nt][0];
            stage[rbase * STRIDE + cbase + 1]       = acc[mt][nt][1];
            stage[(rbase + 8) * STRIDE + cbase]     = acc[mt][nt][2];
            stage[(rbase + 8) * STRIDE + cbase + 1] = acc[mt][nt][3];
        }
    }
    __syncthreads();

    #pragma unroll
    for (int it = 0; it < 16; it++) {
        int idx = tid + it * 256;
        int r = idx >> 5, q = idx & 31, c = q * 4;
        float4 v = *(float4*)&stage[r * STRIDE + c];
        int f0 = col0 + c;
        v.x += bias[f0]; v.y += bias[f0 + 1]; v.z += bias[f0 + 2]; v.w += bias[f0 + 3];
        int gr = row0 + r;
        if (MODE == 0) {
            int b = gr >> 10, n = gr & 1023;
            int which = f0 / CC;
            int hd = f0 - which * CC;
            int h = hd >> 6, d = hd & 63;
            int bh = b * HH + h;
            if (which == 0) {
                const float qs = 0.125f * LOG2E;    // fold log2e for exp2 softmax
                uint4 o;
                o.x = tf32c(v.x * qs); o.y = tf32c(v.y * qs);
                o.z = tf32c(v.z * qs); o.w = tf32c(v.w * qs);
                *(uint4*)&g_qt[((size_t)bh * NN + n) * DD + d] = o;
            } else if (which == 1) {
                uint4 o;
                o.x = tf32c(v.x); o.y = tf32c(v.y); o.z = tf32c(v.z); o.w = tf32c(v.w);
                *(uint4*)&g_kt[((size_t)bh * MKEYS + n) * DD + d] = o;
            } else {
                *(float4*)&g_v[((size_t)bh * NN + n) * DD + d] = v;
            }
        } else {
            *(float4*)&g_p[(size_t)gr * CC + f0] = v;
        }
    }
}

// ---------------------------------------------------------------------------
// Tensor-core flash attention: tf32 QK^T (exp2 domain) + 3x-bf16-split PV.
// Q fragments hoisted to registers; P split via PRMT truncation (no cvt).
// ---------------------------------------------------------------------------
__global__ __launch_bounds__(256)
void attn2(float* __restrict__ out)
{
    extern __shared__ __align__(16) char sm[];
    const uint32_t smb = smem_u32(sm);
    const int tid = threadIdx.x, w = tid >> 5, lane = tid & 31;
    const int g = lane >> 2, c = lane & 3;
    const int bh = blockIdx.y, q0 = blockIdx.x * AQ;
    const int b = bh / HH, h = bh - b * HH;

    // ldmatrix V fragment base addresses (pitch 400B, conflict-free)
    uint32_t vab[4];
    #pragma unroll
    for (int p = 0; p < 4; p++) {
        int vr = p * 16 + (lane & 7) + ((lane >> 4) & 1) * 8;
        vab[p] = smb + SM_V + (uint32_t)vr * 400 + ((lane >> 3) & 1) * 16;
    }

    {
        const uint32_t* src = g_qt + ((size_t)bh * NN + q0) * DD;
        #pragma unroll
        for (int i = 0; i < 8; i++) {
            int idx = tid + i * 256;
            int r = idx >> 4, c16 = idx & 15;
            cp_async16(smb + SM_Q + r * 272 + c16 * 16, src + (size_t)r * DD + c16 * 4);
        }
        const uint32_t* ks = g_kt + (size_t)bh * MKEYS * DD;
        #pragma unroll
        for (int i = 0; i < 4; i++) {
            int idx = tid + i * 256;
            int r = idx >> 4, c16 = idx & 15;
            cp_async16(smb + SM_K + r * 272 + c16 * 16, ks + (size_t)r * DD + c16 * 4);
        }
        const __nv_bfloat16* vs = g_v3 + (size_t)bh * DD * 3 * MKEYS;
        #pragma unroll
        for (int i = 0; i < 6; i++) {
            int idx = tid + i * 256;
            int r = idx / 24, j = idx - r * 24;
            cp_async16(smb + SM_V + r * 400 + j * 16, vs + (size_t)r * 3 * MKEYS + j * 8);
        }
        cp_commit();
    }

    float mprev0 = -INFINITY, mprev1 = -INFINITY, l0 = 0.0f, l1 = 0.0f;
    float o[8][4];
    #pragma unroll
    for (int t = 0; t < 8; t++)
        #pragma unroll
        for (int j = 0; j < 4; j++) o[t][j] = 0.0f;

    uint32_t qfrag[8][4];   // hoisted Q fragments (loop-invariant)

    for (int ch = 0; ch < ANCH; ch++) {
        const int buf = ch & 1;
        if (ch + 1 < ANCH) {
            const int nb = buf ^ 1;
            const uint32_t* ks = g_kt + ((size_t)bh * MKEYS + (ch + 1) * ACH) * DD;
            #pragma unroll
            for (int i = 0; i < 4; i++) {
                int idx = tid + i * 256;
                int r = idx >> 4, c16 = idx & 15;
                cp_async16(smb + SM_K + nb * 17408 + r * 272 + c16 * 16,
                           ks + (size_t)r * DD + c16 * 4);
            }
            const __nv_bfloat16* vs = g_v3 + (size_t)bh * DD * 3 * MKEYS + (ch + 1) * 192;
            #pragma unroll
            for (int i = 0; i < 6; i++) {
                int idx = tid + i * 256;
                int r = idx / 24, j = idx - r * 24;
                cp_async16(smb + SM_V + nb * 25600 + r * 400 + j * 16,
                           vs + (size_t)r * 3 * MKEYS + j * 8);
            }
            cp_commit();
            cp_wait<1>();
        } else {
            cp_wait<0>();
        }
        __syncthreads();

        if (ch == 0) {
            // hoist Q fragments once (Q smem is never overwritten)
            const uint32_t* Qs = (const uint32_t*)(sm + SM_Q);
            #pragma unroll
            for (int ks = 0; ks < 8; ks++) {
                const uint32_t* qb = Qs + (16 * w + g) * 68 + ks * 8 + c;
                qfrag[ks][0] = qb[0]; qfrag[ks][1] = qb[8 * 68];
                qfrag[ks][2] = qb[4]; qfrag[ks][3] = qb[8 * 68 + 4];
            }
        }

        // ---- S = Q K^T (tf32, log2 domain)
        const uint32_t* Ks = (const uint32_t*)(sm + SM_K + buf * 17408);
        float sacc[8][4];
        #pragma unroll
        for (int t = 0; t < 8; t++)
            #pragma unroll
            for (int j = 0; j < 4; j++) sacc[t][j] = 0.0f;

        #pragma unroll
        for (int ks = 0; ks < 8; ks++) {
            #pragma unroll
            for (int t = 0; t < 8; t++) {
                uint32_t bf[2];
                const uint32_t* kb2 = Ks + (t * 8 + g) * 68 + ks * 8 + c;
                bf[0] = kb2[0]; bf[1] = kb2[4];
                mma1688(sacc[t], qfrag[ks], bf);
            }
        }

        // ---- online softmax (exp2)
        float mx0 = -INFINITY, mx1 = -INFINITY;
        #pragma unroll
        for (int t = 0; t < 8; t++) {
            mx0 = fmaxf(mx0, fmaxf(sacc[t][0], sacc[t][1]));
            mx1 = fmaxf(mx1, fmaxf(sacc[t][2], sacc[t][3]));
        }
        mx0 = fmaxf(mx0, __shfl_xor_sync(0xffffffffu, mx0, 1));
        mx0 = fmaxf(mx0, __shfl_xor_sync(0xffffffffu, mx0, 2));
        mx1 = fmaxf(mx1, __shfl_xor_sync(0xffffffffu, mx1, 1));
        mx1 = fmaxf(mx1, __shfl_xor_sync(0xffffffffu, mx1, 2));
        const float mnew0 = fmaxf(mprev0, mx0);
        const float mnew1 = fmaxf(mprev1, mx1);
        const float alpha0 = ex2(mprev0 - mnew0);
        const float alpha1 = ex2(mprev1 - mnew1);

        // P split via truncation: hi = p & 0xFFFF0000 (exact in fp32),
        // lo = p - hi (exact). Packs are single PRMTs -- no F2FP cvts.
        uint32_t* P0 = (uint32_t*)(sm + SM_P) + (16 * w + g) * 100;
        uint32_t* P1 = P0 + 8 * 100;
        float ps0 = 0.0f, ps1 = 0.0f;
        #pragma unroll
        for (int t = 0; t < 8; t++) {
            float p00 = ex2(sacc[t][0] - mnew0);
            float p01 = ex2(sacc[t][1] - mnew0);
            float p10 = ex2(sacc[t][2] - mnew1);
            float p11 = ex2(sacc[t][3] - mnew1);
            ps0 += p00 + p01; ps1 += p10 + p11;
            uint32_t r00 = __float_as_uint(p00), r01 = __float_as_uint(p01);
            uint32_t r10 = __float_as_uint(p10), r11 = __float_as_uint(p11);
            float lo00 = p00 - __uint_as_float(r00 & 0xFFFF0000u);
            float lo01 = p01 - __uint_as_float(r01 & 0xFFFF0000u);
            float lo10 = p10 - __uint_as_float(r10 & 0xFFFF0000u);
            float lo11 = p11 - __uint_as_float(r11 & 0xFFFF0000u);
            uint32_t rl00 = __float_as_uint(lo00), rl01 = __float_as_uint(lo01);
            uint32_t rl10 = __float_as_uint(lo10), rl11 = __float_as_uint(lo11);
            int base = 12 * t + 3 * c;
            P0[base]     = __byte_perm(r00,  r00,  0x7632);   // (h00, h00)
            P0[base + 1] = __byte_perm(rl00, r01,  0x7632);   // (l00, h01)
            P0[base + 2] = __byte_perm(r01,  rl01, 0x7632);   // (h01, l01)
            P1[base]     = __byte_perm(r10,  r10,  0x7632);
            P1[base + 1] = __byte_perm(rl10, r11,  0x7632);
            P1[base + 2] = __byte_perm(r11,  rl11, 0x7632);
        }
        ps0 += __shfl_xor_sync(0xffffffffu, ps0, 1);
        ps0 += __shfl_xor_sync(0xffffffffu, ps0, 2);
        ps1 += __shfl_xor_sync(0xffffffffu, ps1, 1);
        ps1 += __shfl_xor_sync(0xffffffffu, ps1, 2);
        l0 = l0 * alpha0 + ps0; l1 = l1 * alpha1 + ps1;
        mprev0 = mnew0; mprev1 = mnew1;
        #pragma unroll
        for (int t = 0; t < 8; t++) {
            o[t][0] *= alpha0; o[t][1] *= alpha0;
            o[t][2] *= alpha1; o[t][3] *= alpha1;
        }
        __syncwarp();

        // ---- O += P3 V3 (bf16 split) -- V fragments via ldmatrix.x4
        const uint32_t* Pw = (const uint32_t*)(sm + SM_P) + 16 * w * 100;
        const uint32_t vbuf_off = buf * 25600;
        #pragma unroll
        for (int k2 = 0; k2 < 12; k2++) {
            uint32_t a[4];
            const uint32_t* pb = Pw + g * 100 + k2 * 8 + c;
            a[0] = pb[0]; a[1] = pb[8 * 100]; a[2] = pb[4]; a[3] = pb[8 * 100 + 4];
            uint32_t bf[4][4];
            #pragma unroll
            for (int p = 0; p < 4; p++)
                ldsm4(bf[p], vab[p] + vbuf_off + k2 * 32);
            #pragma unroll
            for (int p = 0; p < 4; p++) {
                mma16816(o[2*p],     a, &bf[p][0]);
                mma16816(o[2*p + 1], a, &bf[p][2]);
            }
        }
        __syncthreads();
    }

    // ---- normalize + write out (fp32) and g_ot (tf32)
    const float inv0 = 1.0f / l0, inv1 = 1.0f / l1;
    const int n0 = q0 + 16 * w + g, n1 = n0 + 8;
    #pragma unroll
    for (int t = 0; t < 8; t++) {
        int col = h * DD + 8 * t + 2 * c;
        float v00 = o[t][0] * inv0, v01 = o[t][1] * inv0;
        float v10 = o[t][2] * inv1, v11 = o[t][3] * inv1;
        *(float2*)&out[((size_t)b * NN + n0) * CC + col] = make_float2(v00, v01);
        *(float2*)&out[((size_t)b * NN + n1) * CC + col] = make_float2(v10, v11);
        uint2 t0; t0.x = tf32c(v00); t0.y = tf32c(v01);
        uint2 t1; t1.x = tf32c(v10); t1.y = tf32c(v11);
        *(uint2*)&g_ot[((size_t)b * NN + n0) * CC + col] = t0;
        *(uint2*)&g_ot[((size_t)b * NN + n1) * CC + col] = t1;
    }
}

// ---------------------------------------------------------------------------
__global__ __launch_bounds__(256)
void ln_kernel(const float* __restrict__ nw, const float* __restrict__ nb,
               float* __restrict__ outb)
{
    __shared__ float shs[8], shs2[8];
    const int row = blockIdx.x;
    const int tid = threadIdx.x;
    const float* pr = g_p + (size_t)row * CC;

    float v[3];
    float s = 0.0f, s2 = 0.0f;
    #pragma unroll
    for (int i = 0; i < 3; i++) {
        v[i] = pr[tid + i * 256];
        s  += v[i];
        s2 += v[i] * v[i];
    }
    #pragma unroll
    for (int off = 16; off >= 1; off >>= 1) {
        s  += __shfl_xor_sync(0xffffffffu, s,  off);
        s2 += __shfl_xor_sync(0xffffffffu, s2, off);
    }
    if ((tid & 31) == 0) { shs[tid >> 5] = s; shs2[tid >> 5] = s2; }
    __syncthreads();
    float ts = 0.0f, ts2 = 0.0f;
    #pragma unroll
    for (int w = 0; w < 8; w++) { ts += shs[w]; ts2 += shs2[w]; }

    const float mu  = ts * (1.0f / CC);
    const float var = ts2 * (1.0f / CC) - mu * mu;
    const float r   = rsqrtf(var + 1e-5f);

    #pragma unroll
    for (int i = 0; i < 3; i++) {
        int c = tid + i * 256;
        outb[(size_t)row * CC + c] = (v[i] - mu) * r * nw[c] + nb[c];
    }
}

// ---------------------------------------------------------------------------
extern "C" void kernel_launch(void* const* d_in, const int* in_sizes, int n_in,
                              void* d_out, int out_size)
{
    const float* x      = (const float*)d_in[0];
    const float* qkv_w  = (const float*)d_in[1];
    const float* qkv_b  = (const float*)d_in[2];
    const float* proj_w = (const float*)d_in[3];
    const float* proj_b = (const float*)d_in[4];
    const float* norm_w = (const float*)d_in[5];
    const float* norm_b = (const float*)d_in[6];
    const float* bank_k = (const float*)d_in[7];
    const float* bank_v = (const float*)d_in[8];

    float* out      = (float*)d_out;
    float* bank_upd = out + (size_t)BB * NN * CC;

    cudaFuncSetAttribute(attn2, cudaFuncAttributeMaxDynamicSharedMemorySize, ASMEM);
    cudaFuncSetAttribute(gemm_t<0>, cudaFuncAttributeMaxDynamicSharedMemorySize, GSMEM);
    cudaFuncSetAttribute(gemm_t<1>, cudaFuncAttributeMaxDynamicSharedMemorySize, GSMEM);

    const int nx4  = BB * NN * CC / 4;
    const int nwq4 = 3 * CC * CC / 4;
    const int nwp4 = CC * CC / 4;
    const int nbk4 = BB * HH * BANKN * DD / 4;

    // independent conversions first (overlap with ramp / fill idle SMs)
    convkt_bank<<<(nbk4 + 255) / 256, 256>>>(bank_k);
    convt<0><<<(nx4 + 255) / 256, 256>>>((const float4*)x, nx4);
    convt<1><<<(nwq4 + 255) / 256, 256>>>((const float4*)qkv_w, nwq4);
    convt<3><<<(nwp4 + 255) / 256, 256>>>((const float4*)proj_w, nwp4);
    // QKV GEMM (tf32)
    gemm_t<0><<<dim3(128, 18), 256, GSMEM>>>(qkv_b);
    // V split
    convv3<<<dim3(ANCH, BB*HH), 256>>>(bank_v);
    // flash attention -> out (fp32) + g_ot (tf32)
    attn2<<<dim3(NN / AQ, BB * HH), 256, ASMEM>>>(out);
    // proj GEMM -> g_p
    gemm_t<1><<<dim3(128, 6), 256, GSMEM>>>(proj_b);
    // LayerNorm -> bank_update
    ln_kernel<<<BB * NN, 256>>>(norm_w, norm_b, bank_upd);
}

// round 14
// speedup vs baseline: 3.1132x; 1.0213x over previous
#include <cuda_runtime.h>
#include <cuda_bf16.h>
#include <cstdint>
#include <math.h>

#define BB 16
#define NN 1024
#define CC 768
#define HH 12
#define DD 64
#define BANKN 256
#define MKEYS (NN + BANKN)   // 1280
#define KC2 32               // fp32 K elems per chunk (128 B rows)
#define NCHUNK2 (CC/KC2)     // 24
#define STRIDE 132
#define TILE_M 256
#define GTHREADS 512
#define STAGE_BYTES 49152    // A 32KB + B 16KB
#define GSMEM (3*STAGE_BYTES)// 147456 (also covers 256*132*4=135168 stage buf)

#define LOG2E 1.44269504088896f

// attention tiling
#define AQ 128
#define ACH 64
#define ANCH (MKEYS/ACH)     // 20
#define SM_Q 0               // [128][68] f32 (tf32 bits)
#define SM_K 34816           // 2 x [64][68] f32
#define SM_V 69632           // 2 x [64][100] u32 (bf16x2)
#define SM_P 120832          // [128][100] u32 (bf16x2)
#define ASMEM 172032

// ---------------- scratch ----------------
__device__ __align__(16) float    g_v[BB*HH*NN*DD];             // v (fp32, [bh][n][d])
__device__ __align__(16) float    g_p[BB*NN*CC];                // proj out, pre-LN
__device__ __align__(16) uint32_t g_xt[(size_t)BB*NN*CC];       // x  (tf32)
__device__ __align__(16) uint32_t g_ot[(size_t)BB*NN*CC];       // attn out (tf32)
__device__ __align__(16) uint32_t g_wqt[(size_t)3*CC*CC];       // qkv_w (tf32)
__device__ __align__(16) uint32_t g_wpt[(size_t)CC*CC];         // proj_w (tf32)
__device__ __align__(16) uint32_t g_qt[(size_t)BB*HH*NN*DD];    // q (tf32, scaled log2e/8)
__device__ __align__(16) uint32_t g_kt[(size_t)BB*HH*MKEYS*DD]; // k + bank (tf32)
__device__ __align__(16) __nv_bfloat16 g_v3[(size_t)BB*HH*DD*3*MKEYS]; // v split [bh][d][3m]

// ---------------- PTX helpers ----------------
__device__ __forceinline__ uint32_t smem_u32(const void* p) {
    uint32_t a;
    asm("{ .reg .u64 t; cvta.to.shared.u64 t, %1; cvt.u32.u64 %0, t; }" : "=r"(a) : "l"(p));
    return a;
}
__device__ __forceinline__ void cp_async16(uint32_t dst, const void* src) {
    asm volatile("cp.async.cg.shared.global [%0], [%1], 16;" :: "r"(dst), "l"(src));
}
__device__ __forceinline__ void cp_commit() {
    asm volatile("cp.async.commit_group;");
}
template<int N>
__device__ __forceinline__ void cp_wait() {
    asm volatile("cp.async.wait_group %0;" :: "n"(N));
}
__device__ __forceinline__ void ldsm4(uint32_t* r, uint32_t addr) {
    asm volatile("ldmatrix.sync.aligned.m8n8.x4.shared.b16 {%0,%1,%2,%3}, [%4];"
                 : "=r"(r[0]), "=r"(r[1]), "=r"(r[2]), "=r"(r[3]) : "r"(addr));
}
__device__ __forceinline__ void mma16816(float* d, const uint32_t* a, const uint32_t* b) {
    asm volatile(
        "mma.sync.aligned.m16n8k16.row.col.f32.bf16.bf16.f32 "
        "{%0,%1,%2,%3}, {%4,%5,%6,%7}, {%8,%9}, {%0,%1,%2,%3};"
        : "+f"(d[0]), "+f"(d[1]), "+f"(d[2]), "+f"(d[3])
        : "r"(a[0]), "r"(a[1]), "r"(a[2]), "r"(a[3]), "r"(b[0]), "r"(b[1]));
}
__device__ __forceinline__ void mma1688(float* d, const uint32_t* a, const uint32_t* b) {
    asm volatile(
        "mma.sync.aligned.m16n8k8.row.col.f32.tf32.tf32.f32 "
        "{%0,%1,%2,%3}, {%4,%5,%6,%7}, {%8,%9}, {%0,%1,%2,%3};"
        : "+f"(d[0]), "+f"(d[1]), "+f"(d[2]), "+f"(d[3])
        : "r"(a[0]), "r"(a[1]), "r"(a[2]), "r"(a[3]), "r"(b[0]), "r"(b[1]));
}
__device__ __forceinline__ uint32_t tf32c(float f) {
    uint32_t r; asm("cvt.rna.tf32.f32 %0, %1;" : "=r"(r) : "f"(f)); return r;
}
__device__ __forceinline__ float ex2(float x) {
    float r; asm("ex2.approx.ftz.f32 %0, %1;" : "=f"(r) : "f"(x)); return r;
}

// ---------------------------------------------------------------------------
// tf32 pre-rounding (RNA): 0=x->g_xt  1=qkv_w->g_wqt  3=proj_w->g_wpt
// ---------------------------------------------------------------------------
template<int W>
__global__ __launch_bounds__(256)
void convt(const float4* __restrict__ src, int n4)
{
    int i = blockIdx.x * blockDim.x + threadIdx.x;
    if (i >= n4) return;
    uint4* dst = (W == 0) ? (uint4*)g_xt : (W == 1) ? (uint4*)g_wqt : (uint4*)g_wpt;
    float4 v = src[i];
    uint4 o;
    o.x = tf32c(v.x); o.y = tf32c(v.y); o.z = tf32c(v.z); o.w = tf32c(v.w);
    dst[i] = o;
}

// bank_k rows -> g_kt tail (tf32)
__global__ __launch_bounds__(256)
void convkt_bank(const float* __restrict__ bank_k)
{
    int i = blockIdx.x * blockDim.x + threadIdx.x;     // float4 index
    if (i >= BB*HH*BANKN*DD/4) return;
    int c4 = i & 15;
    int m  = (i >> 4) % BANKN;
    int bh = (i >> 4) / BANKN;
    int h  = bh % HH;
    float4 v = *(const float4*)(bank_k + (size_t)m * CC + h * DD + c4 * 4);
    uint4 o;
    o.x = tf32c(v.x); o.y = tf32c(v.y); o.z = tf32c(v.z); o.w = tf32c(v.w);
    *((uint4*)g_kt + (((size_t)bh * MKEYS + NN + m) * DD + c4 * 4) / 4) = o;
}

// g_v + bank_v -> [bh][d][3m] bf16 split
__global__ __launch_bounds__(256)
void convv3(const float* __restrict__ bank_v)
{
    __shared__ float t[64][65];
    const int tid = threadIdx.x;
    const int m0 = blockIdx.x * 64;
    const int bh = blockIdx.y;
    const int h  = bh % HH;
    #pragma unroll
    for (int i = 0; i < 4; i++) {
        int idx = tid + i * 256;
        int m = idx >> 4, d4 = (idx & 15) * 4;
        int gm = m0 + m;
        const float* src = (gm < NN)
            ? g_v + ((size_t)bh*NN + gm)*DD + d4
            : bank_v + (size_t)(gm - NN)*CC + h*DD + d4;
        float4 v = *(const float4*)src;
        t[m][d4] = v.x; t[m][d4+1] = v.y; t[m][d4+2] = v.z; t[m][d4+3] = v.w;
    }
    __syncthreads();
    const int d = tid >> 2, part = tid & 3;
    __nv_bfloat16 buf[48];
    #pragma unroll
    for (int mm = 0; mm < 16; mm++) {
        float f = t[part*16 + mm][d];
        __nv_bfloat16 hi = __float2bfloat16(f);
        __nv_bfloat16 lo = __float2bfloat16(f - __bfloat162float(hi));
        buf[3*mm] = hi; buf[3*mm+1] = lo; buf[3*mm+2] = hi;
    }
    uint4* dst = (uint4*)(g_v3 + ((size_t)bh*DD + d)*3*MKEYS + 3*(m0 + part*16));
    const uint4* sp = (const uint4*)buf;
    #pragma unroll
    for (int j = 0; j < 6; j++) dst[j] = sp[j];
}

// ---------------------------------------------------------------------------
// tf32 GEMM, 256x128 tile, 512 threads (16 warps, warp tile 32x64),
// 3-stage cp.async pipeline. Stage = A 32KB + B 16KB.
// MODE 0 -> q (tf32 * 0.125*log2e) -> g_qt, k (tf32) -> g_kt, v -> g_v
// MODE 1 -> g_p
// ---------------------------------------------------------------------------
template<int MODE>
__global__ __launch_bounds__(GTHREADS)
void gemm_t(const float* __restrict__ bias)
{
    extern __shared__ __align__(1024) char sm[];
    const uint32_t smb = smem_u32(sm);
    const int tid = threadIdx.x, wid = tid >> 5, lane = tid & 31;
    const int row0 = blockIdx.x * TILE_M, col0 = blockIdx.y * 128;
    const uint32_t* __restrict__ A = (MODE == 0) ? g_xt : g_ot;
    const uint32_t* __restrict__ W = (MODE == 0) ? g_wqt : g_wpt;

    const int wm = wid >> 1;          // 0..7 -> m offset wm*32
    const int wn = wid & 1;           // 0..1 -> n offset wn*64

    uint32_t abase[2]; uint32_t asw[2];
    #pragma unroll
    for (int mt = 0; mt < 2; mt++) {
        int r = wm * 32 + mt * 16 + (lane & 7) + ((lane >> 3) & 1) * 8;
        abase[mt] = (uint32_t)(r * 128);
        asw[mt]   = (uint32_t)(r & 7);
    }
    uint32_t bbase[4]; uint32_t bsw[4];
    #pragma unroll
    for (int p = 0; p < 4; p++) {
        int r = wn * 64 + p * 16 + (lane & 7) + ((lane >> 4) & 1) * 8;
        bbase[p] = (uint32_t)(r * 128);
        bsw[p]   = (uint32_t)(r & 7);
    }
    const uint32_t ka = (lane >> 4) & 1;
    const uint32_t kb = (lane >> 3) & 1;

    // loaders: A rows 0..255 (4x16B per thread), B rows 0..127 (2x16B per thread)
    const int lrA = tid >> 1;              // 0..255
    const int luA = (tid & 1) * 4;         // group base 0 or 4
    uint32_t stA[4];
    #pragma unroll
    for (int it = 0; it < 4; it++) {
        int u = luA + it;
        stA[it] = (uint32_t)(lrA * 128 + (((uint32_t)u ^ (uint32_t)(lrA & 7)) << 4));
    }
    const int lrB = tid >> 2;              // 0..127
    const int luB = (tid & 3) * 2;         // group base 0,2,4,6
    uint32_t stB[2];
    #pragma unroll
    for (int it = 0; it < 2; it++) {
        int u = luB + it;
        stB[it] = (uint32_t)(lrB * 128 + (((uint32_t)u ^ (uint32_t)(lrB & 7)) << 4));
    }

    float acc[2][8][4];
    #pragma unroll
    for (int mt = 0; mt < 2; mt++)
        #pragma unroll
        for (int nt = 0; nt < 8; nt++)
            #pragma unroll
            for (int c = 0; c < 4; c++) acc[mt][nt][c] = 0.0f;

    // -------- prologue: load chunks 0, 1
    #pragma unroll
    for (int pre = 0; pre < 2; pre++) {
        const uint32_t pbuf = smb + pre * STAGE_BYTES;
        const uint32_t* Asrc = A + (size_t)row0 * CC + pre * KC2;
        const uint32_t* Wsrc = W + (size_t)col0 * CC + pre * KC2;
        #pragma unroll
        for (int it = 0; it < 4; it++)
            cp_async16(pbuf + stA[it], Asrc + (size_t)lrA * CC + (luA + it) * 4);
        #pragma unroll
        for (int it = 0; it < 2; it++)
            cp_async16(pbuf + 32768 + stB[it], Wsrc + (size_t)lrB * CC + (luB + it) * 4);
        cp_commit();
    }

    int bufsel = 0;
    for (int ch = 0; ch < NCHUNK2; ch++) {
        const uint32_t buf = smb + bufsel * STAGE_BYTES;
        if (ch + 2 < NCHUNK2) {
            int nb = bufsel + 2; if (nb >= 3) nb -= 3;
            const uint32_t nbuf = smb + nb * STAGE_BYTES;
            const uint32_t* Asrc = A + (size_t)row0 * CC + (ch + 2) * KC2;
            const uint32_t* Wsrc = W + (size_t)col0 * CC + (ch + 2) * KC2;
            #pragma unroll
            for (int it = 0; it < 4; it++)
                cp_async16(nbuf + stA[it], Asrc + (size_t)lrA * CC + (luA + it) * 4);
            #pragma unroll
            for (int it = 0; it < 2; it++)
                cp_async16(nbuf + 32768 + stB[it], Wsrc + (size_t)lrB * CC + (luB + it) * 4);
            cp_commit();
            cp_wait<2>();
        } else if (ch + 1 < NCHUNK2) {
            cp_wait<1>();
        } else {
            cp_wait<0>();
        }
        __syncthreads();

        #pragma unroll
        for (int ks = 0; ks < 4; ks++) {
            uint32_t af[2][4], bf[4][4];
            const uint32_t ga = ka + 2 * ks;
            const uint32_t gb = kb + 2 * ks;
            #pragma unroll
            for (int mt = 0; mt < 2; mt++)
                ldsm4(af[mt], buf + abase[mt] + ((ga ^ asw[mt]) << 4));
            #pragma unroll
            for (int p = 0; p < 4; p++)
                ldsm4(bf[p], buf + 32768 + bbase[p] + ((gb ^ bsw[p]) << 4));
            #pragma unroll
            for (int mt = 0; mt < 2; mt++)
                #pragma unroll
                for (int p = 0; p < 4; p++) {
                    mma1688(acc[mt][2*p],     af[mt], &bf[p][0]);
                    mma1688(acc[mt][2*p + 1], af[mt], &bf[p][2]);
                }
        }
        __syncthreads();
        if (++bufsel == 3) bufsel = 0;
    }

    // -------- epilogue: regs -> stage smem (256 x STRIDE) -> scatter
    float* stage = (float*)sm;
    const int g   = lane >> 2;
    const int tp  = (lane & 3) * 2;
    #pragma unroll
    for (int mt = 0; mt < 2; mt++) {
        int rbase = wm * 32 + mt * 16 + g;
        #pragma unroll
        for (int nt = 0; nt < 8; nt++) {
            int cbase = wn * 64 + nt * 8 + tp;
            stage[rbase * STRIDE + cbase]           = acc[mt][nt][0];
            stage[rbase * STRIDE + cbase + 1]       = acc[mt][nt][1];
            stage[(rbase + 8) * STRIDE + cbase]     = acc[mt][nt][2];
            stage[(rbase + 8) * STRIDE + cbase + 1] = acc[mt][nt][3];
        }
    }
    __syncthreads();

    #pragma unroll
    for (int it = 0; it < 16; it++) {
        int idx = tid + it * GTHREADS;        // 256 rows x 32 float4 = 8192
        int r = idx >> 5, q = idx & 31, c = q * 4;
        float4 v = *(float4*)&stage[r * STRIDE + c];
        int f0 = col0 + c;
        v.x += bias[f0]; v.y += bias[f0 + 1]; v.z += bias[f0 + 2]; v.w += bias[f0 + 3];
        int gr = row0 + r;
        if (MODE == 0) {
            int b = gr >> 10, n = gr & 1023;
            int which = f0 / CC;
            int hd = f0 - which * CC;
            int h = hd >> 6, d = hd & 63;
            int bh = b * HH + h;
            if (which == 0) {
                const float qs = 0.125f * LOG2E;    // fold log2e for exp2 softmax
                uint4 o;
                o.x = tf32c(v.x * qs); o.y = tf32c(v.y * qs);
                o.z = tf32c(v.z * qs); o.w = tf32c(v.w * qs);
                *(uint4*)&g_qt[((size_t)bh * NN + n) * DD + d] = o;
            } else if (which == 1) {
                uint4 o;
                o.x = tf32c(v.x); o.y = tf32c(v.y); o.z = tf32c(v.z); o.w = tf32c(v.w);
                *(uint4*)&g_kt[((size_t)bh * MKEYS + n) * DD + d] = o;
            } else {
                *(float4*)&g_v[((size_t)bh * NN + n) * DD + d] = v;
            }
        } else {
            *(float4*)&g_p[(size_t)gr * CC + f0] = v;
        }
    }
}

// ---------------------------------------------------------------------------
// Tensor-core flash attention: tf32 QK^T (exp2 domain) + 3x-bf16-split PV.
// Q fragments hoisted to registers; P split via PRMT truncation (no cvt).
// ---------------------------------------------------------------------------
__global__ __launch_bounds__(256)
void attn2(float* __restrict__ out)
{
    extern __shared__ __align__(16) char sm[];
    const uint32_t smb = smem_u32(sm);
    const int tid = threadIdx.x, w = tid >> 5, lane = tid & 31;
    const int g = lane >> 2, c = lane & 3;
    const int bh = blockIdx.y, q0 = blockIdx.x * AQ;
    const int b = bh / HH, h = bh - b * HH;

    // ldmatrix V fragment base addresses (pitch 400B, conflict-free)
    uint32_t vab[4];
    #pragma unroll
    for (int p = 0; p < 4; p++) {
        int vr = p * 16 + (lane & 7) + ((lane >> 4) & 1) * 8;
        vab[p] = smb + SM_V + (uint32_t)vr * 400 + ((lane >> 3) & 1) * 16;
    }

    {
        const uint32_t* src = g_qt + ((size_t)bh * NN + q0) * DD;
        #pragma unroll
        for (int i = 0; i < 8; i++) {
            int idx = tid + i * 256;
            int r = idx >> 4, c16 = idx & 15;
            cp_async16(smb + SM_Q + r * 272 + c16 * 16, src + (size_t)r * DD + c16 * 4);
        }
        const uint32_t* ks = g_kt + (size_t)bh * MKEYS * DD;
        #pragma unroll
        for (int i = 0; i < 4; i++) {
            int idx = tid + i * 256;
            int r = idx >> 4, c16 = idx & 15;
            cp_async16(smb + SM_K + r * 272 + c16 * 16, ks + (size_t)r * DD + c16 * 4);
        }
        const __nv_bfloat16* vs = g_v3 + (size_t)bh * DD * 3 * MKEYS;
        #pragma unroll
        for (int i = 0; i < 6; i++) {
            int idx = tid + i * 256;
            int r = idx / 24, j = idx - r * 24;
            cp_async16(smb + SM_V + r * 400 + j * 16, vs + (size_t)r * 3 * MKEYS + j * 8);
        }
        cp_commit();
    }

    float mprev0 = -INFINITY, mprev1 = -INFINITY, l0 = 0.0f, l1 = 0.0f;
    float o[8][4];
    #pragma unroll
    for (int t = 0; t < 8; t++)
        #pragma unroll
        for (int j = 0; j < 4; j++) o[t][j] = 0.0f;

    uint32_t qfrag[8][4];   // hoisted Q fragments (loop-invariant)

    for (int ch = 0; ch < ANCH; ch++) {
        const int buf = ch & 1;
        if (ch + 1 < ANCH) {
            const int nb = buf ^ 1;
            const uint32_t* ks = g_kt + ((size_t)bh * MKEYS + (ch + 1) * ACH) * DD;
            #pragma unroll
            for (int i = 0; i < 4; i++) {
                int idx = tid + i * 256;
                int r = idx >> 4, c16 = idx & 15;
                cp_async16(smb + SM_K + nb * 17408 + r * 272 + c16 * 16,
                           ks + (size_t)r * DD + c16 * 4);
            }
            const __nv_bfloat16* vs = g_v3 + (size_t)bh * DD * 3 * MKEYS + (ch + 1) * 192;
            #pragma unroll
            for (int i = 0; i < 6; i++) {
                int idx = tid + i * 256;
                int r = idx / 24, j = idx - r * 24;
                cp_async16(smb + SM_V + nb * 25600 + r * 400 + j * 16,
                           vs + (size_t)r * 3 * MKEYS + j * 8);
            }
            cp_commit();
            cp_wait<1>();
        } else {
            cp_wait<0>();
        }
        __syncthreads();

        if (ch == 0) {
            const uint32_t* Qs = (const uint32_t*)(sm + SM_Q);
            #pragma unroll
            for (int ks = 0; ks < 8; ks++) {
                const uint32_t* qb = Qs + (16 * w + g) * 68 + ks * 8 + c;
                qfrag[ks][0] = qb[0]; qfrag[ks][1] = qb[8 * 68];
                qfrag[ks][2] = qb[4]; qfrag[ks][3] = qb[8 * 68 + 4];
            }
        }

        // ---- S = Q K^T (tf32, log2 domain)
        const uint32_t* Ks = (const uint32_t*)(sm + SM_K + buf * 17408);
        float sacc[8][4];
        #pragma unroll
        for (int t = 0; t < 8; t++)
            #pragma unroll
            for (int j = 0; j < 4; j++) sacc[t][j] = 0.0f;

        #pragma unroll
        for (int ks = 0; ks < 8; ks++) {
            #pragma unroll
            for (int t = 0; t < 8; t++) {
                uint32_t bf[2];
                const uint32_t* kb2 = Ks + (t * 8 + g) * 68 + ks * 8 + c;
                bf[0] = kb2[0]; bf[1] = kb2[4];
                mma1688(sacc[t], qfrag[ks], bf);
            }
        }

        // ---- online softmax (exp2)
        float mx0 = -INFINITY, mx1 = -INFINITY;
        #pragma unroll
        for (int t = 0; t < 8; t++) {
            mx0 = fmaxf(mx0, fmaxf(sacc[t][0], sacc[t][1]));
            mx1 = fmaxf(mx1, fmaxf(sacc[t][2], sacc[t][3]));
        }
        mx0 = fmaxf(mx0, __shfl_xor_sync(0xffffffffu, mx0, 1));
        mx0 = fmaxf(mx0, __shfl_xor_sync(0xffffffffu, mx0, 2));
        mx1 = fmaxf(mx1, __shfl_xor_sync(0xffffffffu, mx1, 1));
        mx1 = fmaxf(mx1, __shfl_xor_sync(0xffffffffu, mx1, 2));
        const float mnew0 = fmaxf(mprev0, mx0);
        const float mnew1 = fmaxf(mprev1, mx1);
        const float alpha0 = ex2(mprev0 - mnew0);
        const float alpha1 = ex2(mprev1 - mnew1);

        uint32_t* P0 = (uint32_t*)(sm + SM_P) + (16 * w + g) * 100;
        uint32_t* P1 = P0 + 8 * 100;
        float ps0 = 0.0f, ps1 = 0.0f;
        #pragma unroll
        for (int t = 0; t < 8; t++) {
            float p00 = ex2(sacc[t][0] - mnew0);
            float p01 = ex2(sacc[t][1] - mnew0);
            float p10 = ex2(sacc[t][2] - mnew1);
            float p11 = ex2(sacc[t][3] - mnew1);
            ps0 += p00 + p01; ps1 += p10 + p11;
            uint32_t r00 = __float_as_uint(p00), r01 = __float_as_uint(p01);
            uint32_t r10 = __float_as_uint(p10), r11 = __float_as_uint(p11);
            float lo00 = p00 - __uint_as_float(r00 & 0xFFFF0000u);
            float lo01 = p01 - __uint_as_float(r01 & 0xFFFF0000u);
            float lo10 = p10 - __uint_as_float(r10 & 0xFFFF0000u);
            float lo11 = p11 - __uint_as_float(r11 & 0xFFFF0000u);
            uint32_t rl00 = __float_as_uint(lo00), rl01 = __float_as_uint(lo01);
            uint32_t rl10 = __float_as_uint(lo10), rl11 = __float_as_uint(lo11);
            int base = 12 * t + 3 * c;
            P0[base]     = __byte_perm(r00,  r00,  0x7632);
            P0[base + 1] = __byte_perm(rl00, r01,  0x7632);
            P0[base + 2] = __byte_perm(r01,  rl01, 0x7632);
            P1[base]     = __byte_perm(r10,  r10,  0x7632);
            P1[base + 1] = __byte_perm(rl10, r11,  0x7632);
            P1[base + 2] = __byte_perm(r11,  rl11, 0x7632);
        }
        ps0 += __shfl_xor_sync(0xffffffffu, ps0, 1);
        ps0 += __shfl_xor_sync(0xffffffffu, ps0, 2);
        ps1 += __shfl_xor_sync(0xffffffffu, ps1, 1);
        ps1 += __shfl_xor_sync(0xffffffffu, ps1, 2);
        l0 = l0 * alpha0 + ps0; l1 = l1 * alpha1 + ps1;
        mprev0 = mnew0; mprev1 = mnew1;
        #pragma unroll
        for (int t = 0; t < 8; t++) {
            o[t][0] *= alpha0; o[t][1] *= alpha0;
            o[t][2] *= alpha1; o[t][3] *= alpha1;
        }
        __syncwarp();

        // ---- O += P3 V3 (bf16 split) -- V fragments via ldmatrix.x4
        const uint32_t* Pw = (const uint32_t*)(sm + SM_P) + 16 * w * 100;
        const uint32_t vbuf_off = buf * 25600;
        #pragma unroll
        for (int k2 = 0; k2 < 12; k2++) {
            uint32_t a[4];
            const uint32_t* pb = Pw + g * 100 + k2 * 8 + c;
            a[0] = pb[0]; a[1] = pb[8 * 100]; a[2] = pb[4]; a[3] = pb[8 * 100 + 4];
            uint32_t bf[4][4];
            #pragma unroll
            for (int p = 0; p < 4; p++)
                ldsm4(bf[p], vab[p] + vbuf_off + k2 * 32);
            #pragma unroll
            for (int p = 0; p < 4; p++) {
                mma16816(o[2*p],     a, &bf[p][0]);
                mma16816(o[2*p + 1], a, &bf[p][2]);
            }
        }
        __syncthreads();
    }

    // ---- normalize + write out (fp32) and g_ot (tf32)
    const float inv0 = 1.0f / l0, inv1 = 1.0f / l1;
    const int n0 = q0 + 16 * w + g, n1 = n0 + 8;
    #pragma unroll
    for (int t = 0; t < 8; t++) {
        int col = h * DD + 8 * t + 2 * c;
        float v00 = o[t][0] * inv0, v01 = o[t][1] * inv0;
        float v10 = o[t][2] * inv1, v11 = o[t][3] * inv1;
        *(float2*)&out[((size_t)b * NN + n0) * CC + col] = make_float2(v00, v01);
        *(float2*)&out[((size_t)b * NN + n1) * CC + col] = make_float2(v10, v11);
        uint2 t0; t0.x = tf32c(v00); t0.y = tf32c(v01);
        uint2 t1; t1.x = tf32c(v10); t1.y = tf32c(v11);
        *(uint2*)&g_ot[((size_t)b * NN + n0) * CC + col] = t0;
        *(uint2*)&g_ot[((size_t)b * NN + n1) * CC + col] = t1;
    }
}

// ---------------------------------------------------------------------------
__global__ __launch_bounds__(256)
void ln_kernel(const float* __restrict__ nw, const float* __restrict__ nb,
               float* __restrict__ outb)
{
    __shared__ float shs[8], shs2[8];
    const int row = blockIdx.x;
    const int tid = threadIdx.x;
    const float* pr = g_p + (size_t)row * CC;

    float v[3];
    float s = 0.0f, s2 = 0.0f;
    #pragma unroll
    for (int i = 0; i < 3; i++) {
        v[i] = pr[tid + i * 256];
        s  += v[i];
        s2 += v[i] * v[i];
    }
    #pragma unroll
    for (int off = 16; off >= 1; off >>= 1) {
        s  += __shfl_xor_sync(0xffffffffu, s,  off);
        s2 += __shfl_xor_sync(0xffffffffu, s2, off);
    }
    if ((tid & 31) == 0) { shs[tid >> 5] = s; shs2[tid >> 5] = s2; }
    __syncthreads();
    float ts = 0.0f, ts2 = 0.0f;
    #pragma unroll
    for (int w = 0; w < 8; w++) { ts += shs[w]; ts2 += shs2[w]; }

    const float mu  = ts * (1.0f / CC);
    const float var = ts2 * (1.0f / CC) - mu * mu;
    const float r   = rsqrtf(var + 1e-5f);

    #pragma unroll
    for (int i = 0; i < 3; i++) {
        int c = tid + i * 256;
        outb[(size_t)row * CC + c] = (v[i] - mu) * r * nw[c] + nb[c];
    }
}

// ---------------------------------------------------------------------------
extern "C" void kernel_launch(void* const* d_in, const int* in_sizes, int n_in,
                              void* d_out, int out_size)
{
    const float* x      = (const float*)d_in[0];
    const float* qkv_w  = (const float*)d_in[1];
    const float* qkv_b  = (const float*)d_in[2];
    const float* proj_w = (const float*)d_in[3];
    const float* proj_b = (const float*)d_in[4];
    const float* norm_w = (const float*)d_in[5];
    const float* norm_b = (const float*)d_in[6];
    const float* bank_k = (const float*)d_in[7];
    const float* bank_v = (const float*)d_in[8];

    float* out      = (float*)d_out;
    float* bank_upd = out + (size_t)BB * NN * CC;

    cudaFuncSetAttribute(attn2, cudaFuncAttributeMaxDynamicSharedMemorySize, ASMEM);
    cudaFuncSetAttribute(gemm_t<0>, cudaFuncAttributeMaxDynamicSharedMemorySize, GSMEM);
    cudaFuncSetAttribute(gemm_t<1>, cudaFuncAttributeMaxDynamicSharedMemorySize, GSMEM);

    const int nx4  = BB * NN * CC / 4;
    const int nwq4 = 3 * CC * CC / 4;
    const int nwp4 = CC * CC / 4;
    const int nbk4 = BB * HH * BANKN * DD / 4;

    // independent conversions first (overlap with ramp / fill idle SMs)
    convkt_bank<<<(nbk4 + 255) / 256, 256>>>(bank_k);
    convt<0><<<(nx4 + 255) / 256, 256>>>((const float4*)x, nx4);
    convt<1><<<(nwq4 + 255) / 256, 256>>>((const float4*)qkv_w, nwq4);
    convt<3><<<(nwp4 + 255) / 256, 256>>>((const float4*)proj_w, nwp4);
    // QKV GEMM (tf32, 256x128 tiles)
    gemm_t<0><<<dim3(BB*NN/TILE_M, 18), GTHREADS, GSMEM>>>(qkv_b);
    // V split
    convv3<<<dim3(ANCH, BB*HH), 256>>>(bank_v);
    // flash attention -> out (fp32) + g_ot (tf32)
    attn2<<<dim3(NN / AQ, BB * HH), 256, ASMEM>>>(out);
    // proj GEMM -> g_p
    gemm_t<1><<<dim3(BB*NN/TILE_M, 6), GTHREADS, GSMEM>>>(proj_b);
    // LayerNorm -> bank_update
    ln_kernel<<<BB * NN, 256>>>(norm_w, norm_b, bank_upd);
}

// round 16
// speedup vs baseline: 3.6354x; 1.1677x over previous
#include <cuda_runtime.h>
#include <cuda_bf16.h>
#include <cstdint>
#include <math.h>

#define BB 16
#define NN 1024
#define CC 768
#define HH 12
#define DD 64
#define BANKN 256
#define MKEYS (NN + BANKN)   // 1280
#define KC2 32               // fp32 K elems per chunk (128 B rows)
#define NCHUNK2 (CC/KC2)     // 24
#define STRIDE 132
#define TILE_M 256
#define GTHREADS 512
#define STAGE_BYTES 49152    // A 32KB + B 16KB
#define GSMEM (3*STAGE_BYTES)

#define LOG2E 1.44269504088896f

// attention tiling
#define AQ 128
#define ACH 64
#define ANCH (MKEYS/ACH)     // 20
#define SM_Q 0               // [128][68] f32 (tf32 bits)
#define SM_K 34816           // 2 x [64][68] f32
#define SM_V 69632           // 2 x (V_hi 8KB + V_lo 8KB), XOR-swizzled 128B rows
#define VSTAGE 16384
#define ASMEM 102400         // fits 2 CTAs/SM

// ---------------- scratch ----------------
__device__ __align__(16) float    g_v[BB*HH*NN*DD];             // v (fp32, [bh][n][d])
__device__ __align__(16) float    g_p[BB*NN*CC];                // proj out, pre-LN
__device__ __align__(16) uint32_t g_xt[(size_t)BB*NN*CC];       // x  (tf32)
__device__ __align__(16) uint32_t g_ot[(size_t)BB*NN*CC];       // attn out (tf32)
__device__ __align__(16) uint32_t g_wqt[(size_t)3*CC*CC];       // qkv_w (tf32)
__device__ __align__(16) uint32_t g_wpt[(size_t)CC*CC];         // proj_w (tf32)
__device__ __align__(16) uint32_t g_qt[(size_t)BB*HH*NN*DD];    // q (tf32, scaled log2e/8)
__device__ __align__(16) uint32_t g_kt[(size_t)BB*HH*MKEYS*DD]; // k + bank (tf32)
__device__ __align__(16) __nv_bfloat16 g_vh[(size_t)BB*HH*DD*MKEYS]; // v hi plane [bh][d][m]
__device__ __align__(16) __nv_bfloat16 g_vl[(size_t)BB*HH*DD*MKEYS]; // v lo plane [bh][d][m]

// ---------------- PTX helpers ----------------
__device__ __forceinline__ uint32_t smem_u32(const void* p) {
    uint32_t a;
    asm("{ .reg .u64 t; cvta.to.shared.u64 t, %1; cvt.u32.u64 %0, t; }" : "=r"(a) : "l"(p));
    return a;
}
__device__ __forceinline__ void cp_async16(uint32_t dst, const void* src) {
    asm volatile("cp.async.cg.shared.global [%0], [%1], 16;" :: "r"(dst), "l"(src));
}
__device__ __forceinline__ void cp_commit() {
    asm volatile("cp.async.commit_group;");
}
template<int N>
__device__ __forceinline__ void cp_wait() {
    asm volatile("cp.async.wait_group %0;" :: "n"(N));
}
__device__ __forceinline__ void ldsm4(uint32_t* r, uint32_t addr) {
    asm volatile("ldmatrix.sync.aligned.m8n8.x4.shared.b16 {%0,%1,%2,%3}, [%4];"
                 : "=r"(r[0]), "=r"(r[1]), "=r"(r[2]), "=r"(r[3]) : "r"(addr));
}
__device__ __forceinline__ void mma16816(float* d, const uint32_t* a, const uint32_t* b) {
    asm volatile(
        "mma.sync.aligned.m16n8k16.row.col.f32.bf16.bf16.f32 "
        "{%0,%1,%2,%3}, {%4,%5,%6,%7}, {%8,%9}, {%0,%1,%2,%3};"
        : "+f"(d[0]), "+f"(d[1]), "+f"(d[2]), "+f"(d[3])
        : "r"(a[0]), "r"(a[1]), "r"(a[2]), "r"(a[3]), "r"(b[0]), "r"(b[1]));
}
__device__ __forceinline__ void mma1688(float* d, const uint32_t* a, const uint32_t* b) {
    asm volatile(
        "mma.sync.aligned.m16n8k8.row.col.f32.tf32.tf32.f32 "
        "{%0,%1,%2,%3}, {%4,%5,%6,%7}, {%8,%9}, {%0,%1,%2,%3};"
        : "+f"(d[0]), "+f"(d[1]), "+f"(d[2]), "+f"(d[3])
        : "r"(a[0]), "r"(a[1]), "r"(a[2]), "r"(a[3]), "r"(b[0]), "r"(b[1]));
}
__device__ __forceinline__ uint32_t tf32c(float f) {
    uint32_t r; asm("cvt.rna.tf32.f32 %0, %1;" : "=r"(r) : "f"(f)); return r;
}
__device__ __forceinline__ float ex2(float x) {
    float r; asm("ex2.approx.ftz.f32 %0, %1;" : "=f"(r) : "f"(x)); return r;
}

// ---------------------------------------------------------------------------
// tf32 pre-rounding (RNA): 0=x->g_xt  1=qkv_w->g_wqt  3=proj_w->g_wpt
// ---------------------------------------------------------------------------
template<int W>
__global__ __launch_bounds__(256)
void convt(const float4* __restrict__ src, int n4)
{
    int i = blockIdx.x * blockDim.x + threadIdx.x;
    if (i >= n4) return;
    uint4* dst = (W == 0) ? (uint4*)g_xt : (W == 1) ? (uint4*)g_wqt : (uint4*)g_wpt;
    float4 v = src[i];
    uint4 o;
    o.x = tf32c(v.x); o.y = tf32c(v.y); o.z = tf32c(v.z); o.w = tf32c(v.w);
    dst[i] = o;
}

// bank_k rows -> g_kt tail (tf32)
__global__ __launch_bounds__(256)
void convkt_bank(const float* __restrict__ bank_k)
{
    int i = blockIdx.x * blockDim.x + threadIdx.x;     // float4 index
    if (i >= BB*HH*BANKN*DD/4) return;
    int c4 = i & 15;
    int m  = (i >> 4) % BANKN;
    int bh = (i >> 4) / BANKN;
    int h  = bh % HH;
    float4 v = *(const float4*)(bank_k + (size_t)m * CC + h * DD + c4 * 4);
    uint4 o;
    o.x = tf32c(v.x); o.y = tf32c(v.y); o.z = tf32c(v.z); o.w = tf32c(v.w);
    *((uint4*)g_kt + (((size_t)bh * MKEYS + NN + m) * DD + c4 * 4) / 4) = o;
}

// g_v + bank_v -> V_hi / V_lo planes [bh][d][m] (bf16)
__global__ __launch_bounds__(256)
void convv3(const float* __restrict__ bank_v)
{
    __shared__ float t[64][65];
    const int tid = threadIdx.x;
    const int m0 = blockIdx.x * 64;
    const int bh = blockIdx.y;
    const int h  = bh % HH;
    #pragma unroll
    for (int i = 0; i < 4; i++) {
        int idx = tid + i * 256;
        int m = idx >> 4, d4 = (idx & 15) * 4;
        int gm = m0 + m;
        const float* src = (gm < NN)
            ? g_v + ((size_t)bh*NN + gm)*DD + d4
            : bank_v + (size_t)(gm - NN)*CC + h*DD + d4;
        float4 v = *(const float4*)src;
        t[m][d4] = v.x; t[m][d4+1] = v.y; t[m][d4+2] = v.z; t[m][d4+3] = v.w;
    }
    __syncthreads();
    const int d = tid >> 2, part = tid & 3;
    __nv_bfloat16 bhi[16], blo[16];
    #pragma unroll
    for (int mm = 0; mm < 16; mm++) {
        float f = t[part*16 + mm][d];
        __nv_bfloat16 hi = __float2bfloat16(f);
        __nv_bfloat16 lo = __float2bfloat16(f - __bfloat162float(hi));
        bhi[mm] = hi; blo[mm] = lo;
    }
    size_t base = ((size_t)bh*DD + d)*MKEYS + m0 + part*16;
    uint4* dh = (uint4*)(g_vh + base);
    uint4* dl = (uint4*)(g_vl + base);
    const uint4* sh = (const uint4*)bhi;
    const uint4* sl = (const uint4*)blo;
    dh[0] = sh[0]; dh[1] = sh[1];
    dl[0] = sl[0]; dl[1] = sl[1];
}

// ---------------------------------------------------------------------------
// tf32 GEMM, 256x128 tile, 512 threads, 3-stage cp.async pipeline (as R14)
// ---------------------------------------------------------------------------
template<int MODE>
__global__ __launch_bounds__(GTHREADS)
void gemm_t(const float* __restrict__ bias)
{
    extern __shared__ __align__(1024) char sm[];
    const uint32_t smb = smem_u32(sm);
    const int tid = threadIdx.x, wid = tid >> 5, lane = tid & 31;
    const int row0 = blockIdx.x * TILE_M, col0 = blockIdx.y * 128;
    const uint32_t* __restrict__ A = (MODE == 0) ? g_xt : g_ot;
    const uint32_t* __restrict__ W = (MODE == 0) ? g_wqt : g_wpt;

    const int wm = wid >> 1;
    const int wn = wid & 1;

    uint32_t abase[2]; uint32_t asw[2];
    #pragma unroll
    for (int mt = 0; mt < 2; mt++) {
        int r = wm * 32 + mt * 16 + (lane & 7) + ((lane >> 3) & 1) * 8;
        abase[mt] = (uint32_t)(r * 128);
        asw[mt]   = (uint32_t)(r & 7);
    }
    uint32_t bbase[4]; uint32_t bsw[4];
    #pragma unroll
    for (int p = 0; p < 4; p++) {
        int r = wn * 64 + p * 16 + (lane & 7) + ((lane >> 4) & 1) * 8;
        bbase[p] = (uint32_t)(r * 128);
        bsw[p]   = (uint32_t)(r & 7);
    }
    const uint32_t ka = (lane >> 4) & 1;
    const uint32_t kb = (lane >> 3) & 1;

    const int lrA = tid >> 1;
    const int luA = (tid & 1) * 4;
    uint32_t stA[4];
    #pragma unroll
    for (int it = 0; it < 4; it++) {
        int u = luA + it;
        stA[it] = (uint32_t)(lrA * 128 + (((uint32_t)u ^ (uint32_t)(lrA & 7)) << 4));
    }
    const int lrB = tid >> 2;
    const int luB = (tid & 3) * 2;
    uint32_t stB[2];
    #pragma unroll
    for (int it = 0; it < 2; it++) {
        int u = luB + it;
        stB[it] = (uint32_t)(lrB * 128 + (((uint32_t)u ^ (uint32_t)(lrB & 7)) << 4));
    }

    float acc[2][8][4];
    #pragma unroll
    for (int mt = 0; mt < 2; mt++)
        #pragma unroll
        for (int nt = 0; nt < 8; nt++)
            #pragma unroll
            for (int c = 0; c < 4; c++) acc[mt][nt][c] = 0.0f;

    #pragma unroll
    for (int pre = 0; pre < 2; pre++) {
        const uint32_t pbuf = smb + pre * STAGE_BYTES;
        const uint32_t* Asrc = A + (size_t)row0 * CC + pre * KC2;
        const uint32_t* Wsrc = W + (size_t)col0 * CC + pre * KC2;
        #pragma unroll
        for (int it = 0; it < 4; it++)
            cp_async16(pbuf + stA[it], Asrc + (size_t)lrA * CC + (luA + it) * 4);
        #pragma unroll
        for (int it = 0; it < 2; it++)
            cp_async16(pbuf + 32768 + stB[it], Wsrc + (size_t)lrB * CC + (luB + it) * 4);
        cp_commit();
    }

    int bufsel = 0;
    for (int ch = 0; ch < NCHUNK2; ch++) {
        const uint32_t buf = smb + bufsel * STAGE_BYTES;
        if (ch + 2 < NCHUNK2) {
            int nb = bufsel + 2; if (nb >= 3) nb -= 3;
            const uint32_t nbuf = smb + nb * STAGE_BYTES;
            const uint32_t* Asrc = A + (size_t)row0 * CC + (ch + 2) * KC2;
            const uint32_t* Wsrc = W + (size_t)col0 * CC + (ch + 2) * KC2;
            #pragma unroll
            for (int it = 0; it < 4; it++)
                cp_async16(nbuf + stA[it], Asrc + (size_t)lrA * CC + (luA + it) * 4);
            #pragma unroll
            for (int it = 0; it < 2; it++)
                cp_async16(nbuf + 32768 + stB[it], Wsrc + (size_t)lrB * CC + (luB + it) * 4);
            cp_commit();
            cp_wait<2>();
        } else if (ch + 1 < NCHUNK2) {
            cp_wait<1>();
        } else {
            cp_wait<0>();
        }
        __syncthreads();

        #pragma unroll
        for (int ks = 0; ks < 4; ks++) {
            uint32_t af[2][4], bf[4][4];
            const uint32_t ga = ka + 2 * ks;
            const uint32_t gb = kb + 2 * ks;
            #pragma unroll
            for (int mt = 0; mt < 2; mt++)
                ldsm4(af[mt], buf + abase[mt] + ((ga ^ asw[mt]) << 4));
            #pragma unroll
            for (int p = 0; p < 4; p++)
                ldsm4(bf[p], buf + 32768 + bbase[p] + ((gb ^ bsw[p]) << 4));
            #pragma unroll
            for (int mt = 0; mt < 2; mt++)
                #pragma unroll
                for (int p = 0; p < 4; p++) {
                    mma1688(acc[mt][2*p],     af[mt], &bf[p][0]);
                    mma1688(acc[mt][2*p + 1], af[mt], &bf[p][2]);
                }
        }
        __syncthreads();
        if (++bufsel == 3) bufsel = 0;
    }

    float* stage = (float*)sm;
    const int g   = lane >> 2;
    const int tp  = (lane & 3) * 2;
    #pragma unroll
    for (int mt = 0; mt < 2; mt++) {
        int rbase = wm * 32 + mt * 16 + g;
        #pragma unroll
        for (int nt = 0; nt < 8; nt++) {
            int cbase = wn * 64 + nt * 8 + tp;
            stage[rbase * STRIDE + cbase]           = acc[mt][nt][0];
            stage[rbase * STRIDE + cbase + 1]       = acc[mt][nt][1];
            stage[(rbase + 8) * STRIDE + cbase]     = acc[mt][nt][2];
            stage[(rbase + 8) * STRIDE + cbase + 1] = acc[mt][nt][3];
        }
    }
    __syncthreads();

    #pragma unroll
    for (int it = 0; it < 16; it++) {
        int idx = tid + it * GTHREADS;
        int r = idx >> 5, q = idx & 31, c = q * 4;
        float4 v = *(float4*)&stage[r * STRIDE + c];
        int f0 = col0 + c;
        v.x += bias[f0]; v.y += bias[f0 + 1]; v.z += bias[f0 + 2]; v.w += bias[f0 + 3];
        int gr = row0 + r;
        if (MODE == 0) {
            int b = gr >> 10, n = gr & 1023;
            int which = f0 / CC;
            int hd = f0 - which * CC;
            int h = hd >> 6, d = hd & 63;
            int bh = b * HH + h;
            if (which == 0) {
                const float qs = 0.125f * LOG2E;
                uint4 o;
                o.x = tf32c(v.x * qs); o.y = tf32c(v.y * qs);
                o.z = tf32c(v.z * qs); o.w = tf32c(v.w * qs);
                *(uint4*)&g_qt[((size_t)bh * NN + n) * DD + d] = o;
            } else if (which == 1) {
                uint4 o;
                o.x = tf32c(v.x); o.y = tf32c(v.y); o.z = tf32c(v.z); o.w = tf32c(v.w);
                *(uint4*)&g_kt[((size_t)bh * MKEYS + n) * DD + d] = o;
            } else {
                *(float4*)&g_v[((size_t)bh * NN + n) * DD + d] = v;
            }
        } else {
            *(float4*)&g_p[(size_t)gr * CC + f0] = v;
        }
    }
}

// ---------------------------------------------------------------------------
// Flash attention: tf32 QK^T (exp2) + 3x-bf16-split PV with REGISTER-resident
// P (S-accumulator == A-fragment identity). V as hi/lo planes, ldsm B-path.
// 102.4 KB smem -> 2 CTAs/SM.
// ---------------------------------------------------------------------------
__global__ __launch_bounds__(256, 2)
void attn2(float* __restrict__ out)
{
    extern __shared__ __align__(16) char sm[];
    const uint32_t smb = smem_u32(sm);
    const int tid = threadIdx.x, w = tid >> 5, lane = tid & 31;
    const int g = lane >> 2, c = lane & 3;
    const int bh = blockIdx.y, q0 = blockIdx.x * AQ;
    const int b = bh / HH, h = bh - b * HH;

    // ldsm V fragment addressing (gemm-style XOR swizzle, 128B rows)
    uint32_t vbase[4], vsw[4];
    #pragma unroll
    for (int p = 0; p < 4; p++) {
        int vr = p * 16 + (lane & 7) + ((lane >> 4) & 1) * 8;
        vbase[p] = (uint32_t)(vr * 128);
        vsw[p]   = (uint32_t)(vr & 7);
    }
    const uint32_t kbv = (lane >> 3) & 1;

    const __nv_bfloat16* vhsrc = g_vh + (size_t)bh * DD * MKEYS;
    const __nv_bfloat16* vlsrc = g_vl + (size_t)bh * DD * MKEYS;

    // ---- prologue loads
    {
        const uint32_t* src = g_qt + ((size_t)bh * NN + q0) * DD;
        #pragma unroll
        for (int i = 0; i < 8; i++) {
            int idx = tid + i * 256;
            int r = idx >> 4, c16 = idx & 15;
            cp_async16(smb + SM_Q + r * 272 + c16 * 16, src + (size_t)r * DD + c16 * 4);
        }
        const uint32_t* ks = g_kt + (size_t)bh * MKEYS * DD;
        #pragma unroll
        for (int i = 0; i < 4; i++) {
            int idx = tid + i * 256;
            int r = idx >> 4, c16 = idx & 15;
            cp_async16(smb + SM_K + r * 272 + c16 * 16, ks + (size_t)r * DD + c16 * 4);
        }
        #pragma unroll
        for (int i = 0; i < 4; i++) {
            int idx = tid + i * 256;          // 0..1023
            int half = idx >> 9, rem = idx & 511;
            int r = rem >> 3, u = rem & 7;
            const __nv_bfloat16* src2 = (half ? vlsrc : vhsrc) + (size_t)r * MKEYS + u * 8;
            cp_async16(smb + SM_V + half * 8192 + r * 128 + (((uint32_t)u ^ (uint32_t)(r & 7)) << 4),
                       src2);
        }
        cp_commit();
    }

    float mprev0 = -INFINITY, mprev1 = -INFINITY, l0 = 0.0f, l1 = 0.0f;
    float o[8][4];
    #pragma unroll
    for (int t = 0; t < 8; t++)
        #pragma unroll
        for (int j = 0; j < 4; j++) o[t][j] = 0.0f;

    for (int ch = 0; ch < ANCH; ch++) {
        const int buf = ch & 1;
        if (ch + 1 < ANCH) {
            const int nb = buf ^ 1;
            const uint32_t* ks = g_kt + ((size_t)bh * MKEYS + (ch + 1) * ACH) * DD;
            #pragma unroll
            for (int i = 0; i < 4; i++) {
                int idx = tid + i * 256;
                int r = idx >> 4, c16 = idx & 15;
                cp_async16(smb + SM_K + nb * 17408 + r * 272 + c16 * 16,
                           ks + (size_t)r * DD + c16 * 4);
            }
            const int m0 = (ch + 1) * ACH;
            #pragma unroll
            for (int i = 0; i < 4; i++) {
                int idx = tid + i * 256;
                int half = idx >> 9, rem = idx & 511;
                int r = rem >> 3, u = rem & 7;
                const __nv_bfloat16* src2 = (half ? vlsrc : vhsrc) + (size_t)r * MKEYS + m0 + u * 8;
                cp_async16(smb + SM_V + nb * VSTAGE + half * 8192 + r * 128 +
                               (((uint32_t)u ^ (uint32_t)(r & 7)) << 4),
                           src2);
            }
            cp_commit();
            cp_wait<1>();
        } else {
            cp_wait<0>();
        }
        __syncthreads();

        // ---- S = Q K^T (tf32, log2 domain)
        const uint32_t* Qs = (const uint32_t*)(sm + SM_Q);
        const uint32_t* Ks = (const uint32_t*)(sm + SM_K + buf * 17408);
        float sacc[8][4];
        #pragma unroll
        for (int t = 0; t < 8; t++)
            #pragma unroll
            for (int j = 0; j < 4; j++) sacc[t][j] = 0.0f;

        #pragma unroll
        for (int ks = 0; ks < 8; ks++) {
            uint32_t a[4];
            const uint32_t* qb = Qs + (16 * w + g) * 68 + ks * 8 + c;
            a[0] = qb[0]; a[1] = qb[8 * 68]; a[2] = qb[4]; a[3] = qb[8 * 68 + 4];
            #pragma unroll
            for (int t = 0; t < 8; t++) {
                uint32_t bf[2];
                const uint32_t* kb2 = Ks + (t * 8 + g) * 68 + ks * 8 + c;
                bf[0] = kb2[0]; bf[1] = kb2[4];
                mma1688(sacc[t], a, bf);
            }
        }

        // ---- online softmax (exp2); p values back into sacc
        float mx0 = -INFINITY, mx1 = -INFINITY;
        #pragma unroll
        for (int t = 0; t < 8; t++) {
            mx0 = fmaxf(mx0, fmaxf(sacc[t][0], sacc[t][1]));
            mx1 = fmaxf(mx1, fmaxf(sacc[t][2], sacc[t][3]));
        }
        mx0 = fmaxf(mx0, __shfl_xor_sync(0xffffffffu, mx0, 1));
        mx0 = fmaxf(mx0, __shfl_xor_sync(0xffffffffu, mx0, 2));
        mx1 = fmaxf(mx1, __shfl_xor_sync(0xffffffffu, mx1, 1));
        mx1 = fmaxf(mx1, __shfl_xor_sync(0xffffffffu, mx1, 2));
        const float mnew0 = fmaxf(mprev0, mx0);
        const float mnew1 = fmaxf(mprev1, mx1);
        const float alpha0 = ex2(mprev0 - mnew0);
        const float alpha1 = ex2(mprev1 - mnew1);

        float ps0 = 0.0f, ps1 = 0.0f;
        #pragma unroll
        for (int t = 0; t < 8; t++) {
            float p0 = ex2(sacc[t][0] - mnew0);
            float p1 = ex2(sacc[t][1] - mnew0);
            float p2 = ex2(sacc[t][2] - mnew1);
            float p3 = ex2(sacc[t][3] - mnew1);
            ps0 += p0 + p1; ps1 += p2 + p3;
            sacc[t][0] = p0; sacc[t][1] = p1; sacc[t][2] = p2; sacc[t][3] = p3;
        }
        ps0 += __shfl_xor_sync(0xffffffffu, ps0, 1);
        ps0 += __shfl_xor_sync(0xffffffffu, ps0, 2);
        ps1 += __shfl_xor_sync(0xffffffffu, ps1, 1);
        ps1 += __shfl_xor_sync(0xffffffffu, ps1, 2);
        l0 = l0 * alpha0 + ps0; l1 = l1 * alpha1 + ps1;
        mprev0 = mnew0; mprev1 = mnew1;
        #pragma unroll
        for (int t = 0; t < 8; t++) {
            o[t][0] *= alpha0; o[t][1] *= alpha0;
            o[t][2] *= alpha1; o[t][3] *= alpha1;
        }

        // ---- O += P_hi*V_hi + P_hi*V_lo + P_lo*V_hi  (register-resident P)
        const uint32_t vstage = smb + SM_V + buf * VSTAGE;
        #pragma unroll
        for (int u = 0; u < 4; u++) {
            const float* p0 = sacc[2*u];
            const float* p1 = sacc[2*u + 1];
            uint32_t h00 = __float_as_uint(p0[0]), h01 = __float_as_uint(p0[1]);
            uint32_t h02 = __float_as_uint(p0[2]), h03 = __float_as_uint(p0[3]);
            uint32_t h10 = __float_as_uint(p1[0]), h11 = __float_as_uint(p1[1]);
            uint32_t h12 = __float_as_uint(p1[2]), h13 = __float_as_uint(p1[3]);
            uint32_t pa[4], pl[4];
            pa[0] = __byte_perm(h00, h01, 0x7632);
            pa[1] = __byte_perm(h02, h03, 0x7632);
            pa[2] = __byte_perm(h10, h11, 0x7632);
            pa[3] = __byte_perm(h12, h13, 0x7632);
            float l00f = p0[0] - __uint_as_float(h00 & 0xFFFF0000u);
            float l01f = p0[1] - __uint_as_float(h01 & 0xFFFF0000u);
            float l02f = p0[2] - __uint_as_float(h02 & 0xFFFF0000u);
            float l03f = p0[3] - __uint_as_float(h03 & 0xFFFF0000u);
            float l10f = p1[0] - __uint_as_float(h10 & 0xFFFF0000u);
            float l11f = p1[1] - __uint_as_float(h11 & 0xFFFF0000u);
            float l12f = p1[2] - __uint_as_float(h12 & 0xFFFF0000u);
            float l13f = p1[3] - __uint_as_float(h13 & 0xFFFF0000u);
            pl[0] = __byte_perm(__float_as_uint(l00f), __float_as_uint(l01f), 0x7632);
            pl[1] = __byte_perm(__float_as_uint(l02f), __float_as_uint(l03f), 0x7632);
            pl[2] = __byte_perm(__float_as_uint(l10f), __float_as_uint(l11f), 0x7632);
            pl[3] = __byte_perm(__float_as_uint(l12f), __float_as_uint(l13f), 0x7632);

            const uint32_t gbv = kbv + 2 * (uint32_t)u;
            #pragma unroll
            for (int p = 0; p < 4; p++) {
                uint32_t off = vbase[p] + ((gbv ^ vsw[p]) << 4);
                uint32_t vh[4], vl[4];
                ldsm4(vh, vstage + off);
                ldsm4(vl, vstage + 8192 + off);
                mma16816(o[2*p],     pa, &vh[0]);
                mma16816(o[2*p + 1], pa, &vh[2]);
                mma16816(o[2*p],     pa, &vl[0]);
                mma16816(o[2*p + 1], pa, &vl[2]);
                mma16816(o[2*p],     pl, &vh[0]);
                mma16816(o[2*p + 1], pl, &vh[2]);
            }
        }
        __syncthreads();
    }

    // ---- normalize + write out (fp32) and g_ot (tf32)
    const float inv0 = 1.0f / l0, inv1 = 1.0f / l1;
    const int n0 = q0 + 16 * w + g, n1 = n0 + 8;
    #pragma unroll
    for (int t = 0; t < 8; t++) {
        int col = h * DD + 8 * t + 2 * c;
        float v00 = o[t][0] * inv0, v01 = o[t][1] * inv0;
        float v10 = o[t][2] * inv1, v11 = o[t][3] * inv1;
        *(float2*)&out[((size_t)b * NN + n0) * CC + col] = make_float2(v00, v01);
        *(float2*)&out[((size_t)b * NN + n1) * CC + col] = make_float2(v10, v11);
        uint2 t0; t0.x = tf32c(v00); t0.y = tf32c(v01);
        uint2 t1; t1.x = tf32c(v10); t1.y = tf32c(v11);
        *(uint2*)&g_ot[((size_t)b * NN + n0) * CC + col] = t0;
        *(uint2*)&g_ot[((size_t)b * NN + n1) * CC + col] = t1;
    }
}

// ---------------------------------------------------------------------------
__global__ __launch_bounds__(256)
void ln_kernel(const float* __restrict__ nw, const float* __restrict__ nb,
               float* __restrict__ outb)
{
    __shared__ float shs[8], shs2[8];
    const int row = blockIdx.x;
    const int tid = threadIdx.x;
    const float* pr = g_p + (size_t)row * CC;

    float v[3];
    float s = 0.0f, s2 = 0.0f;
    #pragma unroll
    for (int i = 0; i < 3; i++) {
        v[i] = pr[tid + i * 256];
        s  += v[i];
        s2 += v[i] * v[i];
    }
    #pragma unroll
    for (int off = 16; off >= 1; off >>= 1) {
        s  += __shfl_xor_sync(0xffffffffu, s,  off);
        s2 += __shfl_xor_sync(0xffffffffu, s2, off);
    }
    if ((tid & 31) == 0) { shs[tid >> 5] = s; shs2[tid >> 5] = s2; }
    __syncthreads();
    float ts = 0.0f, ts2 = 0.0f;
    #pragma unroll
    for (int w = 0; w < 8; w++) { ts += shs[w]; ts2 += shs2[w]; }

    const float mu  = ts * (1.0f / CC);
    const float var = ts2 * (1.0f / CC) - mu * mu;
    const float r   = rsqrtf(var + 1e-5f);

    #pragma unroll
    for (int i = 0; i < 3; i++) {
        int c = tid + i * 256;
        outb[(size_t)row * CC + c] = (v[i] - mu) * r * nw[c] + nb[c];
    }
}

// ---------------------------------------------------------------------------
extern "C" void kernel_launch(void* const* d_in, const int* in_sizes, int n_in,
                              void* d_out, int out_size)
{
    const float* x      = (const float*)d_in[0];
    const float* qkv_w  = (const float*)d_in[1];
    const float* qkv_b  = (const float*)d_in[2];
    const float* proj_w = (const float*)d_in[3];
    const float* proj_b = (const float*)d_in[4];
    const float* norm_w = (const float*)d_in[5];
    const float* norm_b = (const float*)d_in[6];
    const float* bank_k = (const float*)d_in[7];
    const float* bank_v = (const float*)d_in[8];

    float* out      = (float*)d_out;
    float* bank_upd = out + (size_t)BB * NN * CC;

    cudaFuncSetAttribute(attn2, cudaFuncAttributeMaxDynamicSharedMemorySize, ASMEM);
    cudaFuncSetAttribute(gemm_t<0>, cudaFuncAttributeMaxDynamicSharedMemorySize, GSMEM);
    cudaFuncSetAttribute(gemm_t<1>, cudaFuncAttributeMaxDynamicSharedMemorySize, GSMEM);

    const int nx4  = BB * NN * CC / 4;
    const int nwq4 = 3 * CC * CC / 4;
    const int nwp4 = CC * CC / 4;
    const int nbk4 = BB * HH * BANKN * DD / 4;

    // independent conversions first
    convkt_bank<<<(nbk4 + 255) / 256, 256>>>(bank_k);
    convt<0><<<(nx4 + 255) / 256, 256>>>((const float4*)x, nx4);
    convt<1><<<(nwq4 + 255) / 256, 256>>>((const float4*)qkv_w, nwq4);
    convt<3><<<(nwp4 + 255) / 256, 256>>>((const float4*)proj_w, nwp4);
    // QKV GEMM (tf32)
    gemm_t<0><<<dim3(BB*NN/TILE_M, 18), GTHREADS, GSMEM>>>(qkv_b);
    // V hi/lo planes
    convv3<<<dim3(ANCH, BB*HH), 256>>>(bank_v);
    // flash attention
    attn2<<<dim3(NN / AQ, BB * HH), 256, ASMEM>>>(out);
    // proj GEMM
    gemm_t<1><<<dim3(BB*NN/TILE_M, 6), GTHREADS, GSMEM>>>(proj_b);
    // LayerNorm
    ln_kernel<<<BB * NN, 256>>>(norm_w, norm_b, bank_upd);
}